// round 1
// baseline (speedup 1.0000x reference)
#include <cuda_runtime.h>
#include <math.h>

// ---------------------------------------------------------------------------
// Problem constants
// ---------------------------------------------------------------------------
#define BB 32
#define LL 512
#define DM 512
#define DT 256
#define NH 8
#define HD 64
#define DFF 2048
#define NLAYER 2
#define MROWS (BB * LL)          // 16384
#define DCAT (DM + DT)           // 768

// ---------------------------------------------------------------------------
// Scratch (device globals: allocation-free, graph-capturable)
// ---------------------------------------------------------------------------
__device__ float g_ln0 [MROWS * DM];
__device__ float g_x   [MROWS * DM];
__device__ float g_qkv [MROWS * 3 * DM];
__device__ float g_att [MROWS * DM];
__device__ float g_ao  [MROWS * DM];
__device__ float g_xc  [MROWS * DCAT];
__device__ float g_h1  [MROWS * DFF];
__device__ float g_ff  [MROWS * DCAT];
__device__ float g_tok [MROWS * DM];
__device__ float g_time[MROWS * DT];
__device__ float g_diag[BB * NH * LL];
__device__ float g_pc  [BB * 32 * DCAT];
__device__ float g_o1  [BB * 32 * DT];

// ---------------------------------------------------------------------------
// Generic SGEMM: C[M,N] = act(A[M,K](lda) @ W[N,K]^T + bias)
// 128x128 block tile, BK=16, 8x8 per-thread, double buffered smem.
// All M,N multiples of 128; K multiple of 16 (true for every call here).
// ---------------------------------------------------------------------------
__device__ __forceinline__ float act_apply(float v, int act) {
    if (act == 1) return fmaxf(v, 0.f);
    if (act == 2) return 0.5f * v * (1.f + erff(v * 0.70710678118654752f));
    return v;
}

__global__ __launch_bounds__(256, 2)
void gemm_kernel(const float* __restrict__ A, int lda,
                 const float* __restrict__ W, int K,
                 const float* __restrict__ bias,
                 float* __restrict__ C, int ldc,
                 int act)
{
    __shared__ float As[2][16][128];
    __shared__ float Ws[2][16][128];

    const int tid = threadIdx.x;
    const int m0 = blockIdx.x * 128;
    const int n0 = blockIdx.y * 128;

    const int lr0 = tid >> 2;            // 0..63
    const int lr1 = lr0 + 64;            // 64..127
    const int lc  = (tid & 3) * 4;       // 0,4,8,12

    const float* A0 = A + (long)(m0 + lr0) * lda + lc;
    const float* A1 = A + (long)(m0 + lr1) * lda + lc;
    const float* W0 = W + (long)(n0 + lr0) * K + lc;
    const float* W1 = W + (long)(n0 + lr1) * K + lc;

    const int ty = tid >> 4;   // 0..15 -> C rows ty*8..
    const int tx = tid & 15;   // 0..15 -> C cols tx*8..

    float acc[8][8];
    #pragma unroll
    for (int i = 0; i < 8; i++)
        #pragma unroll
        for (int j = 0; j < 8; j++) acc[i][j] = 0.f;

    float4 a0, a1, w0, w1;

    auto ldg = [&](int k0) {
        a0 = *(const float4*)(A0 + k0);
        a1 = *(const float4*)(A1 + k0);
        w0 = *(const float4*)(W0 + k0);
        w1 = *(const float4*)(W1 + k0);
    };
    auto sts = [&](int buf) {
        As[buf][lc + 0][lr0] = a0.x; As[buf][lc + 1][lr0] = a0.y;
        As[buf][lc + 2][lr0] = a0.z; As[buf][lc + 3][lr0] = a0.w;
        As[buf][lc + 0][lr1] = a1.x; As[buf][lc + 1][lr1] = a1.y;
        As[buf][lc + 2][lr1] = a1.z; As[buf][lc + 3][lr1] = a1.w;
        Ws[buf][lc + 0][lr0] = w0.x; Ws[buf][lc + 1][lr0] = w0.y;
        Ws[buf][lc + 2][lr0] = w0.z; Ws[buf][lc + 3][lr0] = w0.w;
        Ws[buf][lc + 0][lr1] = w1.x; Ws[buf][lc + 1][lr1] = w1.y;
        Ws[buf][lc + 2][lr1] = w1.z; Ws[buf][lc + 3][lr1] = w1.w;
    };

    ldg(0);
    sts(0);
    __syncthreads();

    const int KT = K >> 4;
    for (int kt = 0; kt < KT; kt++) {
        const int buf = kt & 1;
        const bool more = (kt + 1 < KT);
        if (more) ldg((kt + 1) << 4);

        #pragma unroll
        for (int k = 0; k < 16; k++) {
            float a[8], w[8];
            *(float4*)(a)     = *(const float4*)&As[buf][k][ty * 8];
            *(float4*)(a + 4) = *(const float4*)&As[buf][k][ty * 8 + 4];
            *(float4*)(w)     = *(const float4*)&Ws[buf][k][tx * 8];
            *(float4*)(w + 4) = *(const float4*)&Ws[buf][k][tx * 8 + 4];
            #pragma unroll
            for (int i = 0; i < 8; i++)
                #pragma unroll
                for (int j = 0; j < 8; j++)
                    acc[i][j] += a[i] * w[j];
        }
        if (more) sts(buf ^ 1);
        __syncthreads();
    }

    float bv[8];
    #pragma unroll
    for (int j = 0; j < 8; j++) bv[j] = bias[n0 + tx * 8 + j];

    #pragma unroll
    for (int i = 0; i < 8; i++) {
        float r[8];
        #pragma unroll
        for (int j = 0; j < 8; j++) r[j] = act_apply(acc[i][j] + bv[j], act);
        float* cp = C + (long)(m0 + ty * 8 + i) * ldc + n0 + tx * 8;
        *(float4*)(cp)     = *(float4*)(r);
        *(float4*)(cp + 4) = *(float4*)(r + 4);
    }
}

// ---------------------------------------------------------------------------
// LayerNorm (optionally fused residual add), D = blockDim.x * 4
// ---------------------------------------------------------------------------
__device__ __forceinline__ void block_reduce2(float& s, float& q, int t) {
    #pragma unroll
    for (int o = 16; o > 0; o >>= 1) {
        s += __shfl_xor_sync(0xffffffffu, s, o);
        q += __shfl_xor_sync(0xffffffffu, q, o);
    }
    __shared__ float ss[4], sq[4];
    const int w = t >> 5, nw = blockDim.x >> 5;
    if ((t & 31) == 0) { ss[w] = s; sq[w] = q; }
    __syncthreads();
    s = 0.f; q = 0.f;
    for (int i = 0; i < nw; i++) { s += ss[i]; q += sq[i]; }
}

__global__ void ln_kernel(const float* __restrict__ X, int ldx,
                          const float* __restrict__ R, int ldr,
                          const float* __restrict__ g, const float* __restrict__ b,
                          float* __restrict__ Y, int ldy)
{
    const int row = blockIdx.x, t = threadIdx.x;
    const float D = (float)(blockDim.x << 2);
    float4 v = *(const float4*)(X + (long)row * ldx + (t << 2));
    if (R) {
        float4 r = *(const float4*)(R + (long)row * ldr + (t << 2));
        v.x += r.x; v.y += r.y; v.z += r.z; v.w += r.w;
    }
    float s = v.x + v.y + v.z + v.w;
    float q = v.x * v.x + v.y * v.y + v.z * v.z + v.w * v.w;
    block_reduce2(s, q, t);
    const float mean = s / D;
    const float rstd = rsqrtf(fmaxf(q / D - mean * mean, 0.f) + 1e-5f);
    const float4 g4 = *(const float4*)(g + (t << 2));
    const float4 b4 = *(const float4*)(b + (t << 2));
    float4 o;
    o.x = (v.x - mean) * rstd * g4.x + b4.x;
    o.y = (v.y - mean) * rstd * g4.y + b4.y;
    o.z = (v.z - mean) * rstd * g4.z + b4.z;
    o.w = (v.w - mean) * rstd * g4.w + b4.w;
    *(float4*)(Y + (long)row * ldy + (t << 2)) = o;
}

// time branch: LN((diag+1) * x_time); D = 256, 64 threads
__global__ void ln_diag_kernel(const float* __restrict__ X,
                               const float* __restrict__ diag,
                               const float* __restrict__ g, const float* __restrict__ b,
                               float* __restrict__ Y, int ldy)
{
    const int row = blockIdx.x, t = threadIdx.x;        // row = b*512 + l
    const int bb = row >> 9, l = row & 511;
    const int h = t >> 3;                               // head of dims t*4..t*4+3
    const float dscale = diag[((long)bb * NH + h) * LL + l] + 1.f;
    float4 v = *(const float4*)(X + (long)row * DT + (t << 2));
    v.x *= dscale; v.y *= dscale; v.z *= dscale; v.w *= dscale;
    float s = v.x + v.y + v.z + v.w;
    float q = v.x * v.x + v.y * v.y + v.z * v.z + v.w * v.w;
    block_reduce2(s, q, t);
    const float mean = s / (float)DT;
    const float rstd = rsqrtf(fmaxf(q / (float)DT - mean * mean, 0.f) + 1e-5f);
    const float4 g4 = *(const float4*)(g + (t << 2));
    const float4 b4 = *(const float4*)(b + (t << 2));
    float4 o;
    o.x = (v.x - mean) * rstd * g4.x + b4.x;
    o.y = (v.y - mean) * rstd * g4.y + b4.y;
    o.z = (v.z - mean) * rstd * g4.z + b4.z;
    o.w = (v.w - mean) * rstd * g4.w + b4.w;
    *(float4*)(Y + (long)row * ldy + (t << 2)) = o;
}

// ---------------------------------------------------------------------------
// Fused flash-style attention per (b,h), 64-query tile, head dim 64.
// Also emits diag[b,h,q] = probs[q,q] for the time branch.
// blockDim = 128. Dynamic smem: Q[64*64] + K/P[64*68] + V[64*64] floats.
// ---------------------------------------------------------------------------
#define ATT_SMEM ((64 * 64 + 64 * 68 + 64 * 64) * 4)

__global__ __launch_bounds__(128)
void attn_kernel(const float* __restrict__ qkv,
                 float* __restrict__ att,
                 float* __restrict__ diag)
{
    extern __shared__ float sm[];
    float* Qs = sm;                 // stride 64
    float* Ks = sm + 64 * 64;       // stride 68 (reused as P)
    float* Vs = Ks + 64 * 68;       // stride 64

    const int tid = threadIdx.x;
    const int qt = blockIdx.x;      // 0..7
    const int bh = blockIdx.y;      // 0..255
    const int b = bh >> 3, h = bh & 7;

    const float* qb = qkv + ((long)b * LL) * (3 * DM) + h * HD;
    const float* kb = qb + DM;
    const float* vb = qb + 2 * DM;

    // load Q tile
    #pragma unroll
    for (int i = 0; i < 8; i++) {
        const int idx = tid + i * 128;
        const int r = idx >> 4, c4 = (idx & 15) * 4;
        *(float4*)(Qs + r * 64 + c4) =
            *(const float4*)(qb + (long)(qt * 64 + r) * (3 * DM) + c4);
    }

    const int rg = tid >> 3;   // 0..15 -> rows rg*4..rg*4+3
    const int cg = tid & 7;    // 0..7  -> S cols {cg+8j}, O dims cg*8..cg*8+7

    float m[4], l[4], sd[4], o[4][8];
    #pragma unroll
    for (int i = 0; i < 4; i++) {
        m[i] = -1e30f; l[i] = 0.f; sd[i] = 0.f;
        #pragma unroll
        for (int j = 0; j < 8; j++) o[i][j] = 0.f;
    }

    for (int kt = 0; kt < 8; kt++) {
        __syncthreads();   // previous P/V consumers done (and Q visible on kt=0)
        #pragma unroll
        for (int i = 0; i < 8; i++) {
            const int idx = tid + i * 128;
            const int r = idx >> 4, c4 = (idx & 15) * 4;
            *(float4*)(Ks + r * 68 + c4) =
                *(const float4*)(kb + (long)(kt * 64 + r) * (3 * DM) + c4);
            *(float4*)(Vs + r * 64 + c4) =
                *(const float4*)(vb + (long)(kt * 64 + r) * (3 * DM) + c4);
        }
        __syncthreads();

        float s[4][8];
        #pragma unroll
        for (int i = 0; i < 4; i++)
            #pragma unroll
            for (int j = 0; j < 8; j++) s[i][j] = 0.f;

        #pragma unroll
        for (int d4 = 0; d4 < 16; d4++) {
            float4 q4[4];
            #pragma unroll
            for (int i = 0; i < 4; i++)
                q4[i] = *(const float4*)(Qs + (rg * 4 + i) * 64 + d4 * 4);
            #pragma unroll
            for (int j = 0; j < 8; j++) {
                const float4 kv = *(const float4*)(Ks + (cg + 8 * j) * 68 + d4 * 4);
                #pragma unroll
                for (int i = 0; i < 4; i++)
                    s[i][j] += q4[i].x * kv.x + q4[i].y * kv.y
                             + q4[i].z * kv.z + q4[i].w * kv.w;
            }
        }

        #pragma unroll
        for (int i = 0; i < 4; i++)
            #pragma unroll
            for (int j = 0; j < 8; j++) s[i][j] *= 0.125f;

        if (kt == qt) {   // capture raw scaled diagonal score
            #pragma unroll
            for (int i = 0; i < 4; i++) {
                const int r = rg * 4 + i;
                if ((r & 7) == cg) sd[i] = s[i][r >> 3];
            }
        }

        // online softmax update (rows shared across the 8 lanes of this rg)
        #pragma unroll
        for (int i = 0; i < 4; i++) {
            float mt = s[i][0];
            #pragma unroll
            for (int j = 1; j < 8; j++) mt = fmaxf(mt, s[i][j]);
            mt = fmaxf(mt, __shfl_xor_sync(0xffffffffu, mt, 1));
            mt = fmaxf(mt, __shfl_xor_sync(0xffffffffu, mt, 2));
            mt = fmaxf(mt, __shfl_xor_sync(0xffffffffu, mt, 4));
            const float mn = fmaxf(m[i], mt);
            const float corr = __expf(m[i] - mn);
            float ps = 0.f;
            #pragma unroll
            for (int j = 0; j < 8; j++) {
                const float p = __expf(s[i][j] - mn);
                s[i][j] = p; ps += p;
            }
            ps += __shfl_xor_sync(0xffffffffu, ps, 1);
            ps += __shfl_xor_sync(0xffffffffu, ps, 2);
            ps += __shfl_xor_sync(0xffffffffu, ps, 4);
            l[i] = l[i] * corr + ps;
            m[i] = mn;
            #pragma unroll
            for (int j = 0; j < 8; j++) o[i][j] *= corr;
        }

        __syncthreads();   // all S readers of Ks done before overwrite with P
        #pragma unroll
        for (int i = 0; i < 4; i++)
            #pragma unroll
            for (int j = 0; j < 8; j++)
                Ks[(rg * 4 + i) * 68 + cg + 8 * j] = s[i][j];
        __syncthreads();

        // O += P @ V  (this thread: rows rg*4.., dims cg*8..)
        #pragma unroll 4
        for (int c = 0; c < 64; c++) {
            const float4 v0 = *(const float4*)(Vs + c * 64 + cg * 8);
            const float4 v1 = *(const float4*)(Vs + c * 64 + cg * 8 + 4);
            #pragma unroll
            for (int i = 0; i < 4; i++) {
                const float p = Ks[(rg * 4 + i) * 68 + c];
                o[i][0] += p * v0.x; o[i][1] += p * v0.y;
                o[i][2] += p * v0.z; o[i][3] += p * v0.w;
                o[i][4] += p * v1.x; o[i][5] += p * v1.y;
                o[i][6] += p * v1.z; o[i][7] += p * v1.w;
            }
        }
    }

    #pragma unroll
    for (int i = 0; i < 4; i++) {
        const float inv = 1.f / l[i];
        const int rl = rg * 4 + i;
        const int r = qt * 64 + rl;
        float* op = att + ((long)b * LL + r) * DM + h * HD + cg * 8;
        float r0[4] = { o[i][0] * inv, o[i][1] * inv, o[i][2] * inv, o[i][3] * inv };
        float r1[4] = { o[i][4] * inv, o[i][5] * inv, o[i][6] * inv, o[i][7] * inv };
        *(float4*)(op)     = *(float4*)r0;
        *(float4*)(op + 4) = *(float4*)r1;
        if ((rl & 7) == cg)
            diag[(long)bh * LL + r] = __expf(sd[i] - m[i]) * inv;
    }
}

// ---------------------------------------------------------------------------
// MaxPool over 16 seq positions, concat tok|time into [1024, 768]
// ---------------------------------------------------------------------------
__global__ void pool_kernel(const float* __restrict__ tok,
                            const float* __restrict__ tim,
                            float* __restrict__ pc)
{
    const int orow = blockIdx.x;          // b*32 + g
    const int b = orow >> 5, gq = orow & 31;
    for (int d = threadIdx.x; d < DCAT; d += blockDim.x) {
        float mx = -1e30f;
        if (d < DM) {
            const float* p = tok + ((long)b * LL + gq * 16) * DM + d;
            #pragma unroll
            for (int j = 0; j < 16; j++) mx = fmaxf(mx, p[j * DM]);
        } else {
            const float* p = tim + ((long)b * LL + gq * 16) * DT + (d - DM);
            #pragma unroll
            for (int j = 0; j < 16; j++) mx = fmaxf(mx, p[j * DT]);
        }
        pc[(long)orow * DCAT + d] = mx;
    }
}

// ---------------------------------------------------------------------------
// Host orchestration
// ---------------------------------------------------------------------------
extern "C" void kernel_launch(void* const* d_in, const int* in_sizes, int n_in,
                              void* d_out, int out_size)
{
    const float* in[26];
    for (int i = 0; i < 26; i++) in[i] = (const float*)d_in[i];

    float *ln0, *x, *qkvb, *att, *ao, *xc, *h1, *ff, *tok, *timeb, *diag, *pc, *o1;
    cudaGetSymbolAddress((void**)&ln0,   g_ln0);
    cudaGetSymbolAddress((void**)&x,     g_x);
    cudaGetSymbolAddress((void**)&qkvb,  g_qkv);
    cudaGetSymbolAddress((void**)&att,   g_att);
    cudaGetSymbolAddress((void**)&ao,    g_ao);
    cudaGetSymbolAddress((void**)&xc,    g_xc);
    cudaGetSymbolAddress((void**)&h1,    g_h1);
    cudaGetSymbolAddress((void**)&ff,    g_ff);
    cudaGetSymbolAddress((void**)&tok,   g_tok);
    cudaGetSymbolAddress((void**)&timeb, g_time);
    cudaGetSymbolAddress((void**)&diag,  g_diag);
    cudaGetSymbolAddress((void**)&pc,    g_pc);
    cudaGetSymbolAddress((void**)&o1,    g_o1);

    cudaFuncSetAttribute(attn_kernel,
                         cudaFuncAttributeMaxDynamicSharedMemorySize, ATT_SMEM);

    const int M = MROWS;
    for (int i = 0; i < NLAYER; i++) {
        const float* xin = i ? tok : in[0];
        const float* tin = i ? timeb : in[1];

        // in_proj: LN -> GEMM [M,512]x[512,512]
        ln_kernel<<<M, 128>>>(xin, DM, nullptr, 0,
                              in[2] + i * DM, in[3] + i * DM, ln0, DM);
        gemm_kernel<<<dim3(M / 128, DM / 128), 256>>>(
            ln0, DM, in[4] + (long)i * DM * DM, DM, in[5] + i * DM, x, DM, 0);

        // qkv: [M,512]x[512,1536]
        gemm_kernel<<<dim3(M / 128, 3 * DM / 128), 256>>>(
            x, DM, in[6] + (long)i * 3 * DM * DM, DM, in[7] + i * 3 * DM,
            qkvb, 3 * DM, 0);

        // fused attention (+ diag extraction)
        attn_kernel<<<dim3(LL / 64, BB * NH), 128, ATT_SMEM>>>(qkvb, att, diag);

        // attn out proj
        gemm_kernel<<<dim3(M / 128, DM / 128), 256>>>(
            att, DM, in[8] + (long)i * DM * DM, DM, in[9] + i * DM, ao, DM, 0);

        // n1: LN(ao + x) -> xc[:, :512] ; n2: LN((diag+1)*x_time) -> xc[:, 512:]
        ln_kernel<<<M, 128>>>(ao, DM, x, DM,
                              in[14] + i * DM, in[15] + i * DM, xc, DCAT);
        ln_diag_kernel<<<M, 64>>>(tin, diag,
                                  in[16] + i * DT, in[17] + i * DT, xc + DM, DCAT);

        // FFN: relu([M,768]x[768,2048]) x [2048,768]
        gemm_kernel<<<dim3(M / 128, DFF / 128), 256>>>(
            xc, DCAT, in[10] + (long)i * DFF * DCAT, DCAT, in[11] + i * DFF,
            h1, DFF, 1);
        gemm_kernel<<<dim3(M / 128, DCAT / 128), 256>>>(
            h1, DFF, in[12] + (long)i * DCAT * DFF, DFF, in[13] + i * DCAT,
            ff, DCAT, 0);

        // n3 / n4 (post-FFN residual LNs) -> next-layer tok / time streams
        ln_kernel<<<M, 128>>>(ff, DCAT, xc, DCAT,
                              in[18] + i * DM, in[19] + i * DM, tok, DM);
        ln_kernel<<<M, 64>>>(ff + DM, DCAT, xc + DM, DCAT,
                             in[20] + i * DT, in[21] + i * DT, timeb, DT);
    }

    // pool + output projection (gelu) + final LN -> d_out
    pool_kernel<<<BB * 32, 256>>>(tok, timeb, pc);
    gemm_kernel<<<dim3(BB * 32 / 128, DT / 128), 256>>>(
        pc, DCAT, in[22], DCAT, in[23], o1, DT, 2);
    ln_kernel<<<BB * 32, 64>>>(o1, DT, nullptr, 0, in[24], in[25],
                               (float*)d_out, DT);
}

// round 3
// speedup vs baseline: 1.6040x; 1.6040x over previous
#include <cuda_runtime.h>
#include <cuda_bf16.h>
#include <math.h>
#include <stdint.h>

// ---------------------------------------------------------------------------
// Problem constants
// ---------------------------------------------------------------------------
#define BB 32
#define LL 512
#define DM 512
#define DT 256
#define NH 8
#define HD 64
#define DFF 2048
#define NLAYER 2
#define MROWS (BB * LL)          // 16384
#define DCAT (DM + DT)           // 768

// ---------------------------------------------------------------------------
// Scratch (device globals: allocation-free, graph-capturable)
// ---------------------------------------------------------------------------
__device__ float g_ln0 [MROWS * DM];
__device__ float g_x   [MROWS * DM];
__device__ float g_qkv [MROWS * 3 * DM];
__device__ float g_att [MROWS * DM];
__device__ float g_ao  [MROWS * DM];
__device__ float g_xc  [MROWS * DCAT];
__device__ float g_h1  [MROWS * DFF];
__device__ float g_ff  [MROWS * DCAT];
__device__ float g_tok [MROWS * DM];
__device__ float g_time[MROWS * DT];
__device__ float g_diag[BB * NH * LL];
__device__ float g_pc  [BB * 32 * DCAT];
__device__ float g_o1  [BB * 32 * DT];

// ---------------------------------------------------------------------------
// mma.sync bf16x3 GEMM: C[M,N] = act(A[M,K](lda) @ W[N,K]^T + bias)
// 128x128 CTA tile, K-chunk 32, 8 warps of 32x64, double-buffered smem.
// A,W split into bf16 hi+lo; D += Ah*Bh + Al*Bh + Ah*Bl (fp32 accumulate).
// ---------------------------------------------------------------------------
#define PITCH_B 80                 // bytes per 32-elem bf16 row (16B-aligned, LDSM conflict-free)
#define OFF_AH 0
#define OFF_AL (128 * PITCH_B)     // 10240
#define OFF_BH (2 * 128 * PITCH_B) // 20480
#define OFF_BL (3 * 128 * PITCH_B) // 30720
#define STAGE_B (4 * 128 * PITCH_B)// 40960
#define GEMM_SMEM (2 * STAGE_B)    // 81920

__device__ __forceinline__ uint32_t smem_u32(const void* p) {
    uint32_t a;
    asm("{ .reg .u64 t; cvta.to.shared.u64 t, %1; cvt.u32.u64 %0, t; }"
        : "=r"(a) : "l"(p));
    return a;
}

#define LDSM4(R, addr) \
    asm volatile("ldmatrix.sync.aligned.m8n8.x4.shared.b16 {%0,%1,%2,%3}, [%4];" \
        : "=r"((R)[0]), "=r"((R)[1]), "=r"((R)[2]), "=r"((R)[3]) : "r"(addr))

#define MMA16816(D, A, B0, B1) \
    asm volatile("mma.sync.aligned.m16n8k16.row.col.f32.bf16.bf16.f32 " \
        "{%0,%1,%2,%3}, {%4,%5,%6,%7}, {%8,%9}, {%0,%1,%2,%3};" \
        : "+f"((D)[0]), "+f"((D)[1]), "+f"((D)[2]), "+f"((D)[3]) \
        : "r"((A)[0]), "r"((A)[1]), "r"((A)[2]), "r"((A)[3]), "r"(B0), "r"(B1))

__device__ __forceinline__ float act_apply(float v, int act) {
    if (act == 1) return fmaxf(v, 0.f);
    if (act == 2) return 0.5f * v * (1.f + erff(v * 0.70710678118654752f));
    return v;
}

__device__ __forceinline__ void cvt_pair(float x, float y,
                                         uint32_t& hi, uint32_t& lo) {
    __nv_bfloat16 hx = __float2bfloat16_rn(x);
    __nv_bfloat16 hy = __float2bfloat16_rn(y);
    __nv_bfloat16 lx = __float2bfloat16_rn(x - __bfloat162float(hx));
    __nv_bfloat16 ly = __float2bfloat16_rn(y - __bfloat162float(hy));
    hi = (uint32_t)__bfloat16_as_ushort(hx) | ((uint32_t)__bfloat16_as_ushort(hy) << 16);
    lo = (uint32_t)__bfloat16_as_ushort(lx) | ((uint32_t)__bfloat16_as_ushort(ly) << 16);
}

__global__ __launch_bounds__(256)
void gemm_tc(const float* __restrict__ A, int lda,
             const float* __restrict__ W, int K,
             const float* __restrict__ bias,
             float* __restrict__ C, int ldc, int act)
{
    extern __shared__ char sm[];
    const uint32_t sb = smem_u32(sm);

    const int tid = threadIdx.x;
    const int wid = tid >> 5;
    const int lane = tid & 31;
    const int m0 = blockIdx.x * 128;
    const int n0 = blockIdx.y * 128;

    const int wr = wid & 3;        // warp row group (32 rows)
    const int wc = wid >> 2;       // warp col group (64 cols)

    // global-load mapping: 2 threads per row, 16 floats each
    const int grow = tid >> 1;
    const int gcol = (tid & 1) * 16;
    const float* Ap = A + (size_t)(m0 + grow) * lda + gcol;
    const float* Wp = W + (size_t)(n0 + grow) * K + gcol;
    const uint32_t sts_off = (uint32_t)grow * PITCH_B + (uint32_t)gcol * 2;

    // ldmatrix lane address patterns
    const int a_lrow = (lane & 7) + ((lane >> 3) & 1) * 8;
    const int a_koff = (lane >> 4) * 8;
    const int b_lrow = (lane & 7) + ((lane >> 4) & 1) * 8;
    const int b_koff = ((lane >> 3) & 1) * 8;
    const uint32_t a_lbase = (uint32_t)(wr * 32 + a_lrow) * PITCH_B + (uint32_t)a_koff * 2;
    const uint32_t b_lbase = (uint32_t)(wc * 64 + b_lrow) * PITCH_B + (uint32_t)b_koff * 2;

    float acc[2][8][4];
    #pragma unroll
    for (int mt = 0; mt < 2; mt++)
        #pragma unroll
        for (int nt = 0; nt < 8; nt++)
            #pragma unroll
            for (int r = 0; r < 4; r++) acc[mt][nt][r] = 0.f;

    const int NC = K >> 5;

    // prologue: stage 0 -> buf 0
    {
        float4 av[4], bv[4];
        #pragma unroll
        for (int j = 0; j < 4; j++) {
            av[j] = *(const float4*)(Ap + j * 4);
            bv[j] = *(const float4*)(Wp + j * 4);
        }
        #pragma unroll
        for (int j = 0; j < 4; j++) {
            uint32_t h0, l0, h1, l1;
            cvt_pair(av[j].x, av[j].y, h0, l0);
            cvt_pair(av[j].z, av[j].w, h1, l1);
            *(uint2*)(sm + OFF_AH + sts_off + j * 8) = make_uint2(h0, h1);
            *(uint2*)(sm + OFF_AL + sts_off + j * 8) = make_uint2(l0, l1);
            cvt_pair(bv[j].x, bv[j].y, h0, l0);
            cvt_pair(bv[j].z, bv[j].w, h1, l1);
            *(uint2*)(sm + OFF_BH + sts_off + j * 8) = make_uint2(h0, h1);
            *(uint2*)(sm + OFF_BL + sts_off + j * 8) = make_uint2(l0, l1);
        }
    }
    __syncthreads();

    for (int c = 0; c < NC; c++) {
        const uint32_t so = (uint32_t)(c & 1) * STAGE_B;

        // prefetch next chunk into registers
        float4 av[4], bv[4];
        const bool more = (c + 1 < NC);
        if (more) {
            #pragma unroll
            for (int j = 0; j < 4; j++) {
                av[j] = *(const float4*)(Ap + (c + 1) * 32 + j * 4);
                bv[j] = *(const float4*)(Wp + (c + 1) * 32 + j * 4);
            }
        }

        // compute: 2 k16 steps
        #pragma unroll
        for (int step = 0; step < 2; step++) {
            const uint32_t kb = (uint32_t)step * 32;   // 16 elems * 2B

            uint32_t ah[2][4], al[2][4];
            #pragma unroll
            for (int mt = 0; mt < 2; mt++) {
                const uint32_t aa = sb + so + a_lbase + (uint32_t)mt * (16 * PITCH_B) + kb;
                LDSM4(ah[mt], aa + OFF_AH);
                LDSM4(al[mt], aa + OFF_AL);
            }

            #pragma unroll
            for (int g = 0; g < 4; g++) {
                const uint32_t ba = sb + so + b_lbase + (uint32_t)g * (16 * PITCH_B) + kb;
                uint32_t bh[4], bl[4];
                LDSM4(bh, ba + OFF_BH);
                LDSM4(bl, ba + OFF_BL);
                #pragma unroll
                for (int mt = 0; mt < 2; mt++) {
                    MMA16816(acc[mt][2 * g],     ah[mt], bh[0], bh[1]);
                    MMA16816(acc[mt][2 * g],     al[mt], bh[0], bh[1]);
                    MMA16816(acc[mt][2 * g],     ah[mt], bl[0], bl[1]);
                    MMA16816(acc[mt][2 * g + 1], ah[mt], bh[2], bh[3]);
                    MMA16816(acc[mt][2 * g + 1], al[mt], bh[2], bh[3]);
                    MMA16816(acc[mt][2 * g + 1], ah[mt], bl[2], bl[3]);
                }
            }
        }

        // store next chunk into the other buffer
        if (more) {
            char* dst = sm + (STAGE_B - so);   // so ^ STAGE_B
            #pragma unroll
            for (int j = 0; j < 4; j++) {
                uint32_t h0, l0, h1, l1;
                cvt_pair(av[j].x, av[j].y, h0, l0);
                cvt_pair(av[j].z, av[j].w, h1, l1);
                *(uint2*)(dst + OFF_AH + sts_off + j * 8) = make_uint2(h0, h1);
                *(uint2*)(dst + OFF_AL + sts_off + j * 8) = make_uint2(l0, l1);
                cvt_pair(bv[j].x, bv[j].y, h0, l0);
                cvt_pair(bv[j].z, bv[j].w, h1, l1);
                *(uint2*)(dst + OFF_BH + sts_off + j * 8) = make_uint2(h0, h1);
                *(uint2*)(dst + OFF_BL + sts_off + j * 8) = make_uint2(l0, l1);
            }
        }
        __syncthreads();
    }

    // epilogue
    const int g = lane >> 2;
    const int t = lane & 3;
    #pragma unroll
    for (int mt = 0; mt < 2; mt++) {
        #pragma unroll
        for (int nt = 0; nt < 8; nt++) {
            const int col = n0 + wc * 64 + nt * 8 + t * 2;
            const float b0 = bias[col], b1 = bias[col + 1];
            const int r0 = m0 + wr * 32 + mt * 16 + g;
            float2 v0, v1;
            v0.x = act_apply(acc[mt][nt][0] + b0, act);
            v0.y = act_apply(acc[mt][nt][1] + b1, act);
            v1.x = act_apply(acc[mt][nt][2] + b0, act);
            v1.y = act_apply(acc[mt][nt][3] + b1, act);
            *(float2*)(C + (size_t)r0 * ldc + col) = v0;
            *(float2*)(C + (size_t)(r0 + 8) * ldc + col) = v1;
        }
    }
}

// ---------------------------------------------------------------------------
// LayerNorm (optionally fused residual add), D = blockDim.x * 4
// ---------------------------------------------------------------------------
__device__ __forceinline__ void block_reduce2(float& s, float& q, int t) {
    #pragma unroll
    for (int o = 16; o > 0; o >>= 1) {
        s += __shfl_xor_sync(0xffffffffu, s, o);
        q += __shfl_xor_sync(0xffffffffu, q, o);
    }
    __shared__ float ss[4], sq[4];
    const int w = t >> 5, nw = blockDim.x >> 5;
    if ((t & 31) == 0) { ss[w] = s; sq[w] = q; }
    __syncthreads();
    s = 0.f; q = 0.f;
    for (int i = 0; i < nw; i++) { s += ss[i]; q += sq[i]; }
}

__global__ void ln_kernel(const float* __restrict__ X, int ldx,
                          const float* __restrict__ R, int ldr,
                          const float* __restrict__ g, const float* __restrict__ b,
                          float* __restrict__ Y, int ldy)
{
    const int row = blockIdx.x, t = threadIdx.x;
    const float D = (float)(blockDim.x << 2);
    float4 v = *(const float4*)(X + (long)row * ldx + (t << 2));
    if (R) {
        float4 r = *(const float4*)(R + (long)row * ldr + (t << 2));
        v.x += r.x; v.y += r.y; v.z += r.z; v.w += r.w;
    }
    float s = v.x + v.y + v.z + v.w;
    float q = v.x * v.x + v.y * v.y + v.z * v.z + v.w * v.w;
    block_reduce2(s, q, t);
    const float mean = s / D;
    const float rstd = rsqrtf(fmaxf(q / D - mean * mean, 0.f) + 1e-5f);
    const float4 g4 = *(const float4*)(g + (t << 2));
    const float4 b4 = *(const float4*)(b + (t << 2));
    float4 o;
    o.x = (v.x - mean) * rstd * g4.x + b4.x;
    o.y = (v.y - mean) * rstd * g4.y + b4.y;
    o.z = (v.z - mean) * rstd * g4.z + b4.z;
    o.w = (v.w - mean) * rstd * g4.w + b4.w;
    *(float4*)(Y + (long)row * ldy + (t << 2)) = o;
}

// time branch: LN((diag+1) * x_time); D = 256, 64 threads
__global__ void ln_diag_kernel(const float* __restrict__ X,
                               const float* __restrict__ diag,
                               const float* __restrict__ g, const float* __restrict__ b,
                               float* __restrict__ Y, int ldy)
{
    const int row = blockIdx.x, t = threadIdx.x;
    const int bb = row >> 9, l = row & 511;
    const int h = t >> 3;
    const float dscale = diag[((long)bb * NH + h) * LL + l] + 1.f;
    float4 v = *(const float4*)(X + (long)row * DT + (t << 2));
    v.x *= dscale; v.y *= dscale; v.z *= dscale; v.w *= dscale;
    float s = v.x + v.y + v.z + v.w;
    float q = v.x * v.x + v.y * v.y + v.z * v.z + v.w * v.w;
    block_reduce2(s, q, t);
    const float mean = s / (float)DT;
    const float rstd = rsqrtf(fmaxf(q / (float)DT - mean * mean, 0.f) + 1e-5f);
    const float4 g4 = *(const float4*)(g + (t << 2));
    const float4 b4 = *(const float4*)(b + (t << 2));
    float4 o;
    o.x = (v.x - mean) * rstd * g4.x + b4.x;
    o.y = (v.y - mean) * rstd * g4.y + b4.y;
    o.z = (v.z - mean) * rstd * g4.z + b4.z;
    o.w = (v.w - mean) * rstd * g4.w + b4.w;
    *(float4*)(Y + (long)row * ldy + (t << 2)) = o;
}

// ---------------------------------------------------------------------------
// Fused flash-style attention per (b,h), 64-query tile, head dim 64.
// ---------------------------------------------------------------------------
#define ATT_SMEM ((64 * 64 + 64 * 68 + 64 * 64) * 4)

__global__ __launch_bounds__(128)
void attn_kernel(const float* __restrict__ qkv,
                 float* __restrict__ att,
                 float* __restrict__ diag)
{
    extern __shared__ float smf[];
    float* Qs = smf;
    float* Ks = smf + 64 * 64;
    float* Vs = Ks + 64 * 68;

    const int tid = threadIdx.x;
    const int qt = blockIdx.x;
    const int bh = blockIdx.y;
    const int b = bh >> 3, h = bh & 7;

    const float* qb = qkv + ((long)b * LL) * (3 * DM) + h * HD;
    const float* kb = qb + DM;
    const float* vb = qb + 2 * DM;

    #pragma unroll
    for (int i = 0; i < 8; i++) {
        const int idx = tid + i * 128;
        const int r = idx >> 4, c4 = (idx & 15) * 4;
        *(float4*)(Qs + r * 64 + c4) =
            *(const float4*)(qb + (long)(qt * 64 + r) * (3 * DM) + c4);
    }

    const int rg = tid >> 3;
    const int cg = tid & 7;

    float m[4], l[4], sd[4], o[4][8];
    #pragma unroll
    for (int i = 0; i < 4; i++) {
        m[i] = -1e30f; l[i] = 0.f; sd[i] = 0.f;
        #pragma unroll
        for (int j = 0; j < 8; j++) o[i][j] = 0.f;
    }

    for (int kt = 0; kt < 8; kt++) {
        __syncthreads();
        #pragma unroll
        for (int i = 0; i < 8; i++) {
            const int idx = tid + i * 128;
            const int r = idx >> 4, c4 = (idx & 15) * 4;
            *(float4*)(Ks + r * 68 + c4) =
                *(const float4*)(kb + (long)(kt * 64 + r) * (3 * DM) + c4);
            *(float4*)(Vs + r * 64 + c4) =
                *(const float4*)(vb + (long)(kt * 64 + r) * (3 * DM) + c4);
        }
        __syncthreads();

        float s[4][8];
        #pragma unroll
        for (int i = 0; i < 4; i++)
            #pragma unroll
            for (int j = 0; j < 8; j++) s[i][j] = 0.f;

        #pragma unroll
        for (int d4 = 0; d4 < 16; d4++) {
            float4 q4[4];
            #pragma unroll
            for (int i = 0; i < 4; i++)
                q4[i] = *(const float4*)(Qs + (rg * 4 + i) * 64 + d4 * 4);
            #pragma unroll
            for (int j = 0; j < 8; j++) {
                const float4 kv = *(const float4*)(Ks + (cg + 8 * j) * 68 + d4 * 4);
                #pragma unroll
                for (int i = 0; i < 4; i++)
                    s[i][j] += q4[i].x * kv.x + q4[i].y * kv.y
                             + q4[i].z * kv.z + q4[i].w * kv.w;
            }
        }

        #pragma unroll
        for (int i = 0; i < 4; i++)
            #pragma unroll
            for (int j = 0; j < 8; j++) s[i][j] *= 0.125f;

        if (kt == qt) {
            #pragma unroll
            for (int i = 0; i < 4; i++) {
                const int r = rg * 4 + i;
                if ((r & 7) == cg) sd[i] = s[i][r >> 3];
            }
        }

        #pragma unroll
        for (int i = 0; i < 4; i++) {
            float mt = s[i][0];
            #pragma unroll
            for (int j = 1; j < 8; j++) mt = fmaxf(mt, s[i][j]);
            mt = fmaxf(mt, __shfl_xor_sync(0xffffffffu, mt, 1));
            mt = fmaxf(mt, __shfl_xor_sync(0xffffffffu, mt, 2));
            mt = fmaxf(mt, __shfl_xor_sync(0xffffffffu, mt, 4));
            const float mn = fmaxf(m[i], mt);
            const float corr = __expf(m[i] - mn);
            float ps = 0.f;
            #pragma unroll
            for (int j = 0; j < 8; j++) {
                const float p = __expf(s[i][j] - mn);
                s[i][j] = p; ps += p;
            }
            ps += __shfl_xor_sync(0xffffffffu, ps, 1);
            ps += __shfl_xor_sync(0xffffffffu, ps, 2);
            ps += __shfl_xor_sync(0xffffffffu, ps, 4);
            l[i] = l[i] * corr + ps;
            m[i] = mn;
            #pragma unroll
            for (int j = 0; j < 8; j++) o[i][j] *= corr;
        }

        __syncthreads();
        #pragma unroll
        for (int i = 0; i < 4; i++)
            #pragma unroll
            for (int j = 0; j < 8; j++)
                Ks[(rg * 4 + i) * 68 + cg + 8 * j] = s[i][j];
        __syncthreads();

        #pragma unroll 4
        for (int c = 0; c < 64; c++) {
            const float4 v0 = *(const float4*)(Vs + c * 64 + cg * 8);
            const float4 v1 = *(const float4*)(Vs + c * 64 + cg * 8 + 4);
            #pragma unroll
            for (int i = 0; i < 4; i++) {
                const float p = Ks[(rg * 4 + i) * 68 + c];
                o[i][0] += p * v0.x; o[i][1] += p * v0.y;
                o[i][2] += p * v0.z; o[i][3] += p * v0.w;
                o[i][4] += p * v1.x; o[i][5] += p * v1.y;
                o[i][6] += p * v1.z; o[i][7] += p * v1.w;
            }
        }
    }

    #pragma unroll
    for (int i = 0; i < 4; i++) {
        const float inv = 1.f / l[i];
        const int rl = rg * 4 + i;
        const int r = qt * 64 + rl;
        float* op = att + ((long)b * LL + r) * DM + h * HD + cg * 8;
        float r0[4] = { o[i][0] * inv, o[i][1] * inv, o[i][2] * inv, o[i][3] * inv };
        float r1[4] = { o[i][4] * inv, o[i][5] * inv, o[i][6] * inv, o[i][7] * inv };
        *(float4*)(op)     = *(float4*)r0;
        *(float4*)(op + 4) = *(float4*)r1;
        if ((rl & 7) == cg)
            diag[(long)bh * LL + r] = __expf(sd[i] - m[i]) * inv;
    }
}

// ---------------------------------------------------------------------------
// MaxPool over 16 seq positions, concat tok|time into [1024, 768]
// ---------------------------------------------------------------------------
__global__ void pool_kernel(const float* __restrict__ tok,
                            const float* __restrict__ tim,
                            float* __restrict__ pc)
{
    const int orow = blockIdx.x;
    const int b = orow >> 5, gq = orow & 31;
    for (int d = threadIdx.x; d < DCAT; d += blockDim.x) {
        float mx = -1e30f;
        if (d < DM) {
            const float* p = tok + ((long)b * LL + gq * 16) * DM + d;
            #pragma unroll
            for (int j = 0; j < 16; j++) mx = fmaxf(mx, p[j * DM]);
        } else {
            const float* p = tim + ((long)b * LL + gq * 16) * DT + (d - DM);
            #pragma unroll
            for (int j = 0; j < 16; j++) mx = fmaxf(mx, p[j * DT]);
        }
        pc[(long)orow * DCAT + d] = mx;
    }
}

// ---------------------------------------------------------------------------
// Host orchestration
// ---------------------------------------------------------------------------
static void launch_gemm(const float* A, int lda, const float* W, int K,
                        const float* bias, float* C, int ldc, int act,
                        int M, int N)
{
    gemm_tc<<<dim3(M / 128, N / 128), 256, GEMM_SMEM>>>(A, lda, W, K, bias, C, ldc, act);
}

extern "C" void kernel_launch(void* const* d_in, const int* in_sizes, int n_in,
                              void* d_out, int out_size)
{
    const float* in[26];
    for (int i = 0; i < 26; i++) in[i] = (const float*)d_in[i];

    float *ln0, *x, *qkvb, *att, *ao, *xc, *h1, *ff, *tok, *timeb, *diag, *pc, *o1;
    cudaGetSymbolAddress((void**)&ln0,   g_ln0);
    cudaGetSymbolAddress((void**)&x,     g_x);
    cudaGetSymbolAddress((void**)&qkvb,  g_qkv);
    cudaGetSymbolAddress((void**)&att,   g_att);
    cudaGetSymbolAddress((void**)&ao,    g_ao);
    cudaGetSymbolAddress((void**)&xc,    g_xc);
    cudaGetSymbolAddress((void**)&h1,    g_h1);
    cudaGetSymbolAddress((void**)&ff,    g_ff);
    cudaGetSymbolAddress((void**)&tok,   g_tok);
    cudaGetSymbolAddress((void**)&timeb, g_time);
    cudaGetSymbolAddress((void**)&diag,  g_diag);
    cudaGetSymbolAddress((void**)&pc,    g_pc);
    cudaGetSymbolAddress((void**)&o1,    g_o1);

    cudaFuncSetAttribute(attn_kernel,
                         cudaFuncAttributeMaxDynamicSharedMemorySize, ATT_SMEM);
    cudaFuncSetAttribute(gemm_tc,
                         cudaFuncAttributeMaxDynamicSharedMemorySize, GEMM_SMEM);

    const int M = MROWS;
    for (int i = 0; i < NLAYER; i++) {
        const float* xin = i ? tok : in[0];
        const float* tin = i ? timeb : in[1];

        ln_kernel<<<M, 128>>>(xin, DM, nullptr, 0,
                              in[2] + i * DM, in[3] + i * DM, ln0, DM);
        launch_gemm(ln0, DM, in[4] + (long)i * DM * DM, DM, in[5] + i * DM,
                    x, DM, 0, M, DM);

        launch_gemm(x, DM, in[6] + (long)i * 3 * DM * DM, DM, in[7] + i * 3 * DM,
                    qkvb, 3 * DM, 0, M, 3 * DM);

        attn_kernel<<<dim3(LL / 64, BB * NH), 128, ATT_SMEM>>>(qkvb, att, diag);

        launch_gemm(att, DM, in[8] + (long)i * DM * DM, DM, in[9] + i * DM,
                    ao, DM, 0, M, DM);

        ln_kernel<<<M, 128>>>(ao, DM, x, DM,
                              in[14] + i * DM, in[15] + i * DM, xc, DCAT);
        ln_diag_kernel<<<M, 64>>>(tin, diag,
                                  in[16] + i * DT, in[17] + i * DT, xc + DM, DCAT);

        launch_gemm(xc, DCAT, in[10] + (long)i * DFF * DCAT, DCAT, in[11] + i * DFF,
                    h1, DFF, 1, M, DFF);
        launch_gemm(h1, DFF, in[12] + (long)i * DCAT * DFF, DFF, in[13] + i * DCAT,
                    ff, DCAT, 0, M, DCAT);

        ln_kernel<<<M, 128>>>(ff, DCAT, xc, DCAT,
                              in[18] + i * DM, in[19] + i * DM, tok, DM);
        ln_kernel<<<M, 64>>>(ff + DM, DCAT, xc + DM, DCAT,
                             in[20] + i * DT, in[21] + i * DT, timeb, DT);
    }

    pool_kernel<<<BB * 32, 256>>>(tok, timeb, pc);
    launch_gemm(pc, DCAT, in[22], DCAT, in[23], o1, DT, 2, BB * 32, DT);
    ln_kernel<<<BB * 32, 64>>>(o1, DT, nullptr, 0, in[24], in[25],
                               (float*)d_out, DT);
}

// round 5
// speedup vs baseline: 1.7009x; 1.0604x over previous
#include <cuda_runtime.h>
#include <cuda_bf16.h>
#include <math.h>
#include <stdint.h>

// ---------------------------------------------------------------------------
// Problem constants
// ---------------------------------------------------------------------------
#define BB 32
#define LL 512
#define DM 512
#define DT 256
#define NH 8
#define HD 64
#define DFF 2048
#define NLAYER 2
#define MROWS (BB * LL)          // 16384
#define DCAT (DM + DT)           // 768

// ---------------------------------------------------------------------------
// Scratch (device globals)
// ---------------------------------------------------------------------------
__device__ float g_x   [MROWS * DM];
__device__ float g_qkv [MROWS * 3 * DM];
__device__ float g_ao  [MROWS * DM];
__device__ float g_xc  [MROWS * DCAT];
__device__ float g_ff  [MROWS * DCAT];
__device__ float g_tok [MROWS * DM];
__device__ float g_time[MROWS * DT];
__device__ float g_diag[BB * NH * LL];
__device__ float g_o1  [BB * 32 * DT];

// bf16 hi/lo activation buffers (GEMM A inputs)
__device__ __nv_bfloat16 g_ln0h[MROWS * DM],  g_ln0l[MROWS * DM];
__device__ __nv_bfloat16 g_xh  [MROWS * DM],  g_xl  [MROWS * DM];
__device__ __nv_bfloat16 g_atth[MROWS * DM],  g_attl[MROWS * DM];
__device__ __nv_bfloat16 g_xch [MROWS * DCAT],g_xcl [MROWS * DCAT];
__device__ __nv_bfloat16 g_h1h [MROWS * DFF], g_h1l [MROWS * DFF];
__device__ __nv_bfloat16 g_pch [BB * 32 * DCAT], g_pcl[BB * 32 * DCAT];

// bf16 hi/lo weights (all tensors, all layers)
#define OFF_W_IN  0
#define OFF_W_QKV (OFF_W_IN  + NLAYER * DM * DM)
#define OFF_W_AO  (OFF_W_QKV + NLAYER * 3 * DM * DM)
#define OFF_W_L1  (OFF_W_AO  + NLAYER * DM * DM)
#define OFF_W_L2  (OFF_W_L1  + NLAYER * DFF * DCAT)
#define OFF_W_OUT (OFF_W_L2  + NLAYER * DCAT * DFF)
#define W_TOTAL   (OFF_W_OUT + DT * DCAT)
__device__ __nv_bfloat16 g_wh[W_TOTAL], g_wl[W_TOTAL];

// ---------------------------------------------------------------------------
// Helpers
// ---------------------------------------------------------------------------
__device__ __forceinline__ uint32_t smem_u32(const void* p) {
    uint32_t a;
    asm("{ .reg .u64 t; cvta.to.shared.u64 t, %1; cvt.u32.u64 %0, t; }"
        : "=r"(a) : "l"(p));
    return a;
}

__device__ __forceinline__ void split1(float v, __nv_bfloat16& h, __nv_bfloat16& l) {
    h = __float2bfloat16_rn(v);
    l = __float2bfloat16_rn(v - __bfloat162float(h));
}

// float -> (bf16 hi, bf16 lo) split pass
__global__ void split_kernel(const float* __restrict__ X,
                             __nv_bfloat16* __restrict__ H,
                             __nv_bfloat16* __restrict__ L, int n4)
{
    const int i = blockIdx.x * blockDim.x + threadIdx.x;
    if (i >= n4) return;
    const float4 v = *(const float4*)(X + (size_t)i * 4);
    __nv_bfloat16 h[4], l[4];
    split1(v.x, h[0], l[0]); split1(v.y, h[1], l[1]);
    split1(v.z, h[2], l[2]); split1(v.w, h[3], l[3]);
    *(uint2*)(H + (size_t)i * 4) = *(uint2*)h;
    *(uint2*)(L + (size_t)i * 4) = *(uint2*)l;
}

// ---------------------------------------------------------------------------
// bf16x3 mma.sync GEMM. A,W pre-split into bf16 hi/lo in global.
// C = act(A @ W^T + bias); outputs fp32 and/or bf16 hi/lo.
// 128x128 CTA tile, K-chunk 32, 8 warps of 32x64, cp.async double buffer.
// ---------------------------------------------------------------------------
#define PITCH_B 80
#define OFF_AH 0
#define OFF_AL (128 * PITCH_B)
#define OFF_BH (2 * 128 * PITCH_B)
#define OFF_BL (3 * 128 * PITCH_B)
#define STAGE_B (4 * 128 * PITCH_B)   // 40960
#define GEMM_SMEM (2 * STAGE_B)       // 81920

#define LDSM4(R, addr) \
    asm volatile("ldmatrix.sync.aligned.m8n8.x4.shared.b16 {%0,%1,%2,%3}, [%4];" \
        : "=r"((R)[0]), "=r"((R)[1]), "=r"((R)[2]), "=r"((R)[3]) : "r"(addr))

#define MMA16816(D, A, B0, B1) \
    asm volatile("mma.sync.aligned.m16n8k16.row.col.f32.bf16.bf16.f32 " \
        "{%0,%1,%2,%3}, {%4,%5,%6,%7}, {%8,%9}, {%0,%1,%2,%3};" \
        : "+f"((D)[0]), "+f"((D)[1]), "+f"((D)[2]), "+f"((D)[3]) \
        : "r"((A)[0]), "r"((A)[1]), "r"((A)[2]), "r"((A)[3]), "r"(B0), "r"(B1))

__device__ __forceinline__ void cp_async16(uint32_t d, const void* s) {
    asm volatile("cp.async.cg.shared.global [%0], [%1], 16;" :: "r"(d), "l"(s));
}
#define CP_COMMIT() asm volatile("cp.async.commit_group;" ::: "memory")
#define CP_WAIT(n)  asm volatile("cp.async.wait_group %0;" :: "n"(n) : "memory")

__device__ __forceinline__ float act_apply(float v, int act) {
    if (act == 1) return fmaxf(v, 0.f);
    if (act == 2) return 0.5f * v * (1.f + erff(v * 0.70710678118654752f));
    return v;
}

__global__ __launch_bounds__(256)
void gemm_bf(const __nv_bfloat16* __restrict__ Ah, const __nv_bfloat16* __restrict__ Al,
             int lda,
             const __nv_bfloat16* __restrict__ Wh, const __nv_bfloat16* __restrict__ Wl,
             int K,
             const float* __restrict__ bias,
             float* __restrict__ Cf,
             __nv_bfloat16* __restrict__ Ch, __nv_bfloat16* __restrict__ Cl,
             int ldc, int act)
{
    extern __shared__ char sm[];
    const uint32_t sb = smem_u32(sm);

    const int tid = threadIdx.x;
    const int wid = tid >> 5;
    const int lane = tid & 31;
    const int m0 = blockIdx.x * 128;
    const int n0 = blockIdx.y * 128;
    const int wr = wid & 3;
    const int wc = wid >> 2;

    // global load mapping: 2 threads per row, 16 bf16 (32B) each -> 2 x 16B cp.async
    const int grow = tid >> 1;
    const int gcol = (tid & 1) * 16;
    const __nv_bfloat16* Ahp = Ah + (size_t)(m0 + grow) * lda + gcol;
    const __nv_bfloat16* Alp = Al + (size_t)(m0 + grow) * lda + gcol;
    const __nv_bfloat16* Whp = Wh + (size_t)(n0 + grow) * K + gcol;
    const __nv_bfloat16* Wlp = Wl + (size_t)(n0 + grow) * K + gcol;
    const uint32_t sts_off = (uint32_t)grow * PITCH_B + (uint32_t)gcol * 2;

    // ldmatrix lane addressing
    const int a_lrow = (lane & 7) + ((lane >> 3) & 1) * 8;
    const int a_koff = (lane >> 4) * 8;
    const int b_lrow = (lane & 7) + ((lane >> 4) & 1) * 8;
    const int b_koff = ((lane >> 3) & 1) * 8;
    const uint32_t a_lbase = (uint32_t)(wr * 32 + a_lrow) * PITCH_B + (uint32_t)a_koff * 2;
    const uint32_t b_lbase = (uint32_t)(wc * 64 + b_lrow) * PITCH_B + (uint32_t)b_koff * 2;

    float acc[2][8][4];
    #pragma unroll
    for (int mt = 0; mt < 2; mt++)
        #pragma unroll
        for (int nt = 0; nt < 8; nt++)
            #pragma unroll
            for (int r = 0; r < 4; r++) acc[mt][nt][r] = 0.f;

    const int NC = K >> 5;

    auto issue = [&](int c) {
        const uint32_t d = sb + (uint32_t)(c & 1) * STAGE_B + sts_off;
        cp_async16(d + OFF_AH,      Ahp + c * 32);
        cp_async16(d + OFF_AH + 16, Ahp + c * 32 + 8);
        cp_async16(d + OFF_AL,      Alp + c * 32);
        cp_async16(d + OFF_AL + 16, Alp + c * 32 + 8);
        cp_async16(d + OFF_BH,      Whp + c * 32);
        cp_async16(d + OFF_BH + 16, Whp + c * 32 + 8);
        cp_async16(d + OFF_BL,      Wlp + c * 32);
        cp_async16(d + OFF_BL + 16, Wlp + c * 32 + 8);
        CP_COMMIT();
    };

    issue(0);
    if (NC > 1) issue(1);

    for (int c = 0; c < NC; c++) {
        if (c + 1 < NC) CP_WAIT(1); else CP_WAIT(0);
        __syncthreads();

        const uint32_t so = (uint32_t)(c & 1) * STAGE_B;

        #pragma unroll
        for (int step = 0; step < 2; step++) {
            const uint32_t kb = (uint32_t)step * 32;

            uint32_t ahr[2][4], alr[2][4];
            #pragma unroll
            for (int mt = 0; mt < 2; mt++) {
                const uint32_t aa = sb + so + a_lbase + (uint32_t)mt * (16 * PITCH_B) + kb;
                LDSM4(ahr[mt], aa + OFF_AH);
                LDSM4(alr[mt], aa + OFF_AL);
            }

            #pragma unroll
            for (int g = 0; g < 4; g++) {
                const uint32_t ba = sb + so + b_lbase + (uint32_t)g * (16 * PITCH_B) + kb;
                uint32_t bh[4], bl[4];
                LDSM4(bh, ba + OFF_BH);
                LDSM4(bl, ba + OFF_BL);
                #pragma unroll
                for (int mt = 0; mt < 2; mt++) {
                    MMA16816(acc[mt][2 * g],     ahr[mt], bh[0], bh[1]);
                    MMA16816(acc[mt][2 * g],     alr[mt], bh[0], bh[1]);
                    MMA16816(acc[mt][2 * g],     ahr[mt], bl[0], bl[1]);
                    MMA16816(acc[mt][2 * g + 1], ahr[mt], bh[2], bh[3]);
                    MMA16816(acc[mt][2 * g + 1], alr[mt], bh[2], bh[3]);
                    MMA16816(acc[mt][2 * g + 1], ahr[mt], bl[2], bl[3]);
                }
            }
        }
        __syncthreads();
        if (c + 2 < NC) issue(c + 2);
    }

    // epilogue
    const int g = lane >> 2;
    const int t = lane & 3;
    #pragma unroll
    for (int mt = 0; mt < 2; mt++) {
        #pragma unroll
        for (int nt = 0; nt < 8; nt++) {
            const int col = n0 + wc * 64 + nt * 8 + t * 2;
            const float b0 = bias[col], b1 = bias[col + 1];
            const int r0 = m0 + wr * 32 + mt * 16 + g;
            float v00 = act_apply(acc[mt][nt][0] + b0, act);
            float v01 = act_apply(acc[mt][nt][1] + b1, act);
            float v10 = act_apply(acc[mt][nt][2] + b0, act);
            float v11 = act_apply(acc[mt][nt][3] + b1, act);
            if (Cf) {
                *(float2*)(Cf + (size_t)r0 * ldc + col) = make_float2(v00, v01);
                *(float2*)(Cf + (size_t)(r0 + 8) * ldc + col) = make_float2(v10, v11);
            }
            if (Ch) {
                __nv_bfloat16 h[2], l[2];
                split1(v00, h[0], l[0]); split1(v01, h[1], l[1]);
                *(uint32_t*)(Ch + (size_t)r0 * ldc + col) = *(uint32_t*)h;
                *(uint32_t*)(Cl + (size_t)r0 * ldc + col) = *(uint32_t*)l;
                split1(v10, h[0], l[0]); split1(v11, h[1], l[1]);
                *(uint32_t*)(Ch + (size_t)(r0 + 8) * ldc + col) = *(uint32_t*)h;
                *(uint32_t*)(Cl + (size_t)(r0 + 8) * ldc + col) = *(uint32_t*)l;
            }
        }
    }
}

// ---------------------------------------------------------------------------
// LayerNorm (optional residual, optional fp32 out, optional bf16 hi/lo out)
// ---------------------------------------------------------------------------
__device__ __forceinline__ void block_reduce2(float& s, float& q, int t) {
    #pragma unroll
    for (int o = 16; o > 0; o >>= 1) {
        s += __shfl_xor_sync(0xffffffffu, s, o);
        q += __shfl_xor_sync(0xffffffffu, q, o);
    }
    __shared__ float ss[4], sq[4];
    const int w = t >> 5, nw = blockDim.x >> 5;
    if ((t & 31) == 0) { ss[w] = s; sq[w] = q; }
    __syncthreads();
    s = 0.f; q = 0.f;
    for (int i = 0; i < nw; i++) { s += ss[i]; q += sq[i]; }
}

__device__ __forceinline__ void ln_store(float4 o, float* Y, __nv_bfloat16* H,
                                         __nv_bfloat16* L, size_t off) {
    if (Y) *(float4*)(Y + off) = o;
    if (H) {
        __nv_bfloat16 h[4], l[4];
        split1(o.x, h[0], l[0]); split1(o.y, h[1], l[1]);
        split1(o.z, h[2], l[2]); split1(o.w, h[3], l[3]);
        *(uint2*)(H + off) = *(uint2*)h;
        *(uint2*)(L + off) = *(uint2*)l;
    }
}

__global__ void ln_kernel(const float* __restrict__ X, int ldx,
                          const float* __restrict__ R, int ldr,
                          const float* __restrict__ g, const float* __restrict__ b,
                          float* __restrict__ Y,
                          __nv_bfloat16* __restrict__ H,
                          __nv_bfloat16* __restrict__ L, int ldy)
{
    const int row = blockIdx.x, t = threadIdx.x;
    const float D = (float)(blockDim.x << 2);
    float4 v = *(const float4*)(X + (size_t)row * ldx + (t << 2));
    if (R) {
        float4 r = *(const float4*)(R + (size_t)row * ldr + (t << 2));
        v.x += r.x; v.y += r.y; v.z += r.z; v.w += r.w;
    }
    float s = v.x + v.y + v.z + v.w;
    float q = v.x * v.x + v.y * v.y + v.z * v.z + v.w * v.w;
    block_reduce2(s, q, t);
    const float mean = s / D;
    const float rstd = rsqrtf(fmaxf(q / D - mean * mean, 0.f) + 1e-5f);
    const float4 g4 = *(const float4*)(g + (t << 2));
    const float4 b4 = *(const float4*)(b + (t << 2));
    float4 o;
    o.x = (v.x - mean) * rstd * g4.x + b4.x;
    o.y = (v.y - mean) * rstd * g4.y + b4.y;
    o.z = (v.z - mean) * rstd * g4.z + b4.z;
    o.w = (v.w - mean) * rstd * g4.w + b4.w;
    ln_store(o, Y, H, L, (size_t)row * ldy + (t << 2));
}

// time branch: LN((diag+1) * x_time)
__global__ void ln_diag_kernel(const float* __restrict__ X,
                               const float* __restrict__ diag,
                               const float* __restrict__ g, const float* __restrict__ b,
                               float* __restrict__ Y,
                               __nv_bfloat16* __restrict__ H,
                               __nv_bfloat16* __restrict__ L, int ldy)
{
    const int row = blockIdx.x, t = threadIdx.x;
    const int bb = row >> 9, l = row & 511;
    const int h = t >> 3;
    const float dscale = diag[((size_t)bb * NH + h) * LL + l] + 1.f;
    float4 v = *(const float4*)(X + (size_t)row * DT + (t << 2));
    v.x *= dscale; v.y *= dscale; v.z *= dscale; v.w *= dscale;
    float s = v.x + v.y + v.z + v.w;
    float q = v.x * v.x + v.y * v.y + v.z * v.z + v.w * v.w;
    block_reduce2(s, q, t);
    const float mean = s / (float)DT;
    const float rstd = rsqrtf(fmaxf(q / (float)DT - mean * mean, 0.f) + 1e-5f);
    const float4 g4 = *(const float4*)(g + (t << 2));
    const float4 b4 = *(const float4*)(b + (t << 2));
    float4 o;
    o.x = (v.x - mean) * rstd * g4.x + b4.x;
    o.y = (v.y - mean) * rstd * g4.y + b4.y;
    o.z = (v.z - mean) * rstd * g4.z + b4.z;
    o.w = (v.w - mean) * rstd * g4.w + b4.w;
    ln_store(o, Y, H, L, (size_t)row * ldy + (t << 2));
}

// ---------------------------------------------------------------------------
// Fused flash attention per (b,h); emits bf16 hi/lo att + diag.
// ---------------------------------------------------------------------------
#define ATT_SMEM ((64 * 64 + 64 * 68 + 64 * 64) * 4)

__global__ __launch_bounds__(128)
void attn_kernel(const float* __restrict__ qkv,
                 __nv_bfloat16* __restrict__ attH,
                 __nv_bfloat16* __restrict__ attL,
                 float* __restrict__ diag)
{
    extern __shared__ float smf[];
    float* Qs = smf;
    float* Ks = smf + 64 * 64;
    float* Vs = Ks + 64 * 68;

    const int tid = threadIdx.x;
    const int qt = blockIdx.x;
    const int bh = blockIdx.y;
    const int b = bh >> 3, h = bh & 7;

    const float* qb = qkv + ((size_t)b * LL) * (3 * DM) + h * HD;
    const float* kb = qb + DM;
    const float* vb = qb + 2 * DM;

    #pragma unroll
    for (int i = 0; i < 8; i++) {
        const int idx = tid + i * 128;
        const int r = idx >> 4, c4 = (idx & 15) * 4;
        *(float4*)(Qs + r * 64 + c4) =
            *(const float4*)(qb + (size_t)(qt * 64 + r) * (3 * DM) + c4);
    }

    const int rg = tid >> 3;
    const int cg = tid & 7;

    float m[4], l[4], sd[4], o[4][8];
    #pragma unroll
    for (int i = 0; i < 4; i++) {
        m[i] = -1e30f; l[i] = 0.f; sd[i] = 0.f;
        #pragma unroll
        for (int j = 0; j < 8; j++) o[i][j] = 0.f;
    }

    for (int kt = 0; kt < 8; kt++) {
        __syncthreads();
        #pragma unroll
        for (int i = 0; i < 8; i++) {
            const int idx = tid + i * 128;
            const int r = idx >> 4, c4 = (idx & 15) * 4;
            *(float4*)(Ks + r * 68 + c4) =
                *(const float4*)(kb + (size_t)(kt * 64 + r) * (3 * DM) + c4);
            *(float4*)(Vs + r * 64 + c4) =
                *(const float4*)(vb + (size_t)(kt * 64 + r) * (3 * DM) + c4);
        }
        __syncthreads();

        float s[4][8];
        #pragma unroll
        for (int i = 0; i < 4; i++)
            #pragma unroll
            for (int j = 0; j < 8; j++) s[i][j] = 0.f;

        #pragma unroll
        for (int d4 = 0; d4 < 16; d4++) {
            float4 q4[4];
            #pragma unroll
            for (int i = 0; i < 4; i++)
                q4[i] = *(const float4*)(Qs + (rg * 4 + i) * 64 + d4 * 4);
            #pragma unroll
            for (int j = 0; j < 8; j++) {
                const float4 kv = *(const float4*)(Ks + (cg + 8 * j) * 68 + d4 * 4);
                #pragma unroll
                for (int i = 0; i < 4; i++)
                    s[i][j] += q4[i].x * kv.x + q4[i].y * kv.y
                             + q4[i].z * kv.z + q4[i].w * kv.w;
            }
        }

        #pragma unroll
        for (int i = 0; i < 4; i++)
            #pragma unroll
            for (int j = 0; j < 8; j++) s[i][j] *= 0.125f;

        if (kt == qt) {
            #pragma unroll
            for (int i = 0; i < 4; i++) {
                const int r = rg * 4 + i;
                if ((r & 7) == cg) sd[i] = s[i][r >> 3];
            }
        }

        #pragma unroll
        for (int i = 0; i < 4; i++) {
            float mt = s[i][0];
            #pragma unroll
            for (int j = 1; j < 8; j++) mt = fmaxf(mt, s[i][j]);
            mt = fmaxf(mt, __shfl_xor_sync(0xffffffffu, mt, 1));
            mt = fmaxf(mt, __shfl_xor_sync(0xffffffffu, mt, 2));
            mt = fmaxf(mt, __shfl_xor_sync(0xffffffffu, mt, 4));
            const float mn = fmaxf(m[i], mt);
            const float corr = __expf(m[i] - mn);
            float ps = 0.f;
            #pragma unroll
            for (int j = 0; j < 8; j++) {
                const float p = __expf(s[i][j] - mn);
                s[i][j] = p; ps += p;
            }
            ps += __shfl_xor_sync(0xffffffffu, ps, 1);
            ps += __shfl_xor_sync(0xffffffffu, ps, 2);
            ps += __shfl_xor_sync(0xffffffffu, ps, 4);
            l[i] = l[i] * corr + ps;
            m[i] = mn;
            #pragma unroll
            for (int j = 0; j < 8; j++) o[i][j] *= corr;
        }

        __syncthreads();
        #pragma unroll
        for (int i = 0; i < 4; i++)
            #pragma unroll
            for (int j = 0; j < 8; j++)
                Ks[(rg * 4 + i) * 68 + cg + 8 * j] = s[i][j];
        __syncthreads();

        #pragma unroll 4
        for (int c = 0; c < 64; c++) {
            const float4 v0 = *(const float4*)(Vs + c * 64 + cg * 8);
            const float4 v1 = *(const float4*)(Vs + c * 64 + cg * 8 + 4);
            #pragma unroll
            for (int i = 0; i < 4; i++) {
                const float p = Ks[(rg * 4 + i) * 68 + c];
                o[i][0] += p * v0.x; o[i][1] += p * v0.y;
                o[i][2] += p * v0.z; o[i][3] += p * v0.w;
                o[i][4] += p * v1.x; o[i][5] += p * v1.y;
                o[i][6] += p * v1.z; o[i][7] += p * v1.w;
            }
        }
    }

    #pragma unroll
    for (int i = 0; i < 4; i++) {
        const float inv = 1.f / l[i];
        const int rl = rg * 4 + i;
        const int r = qt * 64 + rl;
        const size_t off = ((size_t)b * LL + r) * DM + h * HD + cg * 8;
        __nv_bfloat16 hv[8], lv[8];
        #pragma unroll
        for (int j = 0; j < 8; j++) split1(o[i][j] * inv, hv[j], lv[j]);
        *(uint4*)(attH + off) = *(uint4*)hv;
        *(uint4*)(attL + off) = *(uint4*)lv;
        if ((rl & 7) == cg)
            diag[(size_t)bh * LL + r] = __expf(sd[i] - m[i]) * inv;
    }
}

// ---------------------------------------------------------------------------
// MaxPool 16 over seq, concat tok|time -> bf16 hi/lo [1024, 768]
// ---------------------------------------------------------------------------
__global__ void pool_kernel(const float* __restrict__ tok,
                            const float* __restrict__ tim,
                            __nv_bfloat16* __restrict__ pcH,
                            __nv_bfloat16* __restrict__ pcL)
{
    const int orow = blockIdx.x;
    const int b = orow >> 5, gq = orow & 31;
    for (int d = threadIdx.x; d < DCAT; d += blockDim.x) {
        float mx = -1e30f;
        if (d < DM) {
            const float* p = tok + ((size_t)b * LL + gq * 16) * DM + d;
            #pragma unroll
            for (int j = 0; j < 16; j++) mx = fmaxf(mx, p[j * DM]);
        } else {
            const float* p = tim + ((size_t)b * LL + gq * 16) * DT + (d - DM);
            #pragma unroll
            for (int j = 0; j < 16; j++) mx = fmaxf(mx, p[j * DT]);
        }
        __nv_bfloat16 h, l;
        split1(mx, h, l);
        pcH[(size_t)orow * DCAT + d] = h;
        pcL[(size_t)orow * DCAT + d] = l;
    }
}

// ---------------------------------------------------------------------------
// Host orchestration
// ---------------------------------------------------------------------------
static void split_launch(const float* X, __nv_bfloat16* H, __nv_bfloat16* L, long n)
{
    const int n4 = (int)(n / 4);
    split_kernel<<<(n4 + 255) / 256, 256>>>(X, H, L, n4);
}

extern "C" void kernel_launch(void* const* d_in, const int* in_sizes, int n_in,
                              void* d_out, int out_size)
{
    const float* in[26];
    for (int i = 0; i < 26; i++) in[i] = (const float*)d_in[i];

    float *x, *qkvb, *ao, *xc, *ff, *tok, *timeb, *diag, *o1;
    cudaGetSymbolAddress((void**)&x,     g_x);
    cudaGetSymbolAddress((void**)&qkvb,  g_qkv);
    cudaGetSymbolAddress((void**)&ao,    g_ao);
    cudaGetSymbolAddress((void**)&xc,    g_xc);
    cudaGetSymbolAddress((void**)&ff,    g_ff);
    cudaGetSymbolAddress((void**)&tok,   g_tok);
    cudaGetSymbolAddress((void**)&timeb, g_time);
    cudaGetSymbolAddress((void**)&diag,  g_diag);
    cudaGetSymbolAddress((void**)&o1,    g_o1);

    __nv_bfloat16 *ln0h, *ln0l, *xh, *xl, *atth, *attl, *xch, *xcl, *h1h, *h1l,
                  *pch, *pcl, *wh, *wl;
    cudaGetSymbolAddress((void**)&ln0h, g_ln0h); cudaGetSymbolAddress((void**)&ln0l, g_ln0l);
    cudaGetSymbolAddress((void**)&xh,   g_xh);   cudaGetSymbolAddress((void**)&xl,   g_xl);
    cudaGetSymbolAddress((void**)&atth, g_atth); cudaGetSymbolAddress((void**)&attl, g_attl);
    cudaGetSymbolAddress((void**)&xch,  g_xch);  cudaGetSymbolAddress((void**)&xcl,  g_xcl);
    cudaGetSymbolAddress((void**)&h1h,  g_h1h);  cudaGetSymbolAddress((void**)&h1l,  g_h1l);
    cudaGetSymbolAddress((void**)&pch,  g_pch);  cudaGetSymbolAddress((void**)&pcl,  g_pcl);
    cudaGetSymbolAddress((void**)&wh,   g_wh);   cudaGetSymbolAddress((void**)&wl,   g_wl);

    cudaFuncSetAttribute(attn_kernel,
                         cudaFuncAttributeMaxDynamicSharedMemorySize, ATT_SMEM);
    cudaFuncSetAttribute(gemm_bf,
                         cudaFuncAttributeMaxDynamicSharedMemorySize, GEMM_SMEM);

    // pre-split all weights
    split_launch(in[4],  wh + OFF_W_IN,  wl + OFF_W_IN,  (long)NLAYER * DM * DM);
    split_launch(in[6],  wh + OFF_W_QKV, wl + OFF_W_QKV, (long)NLAYER * 3 * DM * DM);
    split_launch(in[8],  wh + OFF_W_AO,  wl + OFF_W_AO,  (long)NLAYER * DM * DM);
    split_launch(in[10], wh + OFF_W_L1,  wl + OFF_W_L1,  (long)NLAYER * DFF * DCAT);
    split_launch(in[12], wh + OFF_W_L2,  wl + OFF_W_L2,  (long)NLAYER * DCAT * DFF);
    split_launch(in[22], wh + OFF_W_OUT, wl + OFF_W_OUT, (long)DT * DCAT);

    const int M = MROWS;
    for (int i = 0; i < NLAYER; i++) {
        const float* xin = i ? tok : in[0];
        const float* tin = i ? timeb : in[1];

        // norm0 -> bf16 only
        ln_kernel<<<M, 128>>>(xin, DM, nullptr, 0,
                              in[2] + i * DM, in[3] + i * DM,
                              nullptr, ln0h, ln0l, DM);
        // in_proj -> fp32 x (residual) + bf16
        gemm_bf<<<dim3(M / 128, DM / 128), 256, GEMM_SMEM>>>(
            ln0h, ln0l, DM, wh + OFF_W_IN + (long)i * DM * DM,
            wl + OFF_W_IN + (long)i * DM * DM, DM, in[5] + i * DM,
            x, xh, xl, DM, 0);
        // qkv -> fp32 only
        gemm_bf<<<dim3(M / 128, 3 * DM / 128), 256, GEMM_SMEM>>>(
            xh, xl, DM, wh + OFF_W_QKV + (long)i * 3 * DM * DM,
            wl + OFF_W_QKV + (long)i * 3 * DM * DM, DM, in[7] + i * 3 * DM,
            qkvb, nullptr, nullptr, 3 * DM, 0);

        attn_kernel<<<dim3(LL / 64, BB * NH), 128, ATT_SMEM>>>(qkvb, atth, attl, diag);

        // attn out proj -> fp32 only
        gemm_bf<<<dim3(M / 128, DM / 128), 256, GEMM_SMEM>>>(
            atth, attl, DM, wh + OFF_W_AO + (long)i * DM * DM,
            wl + OFF_W_AO + (long)i * DM * DM, DM, in[9] + i * DM,
            ao, nullptr, nullptr, DM, 0);

        // n1 -> xc fp32 + bf16 ; n2 -> xc+DM fp32 + bf16
        ln_kernel<<<M, 128>>>(ao, DM, x, DM,
                              in[14] + i * DM, in[15] + i * DM,
                              xc, xch, xcl, DCAT);
        ln_diag_kernel<<<M, 64>>>(tin, diag,
                                  in[16] + i * DT, in[17] + i * DT,
                                  xc + DM, xch + DM, xcl + DM, DCAT);

        // FF1 -> bf16 only ; FF2 -> fp32 only
        gemm_bf<<<dim3(M / 128, DFF / 128), 256, GEMM_SMEM>>>(
            xch, xcl, DCAT, wh + OFF_W_L1 + (long)i * DFF * DCAT,
            wl + OFF_W_L1 + (long)i * DFF * DCAT, DCAT, in[11] + i * DFF,
            nullptr, h1h, h1l, DFF, 1);
        gemm_bf<<<dim3(M / 128, DCAT / 128), 256, GEMM_SMEM>>>(
            h1h, h1l, DFF, wh + OFF_W_L2 + (long)i * DCAT * DFF,
            wl + OFF_W_L2 + (long)i * DCAT * DFF, DFF, in[13] + i * DCAT,
            ff, nullptr, nullptr, DCAT, 0);

        // n3 / n4 -> fp32 streams
        ln_kernel<<<M, 128>>>(ff, DCAT, xc, DCAT,
                              in[18] + i * DM, in[19] + i * DM,
                              tok, nullptr, nullptr, DM);
        ln_kernel<<<M, 64>>>(ff + DM, DCAT, xc + DM, DCAT,
                             in[20] + i * DT, in[21] + i * DT,
                             timeb, nullptr, nullptr, DT);
    }

    pool_kernel<<<BB * 32, 256>>>(tok, timeb, pch, pcl);
    gemm_bf<<<dim3(BB * 32 / 128, DT / 128), 256, GEMM_SMEM>>>(
        pch, pcl, DCAT, wh + OFF_W_OUT, wl + OFF_W_OUT, DCAT, in[23],
        o1, nullptr, nullptr, DT, 2);
    ln_kernel<<<BB * 32, 64>>>(o1, DT, nullptr, 0, in[24], in[25],
                               (float*)d_out, nullptr, nullptr, DT);
}

// round 7
// speedup vs baseline: 2.4434x; 1.4365x over previous
#include <cuda_runtime.h>
#include <cuda_fp16.h>
#include <math.h>
#include <stdint.h>

// ---------------------------------------------------------------------------
// Problem constants
// ---------------------------------------------------------------------------
#define BB 32
#define LL 512
#define DM 512
#define DT 256
#define NH 8
#define HD 64
#define DFF 2048
#define NLAYER 2
#define MROWS (BB * LL)          // 16384
#define DCAT (DM + DT)           // 768

// ---------------------------------------------------------------------------
// Scratch (device globals)
// ---------------------------------------------------------------------------
__device__ float g_x   [MROWS * DM];
__device__ float g_qkv [MROWS * 3 * DM];
__device__ float g_ao  [MROWS * DM];
__device__ float g_xc  [MROWS * DCAT];
__device__ float g_ff  [MROWS * DCAT];
__device__ float g_tok [MROWS * DM];
__device__ float g_time[MROWS * DT];
__device__ float g_diag[BB * NH * LL];
__device__ float g_o1  [BB * 32 * DT];

// fp16 hi/lo activation buffers (GEMM A inputs)
__device__ __half g_ln0h[MROWS * DM],  g_ln0l[MROWS * DM];
__device__ __half g_xh  [MROWS * DM],  g_xl  [MROWS * DM];
__device__ __half g_atth[MROWS * DM],  g_attl[MROWS * DM];
__device__ __half g_xch [MROWS * DCAT],g_xcl [MROWS * DCAT];
__device__ __half g_h1h [MROWS * DFF], g_h1l [MROWS * DFF];
__device__ __half g_pch [BB * 32 * DCAT], g_pcl[BB * 32 * DCAT];

// fp16 weights (single precision-limited copy; B-low term dropped)
#define OFF_W_IN  0
#define OFF_W_QKV (OFF_W_IN  + NLAYER * DM * DM)
#define OFF_W_AO  (OFF_W_QKV + NLAYER * 3 * DM * DM)
#define OFF_W_L1  (OFF_W_AO  + NLAYER * DM * DM)
#define OFF_W_L2  (OFF_W_L1  + NLAYER * DFF * DCAT)
#define OFF_W_OUT (OFF_W_L2  + NLAYER * DCAT * DFF)
#define W_TOTAL   (OFF_W_OUT + DT * DCAT)
__device__ __half g_wh[W_TOTAL];

// ---------------------------------------------------------------------------
// Helpers
// ---------------------------------------------------------------------------
__device__ __forceinline__ uint32_t smem_u32(const void* p) {
    uint32_t a;
    asm("{ .reg .u64 t; cvta.to.shared.u64 t, %1; cvt.u32.u64 %0, t; }"
        : "=r"(a) : "l"(p));
    return a;
}

__device__ __forceinline__ void split1(float v, __half& h, __half& l) {
    h = __float2half_rn(v);
    l = __float2half_rn(v - __half2float(h));
}

// weights: float -> fp16 (hi only)
__global__ void wsplit_kernel(const float* __restrict__ X,
                              __half* __restrict__ H, int n4)
{
    const int i = blockIdx.x * blockDim.x + threadIdx.x;
    if (i >= n4) return;
    const float4 v = *(const float4*)(X + (size_t)i * 4);
    __half h[4];
    h[0] = __float2half_rn(v.x); h[1] = __float2half_rn(v.y);
    h[2] = __float2half_rn(v.z); h[3] = __float2half_rn(v.w);
    *(uint2*)(H + (size_t)i * 4) = *(uint2*)h;
}

// ---------------------------------------------------------------------------
// fp16x2 mma.sync GEMM: C = act(A @ W^T + bias)
// A = Ah + Al (fp16 hi/lo), W = Wh (fp16). D += Ah*Wh + Al*Wh, fp32 accum.
// 128x128 CTA tile, K-chunk 32, 8 warps of 32x64, cp.async double buffer.
// ---------------------------------------------------------------------------
#define PITCH_B 80
#define OFF_AH 0
#define OFF_AL (128 * PITCH_B)        // 10240
#define OFF_BH (2 * 128 * PITCH_B)    // 20480
#define STAGE_B (3 * 128 * PITCH_B)   // 30720
#define GEMM_SMEM (2 * STAGE_B)       // 61440

#define LDSM4(R, addr) \
    asm volatile("ldmatrix.sync.aligned.m8n8.x4.shared.b16 {%0,%1,%2,%3}, [%4];" \
        : "=r"((R)[0]), "=r"((R)[1]), "=r"((R)[2]), "=r"((R)[3]) : "r"(addr))

#define MMA16816(D, A, B0, B1) \
    asm volatile("mma.sync.aligned.m16n8k16.row.col.f32.f16.f16.f32 " \
        "{%0,%1,%2,%3}, {%4,%5,%6,%7}, {%8,%9}, {%0,%1,%2,%3};" \
        : "+f"((D)[0]), "+f"((D)[1]), "+f"((D)[2]), "+f"((D)[3]) \
        : "r"((A)[0]), "r"((A)[1]), "r"((A)[2]), "r"((A)[3]), "r"(B0), "r"(B1))

__device__ __forceinline__ void cp_async16(uint32_t d, const void* s) {
    asm volatile("cp.async.cg.shared.global [%0], [%1], 16;" :: "r"(d), "l"(s));
}
#define CP_COMMIT() asm volatile("cp.async.commit_group;" ::: "memory")
#define CP_WAIT(n)  asm volatile("cp.async.wait_group %0;" :: "n"(n) : "memory")

__device__ __forceinline__ float act_apply(float v, int act) {
    if (act == 1) return fmaxf(v, 0.f);
    if (act == 2) return 0.5f * v * (1.f + erff(v * 0.70710678118654752f));
    return v;
}

__global__ __launch_bounds__(256)
void gemm_hf(const __half* __restrict__ Ah, const __half* __restrict__ Al,
             int lda,
             const __half* __restrict__ Wh, int K,
             const float* __restrict__ bias,
             float* __restrict__ Cf,
             __half* __restrict__ Ch, __half* __restrict__ Cl,
             int ldc, int act)
{
    extern __shared__ char sm[];
    const uint32_t sb = smem_u32(sm);

    const int tid = threadIdx.x;
    const int wid = tid >> 5;
    const int lane = tid & 31;
    const int m0 = blockIdx.x * 128;
    const int n0 = blockIdx.y * 128;
    const int wr = wid & 3;
    const int wc = wid >> 2;

    // global load mapping: 2 threads per row, 16 halves (32B) each
    const int grow = tid >> 1;
    const int gcol = (tid & 1) * 16;
    const __half* Ahp = Ah + (size_t)(m0 + grow) * lda + gcol;
    const __half* Alp = Al + (size_t)(m0 + grow) * lda + gcol;
    const __half* Whp = Wh + (size_t)(n0 + grow) * K + gcol;
    const uint32_t sts_off = (uint32_t)grow * PITCH_B + (uint32_t)gcol * 2;

    // ldmatrix lane addressing
    const int a_lrow = (lane & 7) + ((lane >> 3) & 1) * 8;
    const int a_koff = (lane >> 4) * 8;
    const int b_lrow = (lane & 7) + ((lane >> 4) & 1) * 8;
    const int b_koff = ((lane >> 3) & 1) * 8;
    const uint32_t a_lbase = (uint32_t)(wr * 32 + a_lrow) * PITCH_B + (uint32_t)a_koff * 2;
    const uint32_t b_lbase = (uint32_t)(wc * 64 + b_lrow) * PITCH_B + (uint32_t)b_koff * 2;

    float acc[2][8][4];
    #pragma unroll
    for (int mt = 0; mt < 2; mt++)
        #pragma unroll
        for (int nt = 0; nt < 8; nt++)
            #pragma unroll
            for (int r = 0; r < 4; r++) acc[mt][nt][r] = 0.f;

    const int NC = K >> 5;

    auto issue = [&](int c) {
        const uint32_t d = sb + (uint32_t)(c & 1) * STAGE_B + sts_off;
        cp_async16(d + OFF_AH,      Ahp + c * 32);
        cp_async16(d + OFF_AH + 16, Ahp + c * 32 + 8);
        cp_async16(d + OFF_AL,      Alp + c * 32);
        cp_async16(d + OFF_AL + 16, Alp + c * 32 + 8);
        cp_async16(d + OFF_BH,      Whp + c * 32);
        cp_async16(d + OFF_BH + 16, Whp + c * 32 + 8);
        CP_COMMIT();
    };

    issue(0);
    if (NC > 1) issue(1);

    for (int c = 0; c < NC; c++) {
        if (c + 1 < NC) CP_WAIT(1); else CP_WAIT(0);
        __syncthreads();

        const uint32_t so = (uint32_t)(c & 1) * STAGE_B;

        #pragma unroll
        for (int step = 0; step < 2; step++) {
            const uint32_t kb = (uint32_t)step * 32;

            uint32_t ahr[2][4], alr[2][4];
            #pragma unroll
            for (int mt = 0; mt < 2; mt++) {
                const uint32_t aa = sb + so + a_lbase + (uint32_t)mt * (16 * PITCH_B) + kb;
                LDSM4(ahr[mt], aa + OFF_AH);
                LDSM4(alr[mt], aa + OFF_AL);
            }

            #pragma unroll
            for (int g = 0; g < 4; g++) {
                const uint32_t ba = sb + so + b_lbase + (uint32_t)g * (16 * PITCH_B) + kb;
                uint32_t bh[4];
                LDSM4(bh, ba + OFF_BH);
                #pragma unroll
                for (int mt = 0; mt < 2; mt++) {
                    MMA16816(acc[mt][2 * g],     ahr[mt], bh[0], bh[1]);
                    MMA16816(acc[mt][2 * g],     alr[mt], bh[0], bh[1]);
                    MMA16816(acc[mt][2 * g + 1], ahr[mt], bh[2], bh[3]);
                    MMA16816(acc[mt][2 * g + 1], alr[mt], bh[2], bh[3]);
                }
            }
        }
        __syncthreads();
        if (c + 2 < NC) issue(c + 2);
    }

    // epilogue
    const int g = lane >> 2;
    const int t = lane & 3;
    #pragma unroll
    for (int mt = 0; mt < 2; mt++) {
        #pragma unroll
        for (int nt = 0; nt < 8; nt++) {
            const int col = n0 + wc * 64 + nt * 8 + t * 2;
            const float b0 = bias[col], b1 = bias[col + 1];
            const int r0 = m0 + wr * 32 + mt * 16 + g;
            float v00 = act_apply(acc[mt][nt][0] + b0, act);
            float v01 = act_apply(acc[mt][nt][1] + b1, act);
            float v10 = act_apply(acc[mt][nt][2] + b0, act);
            float v11 = act_apply(acc[mt][nt][3] + b1, act);
            if (Cf) {
                *(float2*)(Cf + (size_t)r0 * ldc + col) = make_float2(v00, v01);
                *(float2*)(Cf + (size_t)(r0 + 8) * ldc + col) = make_float2(v10, v11);
            }
            if (Ch) {
                __half h[2], l[2];
                split1(v00, h[0], l[0]); split1(v01, h[1], l[1]);
                *(uint32_t*)(Ch + (size_t)r0 * ldc + col) = *(uint32_t*)h;
                *(uint32_t*)(Cl + (size_t)r0 * ldc + col) = *(uint32_t*)l;
                split1(v10, h[0], l[0]); split1(v11, h[1], l[1]);
                *(uint32_t*)(Ch + (size_t)(r0 + 8) * ldc + col) = *(uint32_t*)h;
                *(uint32_t*)(Cl + (size_t)(r0 + 8) * ldc + col) = *(uint32_t*)l;
            }
        }
    }
}

// ---------------------------------------------------------------------------
// LayerNorm (optional residual, optional fp32 out, optional fp16 hi/lo out)
// ---------------------------------------------------------------------------
__device__ __forceinline__ void block_reduce2(float& s, float& q, int t) {
    #pragma unroll
    for (int o = 16; o > 0; o >>= 1) {
        s += __shfl_xor_sync(0xffffffffu, s, o);
        q += __shfl_xor_sync(0xffffffffu, q, o);
    }
    __shared__ float ss[4], sq[4];
    const int w = t >> 5, nw = blockDim.x >> 5;
    if ((t & 31) == 0) { ss[w] = s; sq[w] = q; }
    __syncthreads();
    s = 0.f; q = 0.f;
    for (int i = 0; i < nw; i++) { s += ss[i]; q += sq[i]; }
}

__device__ __forceinline__ void ln_store(float4 o, float* Y, __half* H,
                                         __half* L, size_t off) {
    if (Y) *(float4*)(Y + off) = o;
    if (H) {
        __half h[4], l[4];
        split1(o.x, h[0], l[0]); split1(o.y, h[1], l[1]);
        split1(o.z, h[2], l[2]); split1(o.w, h[3], l[3]);
        *(uint2*)(H + off) = *(uint2*)h;
        *(uint2*)(L + off) = *(uint2*)l;
    }
}

__global__ void ln_kernel(const float* __restrict__ X, int ldx,
                          const float* __restrict__ R, int ldr,
                          const float* __restrict__ g, const float* __restrict__ b,
                          float* __restrict__ Y,
                          __half* __restrict__ H,
                          __half* __restrict__ L, int ldy)
{
    const int row = blockIdx.x, t = threadIdx.x;
    const float D = (float)(blockDim.x << 2);
    float4 v = *(const float4*)(X + (size_t)row * ldx + (t << 2));
    if (R) {
        float4 r = *(const float4*)(R + (size_t)row * ldr + (t << 2));
        v.x += r.x; v.y += r.y; v.z += r.z; v.w += r.w;
    }
    float s = v.x + v.y + v.z + v.w;
    float q = v.x * v.x + v.y * v.y + v.z * v.z + v.w * v.w;
    block_reduce2(s, q, t);
    const float mean = s / D;
    const float rstd = rsqrtf(fmaxf(q / D - mean * mean, 0.f) + 1e-5f);
    const float4 g4 = *(const float4*)(g + (t << 2));
    const float4 b4 = *(const float4*)(b + (t << 2));
    float4 o;
    o.x = (v.x - mean) * rstd * g4.x + b4.x;
    o.y = (v.y - mean) * rstd * g4.y + b4.y;
    o.z = (v.z - mean) * rstd * g4.z + b4.z;
    o.w = (v.w - mean) * rstd * g4.w + b4.w;
    ln_store(o, Y, H, L, (size_t)row * ldy + (t << 2));
}

// time branch: LN((diag+1) * x_time)
__global__ void ln_diag_kernel(const float* __restrict__ X,
                               const float* __restrict__ diag,
                               const float* __restrict__ g, const float* __restrict__ b,
                               float* __restrict__ Y,
                               __half* __restrict__ H,
                               __half* __restrict__ L, int ldy)
{
    const int row = blockIdx.x, t = threadIdx.x;
    const int bb = row >> 9, l = row & 511;
    const int h = t >> 3;
    const float dscale = diag[((size_t)bb * NH + h) * LL + l] + 1.f;
    float4 v = *(const float4*)(X + (size_t)row * DT + (t << 2));
    v.x *= dscale; v.y *= dscale; v.z *= dscale; v.w *= dscale;
    float s = v.x + v.y + v.z + v.w;
    float q = v.x * v.x + v.y * v.y + v.z * v.z + v.w * v.w;
    block_reduce2(s, q, t);
    const float mean = s / (float)DT;
    const float rstd = rsqrtf(fmaxf(q / (float)DT - mean * mean, 0.f) + 1e-5f);
    const float4 g4 = *(const float4*)(g + (t << 2));
    const float4 b4 = *(const float4*)(b + (t << 2));
    float4 o;
    o.x = (v.x - mean) * rstd * g4.x + b4.x;
    o.y = (v.y - mean) * rstd * g4.y + b4.y;
    o.z = (v.z - mean) * rstd * g4.z + b4.z;
    o.w = (v.w - mean) * rstd * g4.w + b4.w;
    ln_store(o, Y, H, L, (size_t)row * ldy + (t << 2));
}

// ---------------------------------------------------------------------------
// Fused flash attention per (b,h); emits fp16 hi/lo att + diag.
// ---------------------------------------------------------------------------
#define ATT_SMEM ((64 * 64 + 64 * 68 + 64 * 64) * 4)

__global__ __launch_bounds__(128)
void attn_kernel(const float* __restrict__ qkv,
                 __half* __restrict__ attH,
                 __half* __restrict__ attL,
                 float* __restrict__ diag)
{
    extern __shared__ float smf[];
    float* Qs = smf;
    float* Ks = smf + 64 * 64;
    float* Vs = Ks + 64 * 68;

    const int tid = threadIdx.x;
    const int qt = blockIdx.x;
    const int bh = blockIdx.y;
    const int b = bh >> 3, h = bh & 7;

    const float* qb = qkv + ((size_t)b * LL) * (3 * DM) + h * HD;
    const float* kb = qb + DM;
    const float* vb = qb + 2 * DM;

    #pragma unroll
    for (int i = 0; i < 8; i++) {
        const int idx = tid + i * 128;
        const int r = idx >> 4, c4 = (idx & 15) * 4;
        *(float4*)(Qs + r * 64 + c4) =
            *(const float4*)(qb + (size_t)(qt * 64 + r) * (3 * DM) + c4);
    }

    const int rg = tid >> 3;
    const int cg = tid & 7;

    float m[4], l[4], sd[4], o[4][8];
    #pragma unroll
    for (int i = 0; i < 4; i++) {
        m[i] = -1e30f; l[i] = 0.f; sd[i] = 0.f;
        #pragma unroll
        for (int j = 0; j < 8; j++) o[i][j] = 0.f;
    }

    for (int kt = 0; kt < 8; kt++) {
        __syncthreads();
        #pragma unroll
        for (int i = 0; i < 8; i++) {
            const int idx = tid + i * 128;
            const int r = idx >> 4, c4 = (idx & 15) * 4;
            *(float4*)(Ks + r * 68 + c4) =
                *(const float4*)(kb + (size_t)(kt * 64 + r) * (3 * DM) + c4);
            *(float4*)(Vs + r * 64 + c4) =
                *(const float4*)(vb + (size_t)(kt * 64 + r) * (3 * DM) + c4);
        }
        __syncthreads();

        float s[4][8];
        #pragma unroll
        for (int i = 0; i < 4; i++)
            #pragma unroll
            for (int j = 0; j < 8; j++) s[i][j] = 0.f;

        #pragma unroll
        for (int d4 = 0; d4 < 16; d4++) {
            float4 q4[4];
            #pragma unroll
            for (int i = 0; i < 4; i++)
                q4[i] = *(const float4*)(Qs + (rg * 4 + i) * 64 + d4 * 4);
            #pragma unroll
            for (int j = 0; j < 8; j++) {
                const float4 kv = *(const float4*)(Ks + (cg + 8 * j) * 68 + d4 * 4);
                #pragma unroll
                for (int i = 0; i < 4; i++)
                    s[i][j] += q4[i].x * kv.x + q4[i].y * kv.y
                             + q4[i].z * kv.z + q4[i].w * kv.w;
            }
        }

        #pragma unroll
        for (int i = 0; i < 4; i++)
            #pragma unroll
            for (int j = 0; j < 8; j++) s[i][j] *= 0.125f;

        if (kt == qt) {
            #pragma unroll
            for (int i = 0; i < 4; i++) {
                const int r = rg * 4 + i;
                if ((r & 7) == cg) sd[i] = s[i][r >> 3];
            }
        }

        #pragma unroll
        for (int i = 0; i < 4; i++) {
            float mt = s[i][0];
            #pragma unroll
            for (int j = 1; j < 8; j++) mt = fmaxf(mt, s[i][j]);
            mt = fmaxf(mt, __shfl_xor_sync(0xffffffffu, mt, 1));
            mt = fmaxf(mt, __shfl_xor_sync(0xffffffffu, mt, 2));
            mt = fmaxf(mt, __shfl_xor_sync(0xffffffffu, mt, 4));
            const float mn = fmaxf(m[i], mt);
            const float corr = __expf(m[i] - mn);
            float ps = 0.f;
            #pragma unroll
            for (int j = 0; j < 8; j++) {
                const float p = __expf(s[i][j] - mn);
                s[i][j] = p; ps += p;
            }
            ps += __shfl_xor_sync(0xffffffffu, ps, 1);
            ps += __shfl_xor_sync(0xffffffffu, ps, 2);
            ps += __shfl_xor_sync(0xffffffffu, ps, 4);
            l[i] = l[i] * corr + ps;
            m[i] = mn;
            #pragma unroll
            for (int j = 0; j < 8; j++) o[i][j] *= corr;
        }

        __syncthreads();
        #pragma unroll
        for (int i = 0; i < 4; i++)
            #pragma unroll
            for (int j = 0; j < 8; j++)
                Ks[(rg * 4 + i) * 68 + cg + 8 * j] = s[i][j];
        __syncthreads();

        #pragma unroll 4
        for (int c = 0; c < 64; c++) {
            const float4 v0 = *(const float4*)(Vs + c * 64 + cg * 8);
            const float4 v1 = *(const float4*)(Vs + c * 64 + cg * 8 + 4);
            #pragma unroll
            for (int i = 0; i < 4; i++) {
                const float p = Ks[(rg * 4 + i) * 68 + c];
                o[i][0] += p * v0.x; o[i][1] += p * v0.y;
                o[i][2] += p * v0.z; o[i][3] += p * v0.w;
                o[i][4] += p * v1.x; o[i][5] += p * v1.y;
                o[i][6] += p * v1.z; o[i][7] += p * v1.w;
            }
        }
    }

    #pragma unroll
    for (int i = 0; i < 4; i++) {
        const float inv = 1.f / l[i];
        const int rl = rg * 4 + i;
        const int r = qt * 64 + rl;
        const size_t off = ((size_t)b * LL + r) * DM + h * HD + cg * 8;
        __half hv[8], lv[8];
        #pragma unroll
        for (int j = 0; j < 8; j++) split1(o[i][j] * inv, hv[j], lv[j]);
        *(uint4*)(attH + off) = *(uint4*)hv;
        *(uint4*)(attL + off) = *(uint4*)lv;
        if ((rl & 7) == cg)
            diag[(size_t)bh * LL + r] = __expf(sd[i] - m[i]) * inv;
    }
}

// ---------------------------------------------------------------------------
// MaxPool 16 over seq, concat tok|time -> fp16 hi/lo [1024, 768]
// ---------------------------------------------------------------------------
__global__ void pool_kernel(const float* __restrict__ tok,
                            const float* __restrict__ tim,
                            __half* __restrict__ pcH,
                            __half* __restrict__ pcL)
{
    const int orow = blockIdx.x;
    const int b = orow >> 5, gq = orow & 31;
    for (int d = threadIdx.x; d < DCAT; d += blockDim.x) {
        float mx = -1e30f;
        if (d < DM) {
            const float* p = tok + ((size_t)b * LL + gq * 16) * DM + d;
            #pragma unroll
            for (int j = 0; j < 16; j++) mx = fmaxf(mx, p[j * DM]);
        } else {
            const float* p = tim + ((size_t)b * LL + gq * 16) * DT + (d - DM);
            #pragma unroll
            for (int j = 0; j < 16; j++) mx = fmaxf(mx, p[j * DT]);
        }
        __half h, l;
        split1(mx, h, l);
        pcH[(size_t)orow * DCAT + d] = h;
        pcL[(size_t)orow * DCAT + d] = l;
    }
}

// ---------------------------------------------------------------------------
// Host orchestration
// ---------------------------------------------------------------------------
static void wsplit_launch(const float* X, __half* H, long n)
{
    const int n4 = (int)(n / 4);
    wsplit_kernel<<<(n4 + 255) / 256, 256>>>(X, H, n4);
}

extern "C" void kernel_launch(void* const* d_in, const int* in_sizes, int n_in,
                              void* d_out, int out_size)
{
    const float* in[26];
    for (int i = 0; i < 26; i++) in[i] = (const float*)d_in[i];

    float *x, *qkvb, *ao, *xc, *ff, *tok, *timeb, *diag, *o1;
    cudaGetSymbolAddress((void**)&x,     g_x);
    cudaGetSymbolAddress((void**)&qkvb,  g_qkv);
    cudaGetSymbolAddress((void**)&ao,    g_ao);
    cudaGetSymbolAddress((void**)&xc,    g_xc);
    cudaGetSymbolAddress((void**)&ff,    g_ff);
    cudaGetSymbolAddress((void**)&tok,   g_tok);
    cudaGetSymbolAddress((void**)&timeb, g_time);
    cudaGetSymbolAddress((void**)&diag,  g_diag);
    cudaGetSymbolAddress((void**)&o1,    g_o1);

    __half *ln0h, *ln0l, *xh, *xl, *atth, *attl, *xch, *xcl, *h1h, *h1l,
           *pch, *pcl, *wh;
    cudaGetSymbolAddress((void**)&ln0h, g_ln0h); cudaGetSymbolAddress((void**)&ln0l, g_ln0l);
    cudaGetSymbolAddress((void**)&xh,   g_xh);   cudaGetSymbolAddress((void**)&xl,   g_xl);
    cudaGetSymbolAddress((void**)&atth, g_atth); cudaGetSymbolAddress((void**)&attl, g_attl);
    cudaGetSymbolAddress((void**)&xch,  g_xch);  cudaGetSymbolAddress((void**)&xcl,  g_xcl);
    cudaGetSymbolAddress((void**)&h1h,  g_h1h);  cudaGetSymbolAddress((void**)&h1l,  g_h1l);
    cudaGetSymbolAddress((void**)&pch,  g_pch);  cudaGetSymbolAddress((void**)&pcl,  g_pcl);
    cudaGetSymbolAddress((void**)&wh,   g_wh);

    cudaFuncSetAttribute(attn_kernel,
                         cudaFuncAttributeMaxDynamicSharedMemorySize, ATT_SMEM);
    cudaFuncSetAttribute(gemm_hf,
                         cudaFuncAttributeMaxDynamicSharedMemorySize, GEMM_SMEM);

    // pre-convert all weights to fp16
    wsplit_launch(in[4],  wh + OFF_W_IN,  (long)NLAYER * DM * DM);
    wsplit_launch(in[6],  wh + OFF_W_QKV, (long)NLAYER * 3 * DM * DM);
    wsplit_launch(in[8],  wh + OFF_W_AO,  (long)NLAYER * DM * DM);
    wsplit_launch(in[10], wh + OFF_W_L1,  (long)NLAYER * DFF * DCAT);
    wsplit_launch(in[12], wh + OFF_W_L2,  (long)NLAYER * DCAT * DFF);
    wsplit_launch(in[22], wh + OFF_W_OUT, (long)DT * DCAT);

    const int M = MROWS;
    for (int i = 0; i < NLAYER; i++) {
        const float* xin = i ? tok : in[0];
        const float* tin = i ? timeb : in[1];

        // norm0 -> fp16 only
        ln_kernel<<<M, 128>>>(xin, DM, nullptr, 0,
                              in[2] + i * DM, in[3] + i * DM,
                              nullptr, ln0h, ln0l, DM);
        // in_proj -> fp32 x (residual) + fp16
        gemm_hf<<<dim3(M / 128, DM / 128), 256, GEMM_SMEM>>>(
            ln0h, ln0l, DM, wh + OFF_W_IN + (long)i * DM * DM, DM,
            in[5] + i * DM, x, xh, xl, DM, 0);
        // qkv -> fp32 only
        gemm_hf<<<dim3(M / 128, 3 * DM / 128), 256, GEMM_SMEM>>>(
            xh, xl, DM, wh + OFF_W_QKV + (long)i * 3 * DM * DM, DM,
            in[7] + i * 3 * DM, qkvb, nullptr, nullptr, 3 * DM, 0);

        attn_kernel<<<dim3(LL / 64, BB * NH), 128, ATT_SMEM>>>(qkvb, atth, attl, diag);

        // attn out proj -> fp32 only
        gemm_hf<<<dim3(M / 128, DM / 128), 256, GEMM_SMEM>>>(
            atth, attl, DM, wh + OFF_W_AO + (long)i * DM * DM, DM,
            in[9] + i * DM, ao, nullptr, nullptr, DM, 0);

        // n1 -> xc fp32 + fp16 ; n2 -> xc+DM fp32 + fp16
        ln_kernel<<<M, 128>>>(ao, DM, x, DM,
                              in[14] + i * DM, in[15] + i * DM,
                              xc, xch, xcl, DCAT);
        ln_diag_kernel<<<M, 64>>>(tin, diag,
                                  in[16] + i * DT, in[17] + i * DT,
                                  xc + DM, xch + DM, xcl + DM, DCAT);

        // FF1 -> fp16 only ; FF2 -> fp32 only
        gemm_hf<<<dim3(M / 128, DFF / 128), 256, GEMM_SMEM>>>(
            xch, xcl, DCAT, wh + OFF_W_L1 + (long)i * DFF * DCAT, DCAT,
            in[11] + i * DFF, nullptr, h1h, h1l, DFF, 1);
        gemm_hf<<<dim3(M / 128, DCAT / 128), 256, GEMM_SMEM>>>(
            h1h, h1l, DFF, wh + OFF_W_L2 + (long)i * DCAT * DFF, DFF,
            in[13] + i * DCAT, ff, nullptr, nullptr, DCAT, 0);

        // n3 / n4 -> fp32 streams
        ln_kernel<<<M, 128>>>(ff, DCAT, xc, DCAT,
                              in[18] + i * DM, in[19] + i * DM,
                              tok, nullptr, nullptr, DM);
        ln_kernel<<<M, 64>>>(ff + DM, DCAT, xc + DM, DCAT,
                             in[20] + i * DT, in[21] + i * DT,
                             timeb, nullptr, nullptr, DT);
    }

    pool_kernel<<<BB * 32, 256>>>(tok, timeb, pch, pcl);
    gemm_hf<<<dim3(BB * 32 / 128, DT / 128), 256, GEMM_SMEM>>>(
        pch, pcl, DCAT, wh + OFF_W_OUT, DCAT, in[23],
        o1, nullptr, nullptr, DT, 2);
    ln_kernel<<<BB * 32, 64>>>(o1, DT, nullptr, 0, in[24], in[25],
                               (float*)d_out, nullptr, nullptr, DT);
}

// round 9
// speedup vs baseline: 3.1248x; 1.2788x over previous
#include <cuda_runtime.h>
#include <cuda_fp16.h>
#include <math.h>
#include <stdint.h>

// ---------------------------------------------------------------------------
// Problem constants
// ---------------------------------------------------------------------------
#define BB 32
#define LL 512
#define DM 512
#define DT 256
#define NH 8
#define HD 64
#define DFF 2048
#define NLAYER 2
#define MROWS (BB * LL)          // 16384
#define DCAT (DM + DT)           // 768

// ---------------------------------------------------------------------------
// Scratch (device globals)
// ---------------------------------------------------------------------------
__device__ float g_x   [MROWS * DM];
__device__ float g_ao  [MROWS * DM];
__device__ float g_xc  [MROWS * DCAT];
__device__ float g_ff  [MROWS * DCAT];
__device__ float g_tok [MROWS * DM];
__device__ float g_time[MROWS * DT];
__device__ float g_diag[BB * NH * LL];
__device__ float g_o1  [BB * 32 * DT];

// fp16 hi/lo activation buffers
__device__ __half g_ln0h[MROWS * DM],  g_ln0l[MROWS * DM];
__device__ __half g_xh  [MROWS * DM],  g_xl  [MROWS * DM];
__device__ __half g_qkvh[MROWS * 3 * DM], g_qkvl[MROWS * 3 * DM];
__device__ __half g_atth[MROWS * DM],  g_attl[MROWS * DM];
__device__ __half g_xch [MROWS * DCAT],g_xcl [MROWS * DCAT];
__device__ __half g_h1h [MROWS * DFF], g_h1l [MROWS * DFF];
__device__ __half g_pch [BB * 32 * DCAT], g_pcl[BB * 32 * DCAT];

// fp16 weights
#define OFF_W_IN  0
#define OFF_W_QKV (OFF_W_IN  + NLAYER * DM * DM)
#define OFF_W_AO  (OFF_W_QKV + NLAYER * 3 * DM * DM)
#define OFF_W_L1  (OFF_W_AO  + NLAYER * DM * DM)
#define OFF_W_L2  (OFF_W_L1  + NLAYER * DFF * DCAT)
#define OFF_W_OUT (OFF_W_L2  + NLAYER * DCAT * DFF)
#define W_TOTAL   (OFF_W_OUT + DT * DCAT)
__device__ __half g_wh[W_TOTAL];

// ---------------------------------------------------------------------------
// Helpers
// ---------------------------------------------------------------------------
__device__ __forceinline__ uint32_t smem_u32(const void* p) {
    uint32_t a;
    asm("{ .reg .u64 t; cvta.to.shared.u64 t, %1; cvt.u32.u64 %0, t; }"
        : "=r"(a) : "l"(p));
    return a;
}

__device__ __forceinline__ void split1(float v, __half& h, __half& l) {
    h = __float2half_rn(v);
    l = __float2half_rn(v - __half2float(h));
}

// pack two floats into half2 hi + half2 lo words
__device__ __forceinline__ uint32_t pack_h2(float a, float b, uint32_t& lo) {
    __half ha, la, hb, lb;
    split1(a, ha, la); split1(b, hb, lb);
    lo = (uint32_t)__half_as_ushort(la) | ((uint32_t)__half_as_ushort(lb) << 16);
    return (uint32_t)__half_as_ushort(ha) | ((uint32_t)__half_as_ushort(hb) << 16);
}

// weights: float -> fp16 (hi only)
__global__ void wsplit_kernel(const float* __restrict__ X,
                              __half* __restrict__ H, int n4)
{
    const int i = blockIdx.x * blockDim.x + threadIdx.x;
    if (i >= n4) return;
    const float4 v = *(const float4*)(X + (size_t)i * 4);
    __half h[4];
    h[0] = __float2half_rn(v.x); h[1] = __float2half_rn(v.y);
    h[2] = __float2half_rn(v.z); h[3] = __float2half_rn(v.w);
    *(uint2*)(H + (size_t)i * 4) = *(uint2*)h;
}

// ---------------------------------------------------------------------------
// MMA / ldmatrix / cp.async primitives
// ---------------------------------------------------------------------------
#define LDSM4(R, addr) \
    asm volatile("ldmatrix.sync.aligned.m8n8.x4.shared.b16 {%0,%1,%2,%3}, [%4];" \
        : "=r"((R)[0]), "=r"((R)[1]), "=r"((R)[2]), "=r"((R)[3]) : "r"(addr))

#define LDSM4T(R, addr) \
    asm volatile("ldmatrix.sync.aligned.m8n8.x4.trans.shared.b16 {%0,%1,%2,%3}, [%4];" \
        : "=r"((R)[0]), "=r"((R)[1]), "=r"((R)[2]), "=r"((R)[3]) : "r"(addr))

#define MMA16816(D, A, B0, B1) \
    asm volatile("mma.sync.aligned.m16n8k16.row.col.f32.f16.f16.f32 " \
        "{%0,%1,%2,%3}, {%4,%5,%6,%7}, {%8,%9}, {%0,%1,%2,%3};" \
        : "+f"((D)[0]), "+f"((D)[1]), "+f"((D)[2]), "+f"((D)[3]) \
        : "r"((A)[0]), "r"((A)[1]), "r"((A)[2]), "r"((A)[3]), "r"(B0), "r"(B1))

__device__ __forceinline__ void cp_async16(uint32_t d, const void* s) {
    asm volatile("cp.async.cg.shared.global [%0], [%1], 16;" :: "r"(d), "l"(s));
}
#define CP_COMMIT() asm volatile("cp.async.commit_group;" ::: "memory")
#define CP_WAIT(n)  asm volatile("cp.async.wait_group %0;" :: "n"(n) : "memory")

__device__ __forceinline__ float act_apply(float v, int act) {
    if (act == 1) return fmaxf(v, 0.f);
    if (act == 2) return 0.5f * v * (1.f + erff(v * 0.70710678118654752f));
    return v;
}

// ---------------------------------------------------------------------------
// fp16x2 mma.sync GEMM
// ---------------------------------------------------------------------------
#define PITCH_B 80
#define OFF_AH 0
#define OFF_AL (128 * PITCH_B)
#define OFF_BH (2 * 128 * PITCH_B)
#define STAGE_B (3 * 128 * PITCH_B)
#define GEMM_SMEM (2 * STAGE_B)

__global__ __launch_bounds__(256)
void gemm_hf(const __half* __restrict__ Ah, const __half* __restrict__ Al,
             int lda,
             const __half* __restrict__ Wh, int K,
             const float* __restrict__ bias,
             float* __restrict__ Cf,
             __half* __restrict__ Ch, __half* __restrict__ Cl,
             int ldc, int act)
{
    extern __shared__ char sm[];
    const uint32_t sb = smem_u32(sm);

    const int tid = threadIdx.x;
    const int wid = tid >> 5;
    const int lane = tid & 31;
    const int m0 = blockIdx.x * 128;
    const int n0 = blockIdx.y * 128;
    const int wr = wid & 3;
    const int wc = wid >> 2;

    const int grow = tid >> 1;
    const int gcol = (tid & 1) * 16;
    const __half* Ahp = Ah + (size_t)(m0 + grow) * lda + gcol;
    const __half* Alp = Al + (size_t)(m0 + grow) * lda + gcol;
    const __half* Whp = Wh + (size_t)(n0 + grow) * K + gcol;
    const uint32_t sts_off = (uint32_t)grow * PITCH_B + (uint32_t)gcol * 2;

    const int a_lrow = (lane & 7) + ((lane >> 3) & 1) * 8;
    const int a_koff = (lane >> 4) * 8;
    const int b_lrow = (lane & 7) + ((lane >> 4) & 1) * 8;
    const int b_koff = ((lane >> 3) & 1) * 8;
    const uint32_t a_lbase = (uint32_t)(wr * 32 + a_lrow) * PITCH_B + (uint32_t)a_koff * 2;
    const uint32_t b_lbase = (uint32_t)(wc * 64 + b_lrow) * PITCH_B + (uint32_t)b_koff * 2;

    float acc[2][8][4];
    #pragma unroll
    for (int mt = 0; mt < 2; mt++)
        #pragma unroll
        for (int nt = 0; nt < 8; nt++)
            #pragma unroll
            for (int r = 0; r < 4; r++) acc[mt][nt][r] = 0.f;

    const int NC = K >> 5;

    auto issue = [&](int c) {
        const uint32_t d = sb + (uint32_t)(c & 1) * STAGE_B + sts_off;
        cp_async16(d + OFF_AH,      Ahp + c * 32);
        cp_async16(d + OFF_AH + 16, Ahp + c * 32 + 8);
        cp_async16(d + OFF_AL,      Alp + c * 32);
        cp_async16(d + OFF_AL + 16, Alp + c * 32 + 8);
        cp_async16(d + OFF_BH,      Whp + c * 32);
        cp_async16(d + OFF_BH + 16, Whp + c * 32 + 8);
        CP_COMMIT();
    };

    issue(0);
    if (NC > 1) issue(1);

    for (int c = 0; c < NC; c++) {
        if (c + 1 < NC) CP_WAIT(1); else CP_WAIT(0);
        __syncthreads();

        const uint32_t so = (uint32_t)(c & 1) * STAGE_B;

        #pragma unroll
        for (int step = 0; step < 2; step++) {
            const uint32_t kb = (uint32_t)step * 32;

            uint32_t ahr[2][4], alr[2][4];
            #pragma unroll
            for (int mt = 0; mt < 2; mt++) {
                const uint32_t aa = sb + so + a_lbase + (uint32_t)mt * (16 * PITCH_B) + kb;
                LDSM4(ahr[mt], aa + OFF_AH);
                LDSM4(alr[mt], aa + OFF_AL);
            }

            #pragma unroll
            for (int g = 0; g < 4; g++) {
                const uint32_t ba = sb + so + b_lbase + (uint32_t)g * (16 * PITCH_B) + kb;
                uint32_t bh[4];
                LDSM4(bh, ba + OFF_BH);
                #pragma unroll
                for (int mt = 0; mt < 2; mt++) {
                    MMA16816(acc[mt][2 * g],     ahr[mt], bh[0], bh[1]);
                    MMA16816(acc[mt][2 * g],     alr[mt], bh[0], bh[1]);
                    MMA16816(acc[mt][2 * g + 1], ahr[mt], bh[2], bh[3]);
                    MMA16816(acc[mt][2 * g + 1], alr[mt], bh[2], bh[3]);
                }
            }
        }
        __syncthreads();
        if (c + 2 < NC) issue(c + 2);
    }

    const int g = lane >> 2;
    const int t = lane & 3;
    #pragma unroll
    for (int mt = 0; mt < 2; mt++) {
        #pragma unroll
        for (int nt = 0; nt < 8; nt++) {
            const int col = n0 + wc * 64 + nt * 8 + t * 2;
            const float b0 = bias[col], b1 = bias[col + 1];
            const int r0 = m0 + wr * 32 + mt * 16 + g;
            float v00 = act_apply(acc[mt][nt][0] + b0, act);
            float v01 = act_apply(acc[mt][nt][1] + b1, act);
            float v10 = act_apply(acc[mt][nt][2] + b0, act);
            float v11 = act_apply(acc[mt][nt][3] + b1, act);
            if (Cf) {
                *(float2*)(Cf + (size_t)r0 * ldc + col) = make_float2(v00, v01);
                *(float2*)(Cf + (size_t)(r0 + 8) * ldc + col) = make_float2(v10, v11);
            }
            if (Ch) {
                uint32_t lo, hi;
                hi = pack_h2(v00, v01, lo);
                *(uint32_t*)(Ch + (size_t)r0 * ldc + col) = hi;
                *(uint32_t*)(Cl + (size_t)r0 * ldc + col) = lo;
                hi = pack_h2(v10, v11, lo);
                *(uint32_t*)(Ch + (size_t)(r0 + 8) * ldc + col) = hi;
                *(uint32_t*)(Cl + (size_t)(r0 + 8) * ldc + col) = lo;
            }
        }
    }
}

// ---------------------------------------------------------------------------
// LayerNorm
// ---------------------------------------------------------------------------
__device__ __forceinline__ void block_reduce2(float& s, float& q, int t) {
    #pragma unroll
    for (int o = 16; o > 0; o >>= 1) {
        s += __shfl_xor_sync(0xffffffffu, s, o);
        q += __shfl_xor_sync(0xffffffffu, q, o);
    }
    __shared__ float ss[4], sq[4];
    const int w = t >> 5, nw = blockDim.x >> 5;
    if ((t & 31) == 0) { ss[w] = s; sq[w] = q; }
    __syncthreads();
    s = 0.f; q = 0.f;
    for (int i = 0; i < nw; i++) { s += ss[i]; q += sq[i]; }
}

__device__ __forceinline__ void ln_store(float4 o, float* Y, __half* H,
                                         __half* L, size_t off) {
    if (Y) *(float4*)(Y + off) = o;
    if (H) {
        __half h[4], l[4];
        split1(o.x, h[0], l[0]); split1(o.y, h[1], l[1]);
        split1(o.z, h[2], l[2]); split1(o.w, h[3], l[3]);
        *(uint2*)(H + off) = *(uint2*)h;
        *(uint2*)(L + off) = *(uint2*)l;
    }
}

__global__ void ln_kernel(const float* __restrict__ X, int ldx,
                          const float* __restrict__ R, int ldr,
                          const float* __restrict__ g, const float* __restrict__ b,
                          float* __restrict__ Y,
                          __half* __restrict__ H,
                          __half* __restrict__ L, int ldy)
{
    const int row = blockIdx.x, t = threadIdx.x;
    const float D = (float)(blockDim.x << 2);
    float4 v = *(const float4*)(X + (size_t)row * ldx + (t << 2));
    if (R) {
        float4 r = *(const float4*)(R + (size_t)row * ldr + (t << 2));
        v.x += r.x; v.y += r.y; v.z += r.z; v.w += r.w;
    }
    float s = v.x + v.y + v.z + v.w;
    float q = v.x * v.x + v.y * v.y + v.z * v.z + v.w * v.w;
    block_reduce2(s, q, t);
    const float mean = s / D;
    const float rstd = rsqrtf(fmaxf(q / D - mean * mean, 0.f) + 1e-5f);
    const float4 g4 = *(const float4*)(g + (t << 2));
    const float4 b4 = *(const float4*)(b + (t << 2));
    float4 o;
    o.x = (v.x - mean) * rstd * g4.x + b4.x;
    o.y = (v.y - mean) * rstd * g4.y + b4.y;
    o.z = (v.z - mean) * rstd * g4.z + b4.z;
    o.w = (v.w - mean) * rstd * g4.w + b4.w;
    ln_store(o, Y, H, L, (size_t)row * ldy + (t << 2));
}

__global__ void ln_diag_kernel(const float* __restrict__ X,
                               const float* __restrict__ diag,
                               const float* __restrict__ g, const float* __restrict__ b,
                               float* __restrict__ Y,
                               __half* __restrict__ H,
                               __half* __restrict__ L, int ldy)
{
    const int row = blockIdx.x, t = threadIdx.x;
    const int bb = row >> 9, l = row & 511;
    const int h = t >> 3;
    const float dscale = diag[((size_t)bb * NH + h) * LL + l] + 1.f;
    float4 v = *(const float4*)(X + (size_t)row * DT + (t << 2));
    v.x *= dscale; v.y *= dscale; v.z *= dscale; v.w *= dscale;
    float s = v.x + v.y + v.z + v.w;
    float q = v.x * v.x + v.y * v.y + v.z * v.z + v.w * v.w;
    block_reduce2(s, q, t);
    const float mean = s / (float)DT;
    const float rstd = rsqrtf(fmaxf(q / (float)DT - mean * mean, 0.f) + 1e-5f);
    const float4 g4 = *(const float4*)(g + (t << 2));
    const float4 b4 = *(const float4*)(b + (t << 2));
    float4 o;
    o.x = (v.x - mean) * rstd * g4.x + b4.x;
    o.y = (v.y - mean) * rstd * g4.y + b4.y;
    o.z = (v.z - mean) * rstd * g4.z + b4.z;
    o.w = (v.w - mean) * rstd * g4.w + b4.w;
    ln_store(o, Y, H, L, (size_t)row * ldy + (t << 2));
}

// ---------------------------------------------------------------------------
// Tensor-core flash attention. Per (b,h), 64-query tile, 4 warps.
// S = (Qh+Ql)·Kh via mma; P split hi/lo in regs; O += (Ph+Pl)·Vh.
// Emits fp16 hi/lo att + diag.
// ---------------------------------------------------------------------------
#define AP 72                              // smem pitch in halves
#define ATT_SMEM (4 * 64 * AP * 2)         // 36864 B

__global__ __launch_bounds__(128)
void attn_kernel(const __half* __restrict__ qkvh,
                 const __half* __restrict__ qkvl,
                 __half* __restrict__ attH,
                 __half* __restrict__ attL,
                 float* __restrict__ diag)
{
    extern __shared__ __half sh[];
    __half* Qh = sh;
    __half* Ql = sh + 64 * AP;
    __half* Ks = sh + 2 * 64 * AP;
    __half* Vs = sh + 3 * 64 * AP;

    const int tid = threadIdx.x;
    const int w = tid >> 5, lane = tid & 31;
    const int qt = blockIdx.x, bhid = blockIdx.y;
    const int b = bhid >> 3, h = bhid & 7;

    const size_t base = (size_t)(b * LL) * (3 * DM) + h * HD;
    const __half* qh_g = qkvh + base;
    const __half* ql_g = qkvl + base;
    const __half* kh_g = qkvh + base + DM;
    const __half* vh_g = qkvh + base + 2 * DM;

    // load Q (hi & lo) into smem
    #pragma unroll
    for (int i = 0; i < 4; i++) {
        const int idx = tid + i * 128;
        const int r = idx >> 3, c = (idx & 7) * 8;
        const size_t go = (size_t)(qt * 64 + r) * (3 * DM) + c;
        *(uint4*)(Qh + r * AP + c) = *(const uint4*)(qh_g + go);
        *(uint4*)(Ql + r * AP + c) = *(const uint4*)(ql_g + go);
    }
    __syncthreads();

    // persistent Q A-frags
    const int a_row = (lane & 7) + ((lane >> 3) & 1) * 8;
    const int a_k   = (lane >> 4) * 8;
    uint32_t qhf[4][4], qlf[4][4];
    #pragma unroll
    for (int ks = 0; ks < 4; ks++) {
        LDSM4(qhf[ks], smem_u32(Qh + (w * 16 + a_row) * AP + ks * 16 + a_k));
        LDSM4(qlf[ks], smem_u32(Ql + (w * 16 + a_row) * AP + ks * 16 + a_k));
    }

    const int g  = lane >> 2;
    const int t2 = (lane & 3) * 2;
    const int b_row = (lane & 7) + ((lane >> 4) & 1) * 8;
    const int b_k   = ((lane >> 3) & 1) * 8;
    const int v_row = (lane & 7) + ((lane >> 3) & 1) * 8;
    const int v_col = ((lane >> 4) & 1) * 8;

    float m_[2] = {-1e30f, -1e30f}, l_[2] = {0.f, 0.f}, sd_[2] = {0.f, 0.f};
    float o[8][4];
    #pragma unroll
    for (int i = 0; i < 8; i++)
        #pragma unroll
        for (int j = 0; j < 4; j++) o[i][j] = 0.f;

    for (int kt = 0; kt < 8; kt++) {
        __syncthreads();
        #pragma unroll
        for (int i = 0; i < 4; i++) {
            const int idx = tid + i * 128;
            const int r = idx >> 3, c = (idx & 7) * 8;
            const size_t go = (size_t)(kt * 64 + r) * (3 * DM) + c;
            *(uint4*)(Ks + r * AP + c) = *(const uint4*)(kh_g + go);
            *(uint4*)(Vs + r * AP + c) = *(const uint4*)(vh_g + go);
        }
        __syncthreads();

        // S = Q K^T
        float s[8][4];
        #pragma unroll
        for (int i = 0; i < 8; i++)
            #pragma unroll
            for (int j = 0; j < 4; j++) s[i][j] = 0.f;

        #pragma unroll
        for (int ks = 0; ks < 4; ks++)
            #pragma unroll
            for (int np = 0; np < 4; np++) {
                uint32_t bf[4];
                LDSM4(bf, smem_u32(Ks + (np * 16 + b_row) * AP + ks * 16 + b_k));
                MMA16816(s[2 * np],     qhf[ks], bf[0], bf[1]);
                MMA16816(s[2 * np],     qlf[ks], bf[0], bf[1]);
                MMA16816(s[2 * np + 1], qhf[ks], bf[2], bf[3]);
                MMA16816(s[2 * np + 1], qlf[ks], bf[2], bf[3]);
            }

        #pragma unroll
        for (int i = 0; i < 8; i++)
            #pragma unroll
            for (int j = 0; j < 4; j++) s[i][j] *= 0.125f;

        if (kt == qt) {
            #pragma unroll
            for (int nt = 0; nt < 8; nt++)
                #pragma unroll
                for (int ci = 0; ci < 4; ci++) {
                    const int ri = w * 16 + g + (ci >> 1) * 8;
                    const int co = nt * 8 + t2 + (ci & 1);
                    if (ri == co) sd_[ci >> 1] = s[nt][ci];
                }
        }

        // online softmax (rows g and g+8)
        #pragma unroll
        for (int r = 0; r < 2; r++) {
            float mt = -1e30f;
            #pragma unroll
            for (int nt = 0; nt < 8; nt++)
                mt = fmaxf(mt, fmaxf(s[nt][2 * r], s[nt][2 * r + 1]));
            mt = fmaxf(mt, __shfl_xor_sync(0xffffffffu, mt, 1));
            mt = fmaxf(mt, __shfl_xor_sync(0xffffffffu, mt, 2));
            const float mn = fmaxf(m_[r], mt);
            const float corr = __expf(m_[r] - mn);
            float ps = 0.f;
            #pragma unroll
            for (int nt = 0; nt < 8; nt++) {
                const float p0 = __expf(s[nt][2 * r] - mn);
                const float p1 = __expf(s[nt][2 * r + 1] - mn);
                s[nt][2 * r] = p0; s[nt][2 * r + 1] = p1;
                ps += p0 + p1;
            }
            ps += __shfl_xor_sync(0xffffffffu, ps, 1);
            ps += __shfl_xor_sync(0xffffffffu, ps, 2);
            l_[r] = l_[r] * corr + ps;
            m_[r] = mn;
            #pragma unroll
            for (int nt = 0; nt < 8; nt++) {
                o[nt][2 * r] *= corr; o[nt][2 * r + 1] *= corr;
            }
        }

        // O += P V  (P hi/lo built in registers: C-frag pair == A-frag)
        #pragma unroll
        for (int j = 0; j < 4; j++) {
            uint32_t phf[4], plf[4];
            phf[0] = pack_h2(s[2 * j][0],     s[2 * j][1],     plf[0]);
            phf[1] = pack_h2(s[2 * j][2],     s[2 * j][3],     plf[1]);
            phf[2] = pack_h2(s[2 * j + 1][0], s[2 * j + 1][1], plf[2]);
            phf[3] = pack_h2(s[2 * j + 1][2], s[2 * j + 1][3], plf[3]);
            #pragma unroll
            for (int dp = 0; dp < 4; dp++) {
                uint32_t vf[4];
                LDSM4T(vf, smem_u32(Vs + (j * 16 + v_row) * AP + dp * 16 + v_col));
                MMA16816(o[2 * dp],     phf, vf[0], vf[1]);
                MMA16816(o[2 * dp],     plf, vf[0], vf[1]);
                MMA16816(o[2 * dp + 1], phf, vf[2], vf[3]);
                MMA16816(o[2 * dp + 1], plf, vf[2], vf[3]);
            }
        }
    }

    // epilogue
    #pragma unroll
    for (int r = 0; r < 2; r++) {
        const float inv = 1.f / l_[r];
        const int row = qt * 64 + w * 16 + g + r * 8;
        const size_t ob = ((size_t)b * LL + row) * DM + h * HD;
        #pragma unroll
        for (int dt = 0; dt < 8; dt++) {
            uint32_t lo;
            const uint32_t hi = pack_h2(o[dt][2 * r] * inv, o[dt][2 * r + 1] * inv, lo);
            *(uint32_t*)(attH + ob + dt * 8 + t2) = hi;
            *(uint32_t*)(attL + ob + dt * 8 + t2) = lo;
        }
        if ((lane & 3) == (g >> 1))
            diag[(size_t)bhid * LL + row] = __expf(sd_[r] - m_[r]) * inv;
    }
}

// ---------------------------------------------------------------------------
// MaxPool 16 over seq, concat tok|time -> fp16 hi/lo [1024, 768]
// ---------------------------------------------------------------------------
__global__ void pool_kernel(const float* __restrict__ tok,
                            const float* __restrict__ tim,
                            __half* __restrict__ pcH,
                            __half* __restrict__ pcL)
{
    const int orow = blockIdx.x;
    const int b = orow >> 5, gq = orow & 31;
    for (int d = threadIdx.x; d < DCAT; d += blockDim.x) {
        float mx = -1e30f;
        if (d < DM) {
            const float* p = tok + ((size_t)b * LL + gq * 16) * DM + d;
            #pragma unroll
            for (int j = 0; j < 16; j++) mx = fmaxf(mx, p[j * DM]);
        } else {
            const float* p = tim + ((size_t)b * LL + gq * 16) * DT + (d - DM);
            #pragma unroll
            for (int j = 0; j < 16; j++) mx = fmaxf(mx, p[j * DT]);
        }
        __half h, l;
        split1(mx, h, l);
        pcH[(size_t)orow * DCAT + d] = h;
        pcL[(size_t)orow * DCAT + d] = l;
    }
}

// ---------------------------------------------------------------------------
// Host orchestration
// ---------------------------------------------------------------------------
static void wsplit_launch(const float* X, __half* H, long n)
{
    const int n4 = (int)(n / 4);
    wsplit_kernel<<<(n4 + 255) / 256, 256>>>(X, H, n4);
}

extern "C" void kernel_launch(void* const* d_in, const int* in_sizes, int n_in,
                              void* d_out, int out_size)
{
    const float* in[26];
    for (int i = 0; i < 26; i++) in[i] = (const float*)d_in[i];

    float *x, *ao, *xc, *ff, *tok, *timeb, *diag, *o1;
    cudaGetSymbolAddress((void**)&x,     g_x);
    cudaGetSymbolAddress((void**)&ao,    g_ao);
    cudaGetSymbolAddress((void**)&xc,    g_xc);
    cudaGetSymbolAddress((void**)&ff,    g_ff);
    cudaGetSymbolAddress((void**)&tok,   g_tok);
    cudaGetSymbolAddress((void**)&timeb, g_time);
    cudaGetSymbolAddress((void**)&diag,  g_diag);
    cudaGetSymbolAddress((void**)&o1,    g_o1);

    __half *ln0h, *ln0l, *xh, *xl, *qkvh, *qkvl, *atth, *attl,
           *xch, *xcl, *h1h, *h1l, *pch, *pcl, *wh;
    cudaGetSymbolAddress((void**)&ln0h, g_ln0h); cudaGetSymbolAddress((void**)&ln0l, g_ln0l);
    cudaGetSymbolAddress((void**)&xh,   g_xh);   cudaGetSymbolAddress((void**)&xl,   g_xl);
    cudaGetSymbolAddress((void**)&qkvh, g_qkvh); cudaGetSymbolAddress((void**)&qkvl, g_qkvl);
    cudaGetSymbolAddress((void**)&atth, g_atth); cudaGetSymbolAddress((void**)&attl, g_attl);
    cudaGetSymbolAddress((void**)&xch,  g_xch);  cudaGetSymbolAddress((void**)&xcl,  g_xcl);
    cudaGetSymbolAddress((void**)&h1h,  g_h1h);  cudaGetSymbolAddress((void**)&h1l,  g_h1l);
    cudaGetSymbolAddress((void**)&pch,  g_pch);  cudaGetSymbolAddress((void**)&pcl,  g_pcl);
    cudaGetSymbolAddress((void**)&wh,   g_wh);

    cudaFuncSetAttribute(attn_kernel,
                         cudaFuncAttributeMaxDynamicSharedMemorySize, ATT_SMEM);
    cudaFuncSetAttribute(gemm_hf,
                         cudaFuncAttributeMaxDynamicSharedMemorySize, GEMM_SMEM);

    // pre-convert all weights to fp16
    wsplit_launch(in[4],  wh + OFF_W_IN,  (long)NLAYER * DM * DM);
    wsplit_launch(in[6],  wh + OFF_W_QKV, (long)NLAYER * 3 * DM * DM);
    wsplit_launch(in[8],  wh + OFF_W_AO,  (long)NLAYER * DM * DM);
    wsplit_launch(in[10], wh + OFF_W_L1,  (long)NLAYER * DFF * DCAT);
    wsplit_launch(in[12], wh + OFF_W_L2,  (long)NLAYER * DCAT * DFF);
    wsplit_launch(in[22], wh + OFF_W_OUT, (long)DT * DCAT);

    const int M = MROWS;
    for (int i = 0; i < NLAYER; i++) {
        const float* xin = i ? tok : in[0];
        const float* tin = i ? timeb : in[1];

        // norm0 -> fp16 only
        ln_kernel<<<M, 128>>>(xin, DM, nullptr, 0,
                              in[2] + i * DM, in[3] + i * DM,
                              nullptr, ln0h, ln0l, DM);
        // in_proj -> fp32 x (residual) + fp16
        gemm_hf<<<dim3(M / 128, DM / 128), 256, GEMM_SMEM>>>(
            ln0h, ln0l, DM, wh + OFF_W_IN + (long)i * DM * DM, DM,
            in[5] + i * DM, x, xh, xl, DM, 0);
        // qkv -> fp16 hi/lo only
        gemm_hf<<<dim3(M / 128, 3 * DM / 128), 256, GEMM_SMEM>>>(
            xh, xl, DM, wh + OFF_W_QKV + (long)i * 3 * DM * DM, DM,
            in[7] + i * 3 * DM, nullptr, qkvh, qkvl, 3 * DM, 0);

        attn_kernel<<<dim3(LL / 64, BB * NH), 128, ATT_SMEM>>>(
            qkvh, qkvl, atth, attl, diag);

        // attn out proj -> fp32 only
        gemm_hf<<<dim3(M / 128, DM / 128), 256, GEMM_SMEM>>>(
            atth, attl, DM, wh + OFF_W_AO + (long)i * DM * DM, DM,
            in[9] + i * DM, ao, nullptr, nullptr, DM, 0);

        // n1 -> xc fp32 + fp16 ; n2 -> xc+DM fp32 + fp16
        ln_kernel<<<M, 128>>>(ao, DM, x, DM,
                              in[14] + i * DM, in[15] + i * DM,
                              xc, xch, xcl, DCAT);
        ln_diag_kernel<<<M, 64>>>(tin, diag,
                                  in[16] + i * DT, in[17] + i * DT,
                                  xc + DM, xch + DM, xcl + DM, DCAT);

        // FF1 -> fp16 only ; FF2 -> fp32 only
        gemm_hf<<<dim3(M / 128, DFF / 128), 256, GEMM_SMEM>>>(
            xch, xcl, DCAT, wh + OFF_W_L1 + (long)i * DFF * DCAT, DCAT,
            in[11] + i * DFF, nullptr, h1h, h1l, DFF, 1);
        gemm_hf<<<dim3(M / 128, DCAT / 128), 256, GEMM_SMEM>>>(
            h1h, h1l, DFF, wh + OFF_W_L2 + (long)i * DCAT * DFF, DFF,
            in[13] + i * DCAT, ff, nullptr, nullptr, DCAT, 0);

        // n3 / n4 -> fp32 streams
        ln_kernel<<<M, 128>>>(ff, DCAT, xc, DCAT,
                              in[18] + i * DM, in[19] + i * DM,
                              tok, nullptr, nullptr, DM);
        ln_kernel<<<M, 64>>>(ff + DM, DCAT, xc + DM, DCAT,
                             in[20] + i * DT, in[21] + i * DT,
                             timeb, nullptr, nullptr, DT);
    }

    pool_kernel<<<BB * 32, 256>>>(tok, timeb, pch, pcl);
    gemm_hf<<<dim3(BB * 32 / 128, DT / 128), 256, GEMM_SMEM>>>(
        pch, pcl, DCAT, wh + OFF_W_OUT, DCAT, in[23],
        o1, nullptr, nullptr, DT, 2);
    ln_kernel<<<BB * 32, 64>>>(o1, DT, nullptr, 0, in[24], in[25],
                               (float*)d_out, nullptr, nullptr, DT);
}

// round 11
// speedup vs baseline: 3.3946x; 1.0863x over previous
#include <cuda_runtime.h>
#include <cuda_fp16.h>
#include <math.h>
#include <stdint.h>

// ---------------------------------------------------------------------------
// Problem constants
// ---------------------------------------------------------------------------
#define BB 32
#define LL 512
#define DM 512
#define DT 256
#define NH 8
#define HD 64
#define DFF 2048
#define NLAYER 2
#define MROWS (BB * LL)          // 16384
#define DCAT (DM + DT)           // 768

// ---------------------------------------------------------------------------
// Scratch (device globals)
// ---------------------------------------------------------------------------
__device__ float g_x   [MROWS * DM];
__device__ float g_ao  [MROWS * DM];
__device__ float g_xc  [MROWS * DCAT];
__device__ float g_ff  [MROWS * DCAT];
__device__ float g_tok [MROWS * DM];
__device__ float g_time[MROWS * DT];
__device__ float g_diag[BB * NH * LL];
__device__ float g_o1  [BB * 32 * DT];

// fp16 hi/lo activation buffers
__device__ __half g_ln0h[MROWS * DM],  g_ln0l[MROWS * DM];
__device__ __half g_xh  [MROWS * DM],  g_xl  [MROWS * DM];
__device__ __half g_qkvh[MROWS * 3 * DM], g_qkvl[MROWS * 3 * DM];
__device__ __half g_atth[MROWS * DM],  g_attl[MROWS * DM];
__device__ __half g_xch [MROWS * DCAT];                 // hi only (FF1 1-term)
__device__ __half g_h1h [MROWS * DFF];                  // hi only (FF2 1-term)
__device__ __half g_pch [BB * 32 * DCAT], g_pcl[BB * 32 * DCAT];

// fp16 weights
#define OFF_W_IN  0
#define OFF_W_QKV (OFF_W_IN  + NLAYER * DM * DM)
#define OFF_W_AO  (OFF_W_QKV + NLAYER * 3 * DM * DM)
#define OFF_W_L1  (OFF_W_AO  + NLAYER * DM * DM)
#define OFF_W_L2  (OFF_W_L1  + NLAYER * DFF * DCAT)
#define OFF_W_OUT (OFF_W_L2  + NLAYER * DCAT * DFF)
#define W_TOTAL   (OFF_W_OUT + DT * DCAT)
__device__ __half g_wh[W_TOTAL];

// ---------------------------------------------------------------------------
// Helpers
// ---------------------------------------------------------------------------
__device__ __forceinline__ uint32_t smem_u32(const void* p) {
    uint32_t a;
    asm("{ .reg .u64 t; cvta.to.shared.u64 t, %1; cvt.u32.u64 %0, t; }"
        : "=r"(a) : "l"(p));
    return a;
}

__device__ __forceinline__ void split1(float v, __half& h, __half& l) {
    h = __float2half_rn(v);
    l = __float2half_rn(v - __half2float(h));
}

__device__ __forceinline__ uint32_t pack_h2(float a, float b, uint32_t& lo) {
    __half ha, la, hb, lb;
    split1(a, ha, la); split1(b, hb, lb);
    lo = (uint32_t)__half_as_ushort(la) | ((uint32_t)__half_as_ushort(lb) << 16);
    return (uint32_t)__half_as_ushort(ha) | ((uint32_t)__half_as_ushort(hb) << 16);
}

__device__ __forceinline__ uint32_t pack_h2_hi(float a, float b) {
    __half ha = __float2half_rn(a), hb = __float2half_rn(b);
    return (uint32_t)__half_as_ushort(ha) | ((uint32_t)__half_as_ushort(hb) << 16);
}

// weights: float -> fp16 (hi only)
__global__ void wsplit_kernel(const float* __restrict__ X,
                              __half* __restrict__ H, int n4)
{
    const int i = blockIdx.x * blockDim.x + threadIdx.x;
    if (i >= n4) return;
    const float4 v = *(const float4*)(X + (size_t)i * 4);
    __half h[4];
    h[0] = __float2half_rn(v.x); h[1] = __float2half_rn(v.y);
    h[2] = __float2half_rn(v.z); h[3] = __float2half_rn(v.w);
    *(uint2*)(H + (size_t)i * 4) = *(uint2*)h;
}

// ---------------------------------------------------------------------------
// MMA / ldmatrix / cp.async primitives
// ---------------------------------------------------------------------------
#define LDSM4(R, addr) \
    asm volatile("ldmatrix.sync.aligned.m8n8.x4.shared.b16 {%0,%1,%2,%3}, [%4];" \
        : "=r"((R)[0]), "=r"((R)[1]), "=r"((R)[2]), "=r"((R)[3]) : "r"(addr))

#define LDSM4T(R, addr) \
    asm volatile("ldmatrix.sync.aligned.m8n8.x4.trans.shared.b16 {%0,%1,%2,%3}, [%4];" \
        : "=r"((R)[0]), "=r"((R)[1]), "=r"((R)[2]), "=r"((R)[3]) : "r"(addr))

#define MMA16816(D, A, B0, B1) \
    asm volatile("mma.sync.aligned.m16n8k16.row.col.f32.f16.f16.f32 " \
        "{%0,%1,%2,%3}, {%4,%5,%6,%7}, {%8,%9}, {%0,%1,%2,%3};" \
        : "+f"((D)[0]), "+f"((D)[1]), "+f"((D)[2]), "+f"((D)[3]) \
        : "r"((A)[0]), "r"((A)[1]), "r"((A)[2]), "r"((A)[3]), "r"(B0), "r"(B1))

__device__ __forceinline__ void cp_async16(uint32_t d, const void* s) {
    asm volatile("cp.async.cg.shared.global [%0], [%1], 16;" :: "r"(d), "l"(s));
}
#define CP_COMMIT() asm volatile("cp.async.commit_group;" ::: "memory")
#define CP_WAIT(n)  asm volatile("cp.async.wait_group %0;" :: "n"(n) : "memory")

__device__ __forceinline__ float act_apply(float v, int act) {
    if (act == 1) return fmaxf(v, 0.f);
    if (act == 2) return 0.5f * v * (1.f + erff(v * 0.70710678118654752f));
    return v;
}

// ---------------------------------------------------------------------------
// fp16 mma.sync GEMM. A = Ah (+ optional Al) fp16, W = Wh fp16, fp32 accum.
// 128x128 CTA tile, K-chunk 32, 8 warps of 32x64, cp.async double buffer.
// ---------------------------------------------------------------------------
#define PITCH_B 80
#define OFF_AH 0
#define OFF_AL (128 * PITCH_B)
#define OFF_BH (2 * 128 * PITCH_B)
#define STAGE_B (3 * 128 * PITCH_B)
#define GEMM_SMEM (2 * STAGE_B)

__global__ __launch_bounds__(256)
void gemm_hf(const __half* __restrict__ Ah, const __half* __restrict__ Al,
             int lda,
             const __half* __restrict__ Wh, int K,
             const float* __restrict__ bias,
             float* __restrict__ Cf,
             __half* __restrict__ Ch, __half* __restrict__ Cl,
             int ldc, int act)
{
    extern __shared__ char sm[];
    const uint32_t sb = smem_u32(sm);
    const bool twoA = (Al != nullptr);

    const int tid = threadIdx.x;
    const int wid = tid >> 5;
    const int lane = tid & 31;
    const int m0 = blockIdx.x * 128;
    const int n0 = blockIdx.y * 128;
    const int wr = wid & 3;
    const int wc = wid >> 2;

    const int grow = tid >> 1;
    const int gcol = (tid & 1) * 16;
    const __half* Ahp = Ah + (size_t)(m0 + grow) * lda + gcol;
    const __half* Alp = twoA ? (Al + (size_t)(m0 + grow) * lda + gcol) : nullptr;
    const __half* Whp = Wh + (size_t)(n0 + grow) * K + gcol;
    const uint32_t sts_off = (uint32_t)grow * PITCH_B + (uint32_t)gcol * 2;

    const int a_lrow = (lane & 7) + ((lane >> 3) & 1) * 8;
    const int a_koff = (lane >> 4) * 8;
    const int b_lrow = (lane & 7) + ((lane >> 4) & 1) * 8;
    const int b_koff = ((lane >> 3) & 1) * 8;
    const uint32_t a_lbase = (uint32_t)(wr * 32 + a_lrow) * PITCH_B + (uint32_t)a_koff * 2;
    const uint32_t b_lbase = (uint32_t)(wc * 64 + b_lrow) * PITCH_B + (uint32_t)b_koff * 2;

    float acc[2][8][4];
    #pragma unroll
    for (int mt = 0; mt < 2; mt++)
        #pragma unroll
        for (int nt = 0; nt < 8; nt++)
            #pragma unroll
            for (int r = 0; r < 4; r++) acc[mt][nt][r] = 0.f;

    const int NC = K >> 5;

    auto issue = [&](int c) {
        const uint32_t d = sb + (uint32_t)(c & 1) * STAGE_B + sts_off;
        cp_async16(d + OFF_AH,      Ahp + c * 32);
        cp_async16(d + OFF_AH + 16, Ahp + c * 32 + 8);
        if (twoA) {
            cp_async16(d + OFF_AL,      Alp + c * 32);
            cp_async16(d + OFF_AL + 16, Alp + c * 32 + 8);
        }
        cp_async16(d + OFF_BH,      Whp + c * 32);
        cp_async16(d + OFF_BH + 16, Whp + c * 32 + 8);
        CP_COMMIT();
    };

    issue(0);
    if (NC > 1) issue(1);

    for (int c = 0; c < NC; c++) {
        if (c + 1 < NC) CP_WAIT(1); else CP_WAIT(0);
        __syncthreads();

        const uint32_t so = (uint32_t)(c & 1) * STAGE_B;

        #pragma unroll
        for (int step = 0; step < 2; step++) {
            const uint32_t kb = (uint32_t)step * 32;

            uint32_t ahr[2][4], alr[2][4];
            #pragma unroll
            for (int mt = 0; mt < 2; mt++) {
                const uint32_t aa = sb + so + a_lbase + (uint32_t)mt * (16 * PITCH_B) + kb;
                LDSM4(ahr[mt], aa + OFF_AH);
                if (twoA) LDSM4(alr[mt], aa + OFF_AL);
            }

            #pragma unroll
            for (int g = 0; g < 4; g++) {
                const uint32_t ba = sb + so + b_lbase + (uint32_t)g * (16 * PITCH_B) + kb;
                uint32_t bh[4];
                LDSM4(bh, ba + OFF_BH);
                #pragma unroll
                for (int mt = 0; mt < 2; mt++) {
                    MMA16816(acc[mt][2 * g],     ahr[mt], bh[0], bh[1]);
                    MMA16816(acc[mt][2 * g + 1], ahr[mt], bh[2], bh[3]);
                    if (twoA) {
                        MMA16816(acc[mt][2 * g],     alr[mt], bh[0], bh[1]);
                        MMA16816(acc[mt][2 * g + 1], alr[mt], bh[2], bh[3]);
                    }
                }
            }
        }
        __syncthreads();
        if (c + 2 < NC) issue(c + 2);
    }

    const int g = lane >> 2;
    const int t = lane & 3;
    #pragma unroll
    for (int mt = 0; mt < 2; mt++) {
        #pragma unroll
        for (int nt = 0; nt < 8; nt++) {
            const int col = n0 + wc * 64 + nt * 8 + t * 2;
            const float b0 = bias[col], b1 = bias[col + 1];
            const int r0 = m0 + wr * 32 + mt * 16 + g;
            float v00 = act_apply(acc[mt][nt][0] + b0, act);
            float v01 = act_apply(acc[mt][nt][1] + b1, act);
            float v10 = act_apply(acc[mt][nt][2] + b0, act);
            float v11 = act_apply(acc[mt][nt][3] + b1, act);
            if (Cf) {
                *(float2*)(Cf + (size_t)r0 * ldc + col) = make_float2(v00, v01);
                *(float2*)(Cf + (size_t)(r0 + 8) * ldc + col) = make_float2(v10, v11);
            }
            if (Ch) {
                if (Cl) {
                    uint32_t lo, hi;
                    hi = pack_h2(v00, v01, lo);
                    *(uint32_t*)(Ch + (size_t)r0 * ldc + col) = hi;
                    *(uint32_t*)(Cl + (size_t)r0 * ldc + col) = lo;
                    hi = pack_h2(v10, v11, lo);
                    *(uint32_t*)(Ch + (size_t)(r0 + 8) * ldc + col) = hi;
                    *(uint32_t*)(Cl + (size_t)(r0 + 8) * ldc + col) = lo;
                } else {
                    *(uint32_t*)(Ch + (size_t)r0 * ldc + col) = pack_h2_hi(v00, v01);
                    *(uint32_t*)(Ch + (size_t)(r0 + 8) * ldc + col) = pack_h2_hi(v10, v11);
                }
            }
        }
    }
}

// ---------------------------------------------------------------------------
// Warp-per-row LayerNorm. 8 warps/block, 1 row/warp. NV4 = D/128.
// ---------------------------------------------------------------------------
__device__ __forceinline__ void warp_reduce2(float& s, float& q) {
    #pragma unroll
    for (int o = 16; o > 0; o >>= 1) {
        s += __shfl_xor_sync(0xffffffffu, s, o);
        q += __shfl_xor_sync(0xffffffffu, q, o);
    }
}

__device__ __forceinline__ void ln_store(float4 o, float* Y, __half* H,
                                         __half* L, size_t off) {
    if (Y) *(float4*)(Y + off) = o;
    if (H) {
        if (L) {
            __half h[4], l[4];
            split1(o.x, h[0], l[0]); split1(o.y, h[1], l[1]);
            split1(o.z, h[2], l[2]); split1(o.w, h[3], l[3]);
            *(uint2*)(H + off) = *(uint2*)h;
            *(uint2*)(L + off) = *(uint2*)l;
        } else {
            __half h[4];
            h[0] = __float2half_rn(o.x); h[1] = __float2half_rn(o.y);
            h[2] = __float2half_rn(o.z); h[3] = __float2half_rn(o.w);
            *(uint2*)(H + off) = *(uint2*)h;
        }
    }
}

template <int NV4>
__global__ void ln_kernel(const float* __restrict__ X, int ldx,
                          const float* __restrict__ R, int ldr,
                          const float* __restrict__ g, const float* __restrict__ b,
                          float* __restrict__ Y,
                          __half* __restrict__ H,
                          __half* __restrict__ L, int ldy)
{
    const int row = blockIdx.x * 8 + (threadIdx.x >> 5);
    const int lane = threadIdx.x & 31;
    const float D = (float)(NV4 * 128);

    float4 v[NV4];
    float s = 0.f, q = 0.f;
    #pragma unroll
    for (int j = 0; j < NV4; j++) {
        const int c4 = (lane + j * 32) << 2;
        v[j] = *(const float4*)(X + (size_t)row * ldx + c4);
        if (R) {
            const float4 r = *(const float4*)(R + (size_t)row * ldr + c4);
            v[j].x += r.x; v[j].y += r.y; v[j].z += r.z; v[j].w += r.w;
        }
        s += v[j].x + v[j].y + v[j].z + v[j].w;
        q += v[j].x * v[j].x + v[j].y * v[j].y + v[j].z * v[j].z + v[j].w * v[j].w;
    }
    warp_reduce2(s, q);
    const float mean = s / D;
    const float rstd = rsqrtf(fmaxf(q / D - mean * mean, 0.f) + 1e-5f);
    #pragma unroll
    for (int j = 0; j < NV4; j++) {
        const int c4 = (lane + j * 32) << 2;
        const float4 g4 = *(const float4*)(g + c4);
        const float4 b4 = *(const float4*)(b + c4);
        float4 o;
        o.x = (v[j].x - mean) * rstd * g4.x + b4.x;
        o.y = (v[j].y - mean) * rstd * g4.y + b4.y;
        o.z = (v[j].z - mean) * rstd * g4.z + b4.z;
        o.w = (v[j].w - mean) * rstd * g4.w + b4.w;
        ln_store(o, Y, H, L, (size_t)row * ldy + c4);
    }
}

// time branch: LN((diag+1) * x_time), D = 256
__global__ void ln_diag_kernel(const float* __restrict__ X,
                               const float* __restrict__ diag,
                               const float* __restrict__ g, const float* __restrict__ b,
                               float* __restrict__ Y,
                               __half* __restrict__ H, int ldy)
{
    const int row = blockIdx.x * 8 + (threadIdx.x >> 5);
    const int lane = threadIdx.x & 31;
    const int bb = row >> 9, l = row & 511;

    float4 v[2];
    float s = 0.f, q = 0.f;
    #pragma unroll
    for (int j = 0; j < 2; j++) {
        const int c4 = (lane + j * 32) << 2;
        const int h = c4 >> 5;
        const float dscale = diag[((size_t)bb * NH + h) * LL + l] + 1.f;
        v[j] = *(const float4*)(X + (size_t)row * DT + c4);
        v[j].x *= dscale; v[j].y *= dscale; v[j].z *= dscale; v[j].w *= dscale;
        s += v[j].x + v[j].y + v[j].z + v[j].w;
        q += v[j].x * v[j].x + v[j].y * v[j].y + v[j].z * v[j].z + v[j].w * v[j].w;
    }
    warp_reduce2(s, q);
    const float mean = s / (float)DT;
    const float rstd = rsqrtf(fmaxf(q / (float)DT - mean * mean, 0.f) + 1e-5f);
    #pragma unroll
    for (int j = 0; j < 2; j++) {
        const int c4 = (lane + j * 32) << 2;
        const float4 g4 = *(const float4*)(g + c4);
        const float4 b4 = *(const float4*)(b + c4);
        float4 o;
        o.x = (v[j].x - mean) * rstd * g4.x + b4.x;
        o.y = (v[j].y - mean) * rstd * g4.y + b4.y;
        o.z = (v[j].z - mean) * rstd * g4.z + b4.z;
        o.w = (v[j].w - mean) * rstd * g4.w + b4.w;
        ln_store(o, Y, H, nullptr, (size_t)row * ldy + c4);
    }
}

// ---------------------------------------------------------------------------
// Tensor-core flash attention.
// ---------------------------------------------------------------------------
#define AP 72
#define ATT_SMEM (4 * 64 * AP * 2)

__global__ __launch_bounds__(128)
void attn_kernel(const __half* __restrict__ qkvh,
                 const __half* __restrict__ qkvl,
                 __half* __restrict__ attH,
                 __half* __restrict__ attL,
                 float* __restrict__ diag)
{
    extern __shared__ __half sh[];
    __half* Qh = sh;
    __half* Ql = sh + 64 * AP;
    __half* Ks = sh + 2 * 64 * AP;
    __half* Vs = sh + 3 * 64 * AP;

    const int tid = threadIdx.x;
    const int w = tid >> 5, lane = tid & 31;
    const int qt = blockIdx.x, bhid = blockIdx.y;
    const int b = bhid >> 3, h = bhid & 7;

    const size_t base = (size_t)(b * LL) * (3 * DM) + h * HD;
    const __half* qh_g = qkvh + base;
    const __half* ql_g = qkvl + base;
    const __half* kh_g = qkvh + base + DM;
    const __half* vh_g = qkvh + base + 2 * DM;

    #pragma unroll
    for (int i = 0; i < 4; i++) {
        const int idx = tid + i * 128;
        const int r = idx >> 3, c = (idx & 7) * 8;
        const size_t go = (size_t)(qt * 64 + r) * (3 * DM) + c;
        *(uint4*)(Qh + r * AP + c) = *(const uint4*)(qh_g + go);
        *(uint4*)(Ql + r * AP + c) = *(const uint4*)(ql_g + go);
    }
    __syncthreads();

    const int a_row = (lane & 7) + ((lane >> 3) & 1) * 8;
    const int a_k   = (lane >> 4) * 8;
    uint32_t qhf[4][4], qlf[4][4];
    #pragma unroll
    for (int ks = 0; ks < 4; ks++) {
        LDSM4(qhf[ks], smem_u32(Qh + (w * 16 + a_row) * AP + ks * 16 + a_k));
        LDSM4(qlf[ks], smem_u32(Ql + (w * 16 + a_row) * AP + ks * 16 + a_k));
    }

    const int g  = lane >> 2;
    const int t2 = (lane & 3) * 2;
    const int b_row = (lane & 7) + ((lane >> 4) & 1) * 8;
    const int b_k   = ((lane >> 3) & 1) * 8;
    const int v_row = (lane & 7) + ((lane >> 3) & 1) * 8;
    const int v_col = ((lane >> 4) & 1) * 8;

    float m_[2] = {-1e30f, -1e30f}, l_[2] = {0.f, 0.f}, sd_[2] = {0.f, 0.f};
    float o[8][4];
    #pragma unroll
    for (int i = 0; i < 8; i++)
        #pragma unroll
        for (int j = 0; j < 4; j++) o[i][j] = 0.f;

    for (int kt = 0; kt < 8; kt++) {
        __syncthreads();
        #pragma unroll
        for (int i = 0; i < 4; i++) {
            const int idx = tid + i * 128;
            const int r = idx >> 3, c = (idx & 7) * 8;
            const size_t go = (size_t)(kt * 64 + r) * (3 * DM) + c;
            *(uint4*)(Ks + r * AP + c) = *(const uint4*)(kh_g + go);
            *(uint4*)(Vs + r * AP + c) = *(const uint4*)(vh_g + go);
        }
        __syncthreads();

        float s[8][4];
        #pragma unroll
        for (int i = 0; i < 8; i++)
            #pragma unroll
            for (int j = 0; j < 4; j++) s[i][j] = 0.f;

        #pragma unroll
        for (int ks = 0; ks < 4; ks++)
            #pragma unroll
            for (int np = 0; np < 4; np++) {
                uint32_t bf[4];
                LDSM4(bf, smem_u32(Ks + (np * 16 + b_row) * AP + ks * 16 + b_k));
                MMA16816(s[2 * np],     qhf[ks], bf[0], bf[1]);
                MMA16816(s[2 * np],     qlf[ks], bf[0], bf[1]);
                MMA16816(s[2 * np + 1], qhf[ks], bf[2], bf[3]);
                MMA16816(s[2 * np + 1], qlf[ks], bf[2], bf[3]);
            }

        #pragma unroll
        for (int i = 0; i < 8; i++)
            #pragma unroll
            for (int j = 0; j < 4; j++) s[i][j] *= 0.125f;

        if (kt == qt) {
            #pragma unroll
            for (int nt = 0; nt < 8; nt++)
                #pragma unroll
                for (int ci = 0; ci < 4; ci++) {
                    const int ri = w * 16 + g + (ci >> 1) * 8;
                    const int co = nt * 8 + t2 + (ci & 1);
                    if (ri == co) sd_[ci >> 1] = s[nt][ci];
                }
        }

        #pragma unroll
        for (int r = 0; r < 2; r++) {
            float mt = -1e30f;
            #pragma unroll
            for (int nt = 0; nt < 8; nt++)
                mt = fmaxf(mt, fmaxf(s[nt][2 * r], s[nt][2 * r + 1]));
            mt = fmaxf(mt, __shfl_xor_sync(0xffffffffu, mt, 1));
            mt = fmaxf(mt, __shfl_xor_sync(0xffffffffu, mt, 2));
            const float mn = fmaxf(m_[r], mt);
            const float corr = __expf(m_[r] - mn);
            float ps = 0.f;
            #pragma unroll
            for (int nt = 0; nt < 8; nt++) {
                const float p0 = __expf(s[nt][2 * r] - mn);
                const float p1 = __expf(s[nt][2 * r + 1] - mn);
                s[nt][2 * r] = p0; s[nt][2 * r + 1] = p1;
                ps += p0 + p1;
            }
            ps += __shfl_xor_sync(0xffffffffu, ps, 1);
            ps += __shfl_xor_sync(0xffffffffu, ps, 2);
            l_[r] = l_[r] * corr + ps;
            m_[r] = mn;
            #pragma unroll
            for (int nt = 0; nt < 8; nt++) {
                o[nt][2 * r] *= corr; o[nt][2 * r + 1] *= corr;
            }
        }

        #pragma unroll
        for (int j = 0; j < 4; j++) {
            uint32_t phf[4], plf[4];
            phf[0] = pack_h2(s[2 * j][0],     s[2 * j][1],     plf[0]);
            phf[1] = pack_h2(s[2 * j][2],     s[2 * j][3],     plf[1]);
            phf[2] = pack_h2(s[2 * j + 1][0], s[2 * j + 1][1], plf[2]);
            phf[3] = pack_h2(s[2 * j + 1][2], s[2 * j + 1][3], plf[3]);
            #pragma unroll
            for (int dp = 0; dp < 4; dp++) {
                uint32_t vf[4];
                LDSM4T(vf, smem_u32(Vs + (j * 16 + v_row) * AP + dp * 16 + v_col));
                MMA16816(o[2 * dp],     phf, vf[0], vf[1]);
                MMA16816(o[2 * dp],     plf, vf[0], vf[1]);
                MMA16816(o[2 * dp + 1], phf, vf[2], vf[3]);
                MMA16816(o[2 * dp + 1], plf, vf[2], vf[3]);
            }
        }
    }

    #pragma unroll
    for (int r = 0; r < 2; r++) {
        const float inv = 1.f / l_[r];
        const int row = qt * 64 + w * 16 + g + r * 8;
        const size_t ob = ((size_t)b * LL + row) * DM + h * HD;
        #pragma unroll
        for (int dt = 0; dt < 8; dt++) {
            uint32_t lo;
            const uint32_t hi = pack_h2(o[dt][2 * r] * inv, o[dt][2 * r + 1] * inv, lo);
            *(uint32_t*)(attH + ob + dt * 8 + t2) = hi;
            *(uint32_t*)(attL + ob + dt * 8 + t2) = lo;
        }
        if ((lane & 3) == (g >> 1))
            diag[(size_t)bhid * LL + row] = __expf(sd_[r] - m_[r]) * inv;
    }
}

// ---------------------------------------------------------------------------
// MaxPool 16 over seq, concat tok|time -> fp16 hi/lo [1024, 768]
// ---------------------------------------------------------------------------
__global__ void pool_kernel(const float* __restrict__ tok,
                            const float* __restrict__ tim,
                            __half* __restrict__ pcH,
                            __half* __restrict__ pcL)
{
    const int orow = blockIdx.x;
    const int b = orow >> 5, gq = orow & 31;
    for (int d = threadIdx.x; d < DCAT; d += blockDim.x) {
        float mx = -1e30f;
        if (d < DM) {
            const float* p = tok + ((size_t)b * LL + gq * 16) * DM + d;
            #pragma unroll
            for (int j = 0; j < 16; j++) mx = fmaxf(mx, p[j * DM]);
        } else {
            const float* p = tim + ((size_t)b * LL + gq * 16) * DT + (d - DM);
            #pragma unroll
            for (int j = 0; j < 16; j++) mx = fmaxf(mx, p[j * DT]);
        }
        __half h, l;
        split1(mx, h, l);
        pcH[(size_t)orow * DCAT + d] = h;
        pcL[(size_t)orow * DCAT + d] = l;
    }
}

// ---------------------------------------------------------------------------
// Host orchestration
// ---------------------------------------------------------------------------
static void wsplit_launch(const float* X, __half* H, long n)
{
    const int n4 = (int)(n / 4);
    wsplit_kernel<<<(n4 + 255) / 256, 256>>>(X, H, n4);
}

extern "C" void kernel_launch(void* const* d_in, const int* in_sizes, int n_in,
                              void* d_out, int out_size)
{
    const float* in[26];
    for (int i = 0; i < 26; i++) in[i] = (const float*)d_in[i];

    float *x, *ao, *xc, *ff, *tok, *timeb, *diag, *o1;
    cudaGetSymbolAddress((void**)&x,     g_x);
    cudaGetSymbolAddress((void**)&ao,    g_ao);
    cudaGetSymbolAddress((void**)&xc,    g_xc);
    cudaGetSymbolAddress((void**)&ff,    g_ff);
    cudaGetSymbolAddress((void**)&tok,   g_tok);
    cudaGetSymbolAddress((void**)&timeb, g_time);
    cudaGetSymbolAddress((void**)&diag,  g_diag);
    cudaGetSymbolAddress((void**)&o1,    g_o1);

    __half *ln0h, *ln0l, *xh, *xl, *qkvh, *qkvl, *atth, *attl,
           *xch, *h1h, *pch, *pcl, *wh;
    cudaGetSymbolAddress((void**)&ln0h, g_ln0h); cudaGetSymbolAddress((void**)&ln0l, g_ln0l);
    cudaGetSymbolAddress((void**)&xh,   g_xh);   cudaGetSymbolAddress((void**)&xl,   g_xl);
    cudaGetSymbolAddress((void**)&qkvh, g_qkvh); cudaGetSymbolAddress((void**)&qkvl, g_qkvl);
    cudaGetSymbolAddress((void**)&atth, g_atth); cudaGetSymbolAddress((void**)&attl, g_attl);
    cudaGetSymbolAddress((void**)&xch,  g_xch);
    cudaGetSymbolAddress((void**)&h1h,  g_h1h);
    cudaGetSymbolAddress((void**)&pch,  g_pch);  cudaGetSymbolAddress((void**)&pcl,  g_pcl);
    cudaGetSymbolAddress((void**)&wh,   g_wh);

    cudaFuncSetAttribute(attn_kernel,
                         cudaFuncAttributeMaxDynamicSharedMemorySize, ATT_SMEM);
    cudaFuncSetAttribute(gemm_hf,
                         cudaFuncAttributeMaxDynamicSharedMemorySize, GEMM_SMEM);

    // pre-convert all weights to fp16
    wsplit_launch(in[4],  wh + OFF_W_IN,  (long)NLAYER * DM * DM);
    wsplit_launch(in[6],  wh + OFF_W_QKV, (long)NLAYER * 3 * DM * DM);
    wsplit_launch(in[8],  wh + OFF_W_AO,  (long)NLAYER * DM * DM);
    wsplit_launch(in[10], wh + OFF_W_L1,  (long)NLAYER * DFF * DCAT);
    wsplit_launch(in[12], wh + OFF_W_L2,  (long)NLAYER * DCAT * DFF);
    wsplit_launch(in[22], wh + OFF_W_OUT, (long)DT * DCAT);

    const int M = MROWS;
    for (int i = 0; i < NLAYER; i++) {
        const float* xin = i ? tok : in[0];
        const float* tin = i ? timeb : in[1];

        // norm0 -> fp16 hi/lo
        ln_kernel<4><<<M / 8, 256>>>(xin, DM, nullptr, 0,
                                     in[2] + i * DM, in[3] + i * DM,
                                     nullptr, ln0h, ln0l, DM);
        // in_proj (2-term) -> fp32 x + fp16 hi/lo
        gemm_hf<<<dim3(M / 128, DM / 128), 256, GEMM_SMEM>>>(
            ln0h, ln0l, DM, wh + OFF_W_IN + (long)i * DM * DM, DM,
            in[5] + i * DM, x, xh, xl, DM, 0);
        // qkv (2-term) -> fp16 hi/lo
        gemm_hf<<<dim3(M / 128, 3 * DM / 128), 256, GEMM_SMEM>>>(
            xh, xl, DM, wh + OFF_W_QKV + (long)i * 3 * DM * DM, DM,
            in[7] + i * 3 * DM, nullptr, qkvh, qkvl, 3 * DM, 0);

        attn_kernel<<<dim3(LL / 64, BB * NH), 128, ATT_SMEM>>>(
            qkvh, qkvl, atth, attl, diag);

        // attn out proj (2-term) -> fp32
        gemm_hf<<<dim3(M / 128, DM / 128), 256, GEMM_SMEM>>>(
            atth, attl, DM, wh + OFF_W_AO + (long)i * DM * DM, DM,
            in[9] + i * DM, ao, nullptr, nullptr, DM, 0);

        // n1 -> xc fp32 + xch hi-only ; n2 -> xc+DM fp32 + xch+DM hi-only
        ln_kernel<4><<<M / 8, 256>>>(ao, DM, x, DM,
                                     in[14] + i * DM, in[15] + i * DM,
                                     xc, xch, nullptr, DCAT);
        ln_diag_kernel<<<M / 8, 256>>>(tin, diag,
                                       in[16] + i * DT, in[17] + i * DT,
                                       xc + DM, xch + DM, DCAT);

        // FF1 (1-term) -> h1 hi-only ; FF2 (1-term) -> fp32
        gemm_hf<<<dim3(M / 128, DFF / 128), 256, GEMM_SMEM>>>(
            xch, nullptr, DCAT, wh + OFF_W_L1 + (long)i * DFF * DCAT, DCAT,
            in[11] + i * DFF, nullptr, h1h, nullptr, DFF, 1);
        gemm_hf<<<dim3(M / 128, DCAT / 128), 256, GEMM_SMEM>>>(
            h1h, nullptr, DFF, wh + OFF_W_L2 + (long)i * DCAT * DFF, DFF,
            in[13] + i * DCAT, ff, nullptr, nullptr, DCAT, 0);

        // n3 / n4 -> fp32 streams
        ln_kernel<4><<<M / 8, 256>>>(ff, DCAT, xc, DCAT,
                                     in[18] + i * DM, in[19] + i * DM,
                                     tok, nullptr, nullptr, DM);
        ln_kernel<2><<<M / 8, 256>>>(ff + DM, DCAT, xc + DM, DCAT,
                                     in[20] + i * DT, in[21] + i * DT,
                                     timeb, nullptr, nullptr, DT);
    }

    pool_kernel<<<BB * 32, 256>>>(tok, timeb, pch, pcl);
    gemm_hf<<<dim3(BB * 32 / 128, DT / 128), 256, GEMM_SMEM>>>(
        pch, pcl, DCAT, wh + OFF_W_OUT, DCAT, in[23],
        o1, nullptr, nullptr, DT, 2);
    ln_kernel<2><<<BB * 32 / 8, 256>>>(o1, DT, nullptr, 0, in[24], in[25],
                                       (float*)d_out, nullptr, nullptr, DT);
}

// round 12
// speedup vs baseline: 3.6792x; 1.0838x over previous
#include <cuda_runtime.h>
#include <cuda_fp16.h>
#include <math.h>
#include <stdint.h>

// ---------------------------------------------------------------------------
// Problem constants
// ---------------------------------------------------------------------------
#define BB 32
#define LL 512
#define DM 512
#define DT 256
#define NH 8
#define HD 64
#define DFF 2048
#define NLAYER 2
#define MROWS (BB * LL)          // 16384
#define DCAT (DM + DT)           // 768

// ---------------------------------------------------------------------------
// Scratch (device globals)
// ---------------------------------------------------------------------------
__device__ float g_x   [MROWS * DM];
__device__ float g_ao  [MROWS * DM];
__device__ float g_xc  [MROWS * DCAT];
__device__ float g_ff  [MROWS * DCAT];
__device__ float g_tok [MROWS * DM];
__device__ float g_time[MROWS * DT];
__device__ float g_diag[BB * NH * LL];
__device__ float g_o1  [BB * 32 * DT];

// fp16 activation buffers
__device__ __half g_ln0h[MROWS * DM];                   // hi only
__device__ __half g_xh  [MROWS * DM];                   // hi only
__device__ __half g_qkvh[MROWS * 3 * DM], g_qkvl[MROWS * 3 * DM];
__device__ __half g_atth[MROWS * DM];                   // hi only
__device__ __half g_xch [MROWS * DCAT];                 // hi only
__device__ __half g_h1h [MROWS * DFF];                  // hi only
__device__ __half g_pch [BB * 32 * DCAT], g_pcl[BB * 32 * DCAT];

// fp16 weights
#define OFF_W_IN  0
#define OFF_W_QKV (OFF_W_IN  + NLAYER * DM * DM)
#define OFF_W_AO  (OFF_W_QKV + NLAYER * 3 * DM * DM)
#define OFF_W_L1  (OFF_W_AO  + NLAYER * DM * DM)
#define OFF_W_L2  (OFF_W_L1  + NLAYER * DFF * DCAT)
#define OFF_W_OUT (OFF_W_L2  + NLAYER * DCAT * DFF)
#define W_TOTAL   (OFF_W_OUT + DT * DCAT)
__device__ __half g_wh[W_TOTAL];

// ---------------------------------------------------------------------------
// Helpers
// ---------------------------------------------------------------------------
__device__ __forceinline__ uint32_t smem_u32(const void* p) {
    uint32_t a;
    asm("{ .reg .u64 t; cvta.to.shared.u64 t, %1; cvt.u32.u64 %0, t; }"
        : "=r"(a) : "l"(p));
    return a;
}

__device__ __forceinline__ void split1(float v, __half& h, __half& l) {
    h = __float2half_rn(v);
    l = __float2half_rn(v - __half2float(h));
}

__device__ __forceinline__ uint32_t pack_h2(float a, float b, uint32_t& lo) {
    __half ha, la, hb, lb;
    split1(a, ha, la); split1(b, hb, lb);
    lo = (uint32_t)__half_as_ushort(la) | ((uint32_t)__half_as_ushort(lb) << 16);
    return (uint32_t)__half_as_ushort(ha) | ((uint32_t)__half_as_ushort(hb) << 16);
}

__device__ __forceinline__ uint32_t pack_h2_hi(float a, float b) {
    __half ha = __float2half_rn(a), hb = __float2half_rn(b);
    return (uint32_t)__half_as_ushort(ha) | ((uint32_t)__half_as_ushort(hb) << 16);
}

// weights: float -> fp16 (hi only)
__global__ void wsplit_kernel(const float* __restrict__ X,
                              __half* __restrict__ H, int n4)
{
    const int i = blockIdx.x * blockDim.x + threadIdx.x;
    if (i >= n4) return;
    const float4 v = *(const float4*)(X + (size_t)i * 4);
    __half h[4];
    h[0] = __float2half_rn(v.x); h[1] = __float2half_rn(v.y);
    h[2] = __float2half_rn(v.z); h[3] = __float2half_rn(v.w);
    *(uint2*)(H + (size_t)i * 4) = *(uint2*)h;
}

// ---------------------------------------------------------------------------
// MMA / ldmatrix / cp.async primitives
// ---------------------------------------------------------------------------
#define LDSM4(R, addr) \
    asm volatile("ldmatrix.sync.aligned.m8n8.x4.shared.b16 {%0,%1,%2,%3}, [%4];" \
        : "=r"((R)[0]), "=r"((R)[1]), "=r"((R)[2]), "=r"((R)[3]) : "r"(addr))

#define LDSM4T(R, addr) \
    asm volatile("ldmatrix.sync.aligned.m8n8.x4.trans.shared.b16 {%0,%1,%2,%3}, [%4];" \
        : "=r"((R)[0]), "=r"((R)[1]), "=r"((R)[2]), "=r"((R)[3]) : "r"(addr))

#define MMA16816(D, A, B0, B1) \
    asm volatile("mma.sync.aligned.m16n8k16.row.col.f32.f16.f16.f32 " \
        "{%0,%1,%2,%3}, {%4,%5,%6,%7}, {%8,%9}, {%0,%1,%2,%3};" \
        : "+f"((D)[0]), "+f"((D)[1]), "+f"((D)[2]), "+f"((D)[3]) \
        : "r"((A)[0]), "r"((A)[1]), "r"((A)[2]), "r"((A)[3]), "r"(B0), "r"(B1))

__device__ __forceinline__ void cp_async16(uint32_t d, const void* s) {
    asm volatile("cp.async.cg.shared.global [%0], [%1], 16;" :: "r"(d), "l"(s));
}
#define CP_COMMIT() asm volatile("cp.async.commit_group;" ::: "memory")
#define CP_WAIT(n)  asm volatile("cp.async.wait_group %0;" :: "n"(n) : "memory")

__device__ __forceinline__ float act_apply(float v, int act) {
    if (act == 1) return fmaxf(v, 0.f);
    if (act == 2) return 0.5f * v * (1.f + erff(v * 0.70710678118654752f));
    return v;
}

// ---------------------------------------------------------------------------
// fp16 mma.sync GEMM. A = Ah (+ optional Al) fp16, W = Wh fp16, fp32 accum.
// 128x128 CTA tile, K-chunk 32, 8 warps of 32x64, cp.async double buffer.
// ---------------------------------------------------------------------------
#define PITCH_B 80
#define OFF_AH 0
#define OFF_AL (128 * PITCH_B)
#define OFF_BH (2 * 128 * PITCH_B)
#define STAGE_B (3 * 128 * PITCH_B)
#define GEMM_SMEM (2 * STAGE_B)

__global__ __launch_bounds__(256)
void gemm_hf(const __half* __restrict__ Ah, const __half* __restrict__ Al,
             int lda,
             const __half* __restrict__ Wh, int K,
             const float* __restrict__ bias,
             float* __restrict__ Cf,
             __half* __restrict__ Ch, __half* __restrict__ Cl,
             int ldc, int act)
{
    extern __shared__ char sm[];
    const uint32_t sb = smem_u32(sm);
    const bool twoA = (Al != nullptr);

    const int tid = threadIdx.x;
    const int wid = tid >> 5;
    const int lane = tid & 31;
    const int m0 = blockIdx.x * 128;
    const int n0 = blockIdx.y * 128;
    const int wr = wid & 3;
    const int wc = wid >> 2;

    const int grow = tid >> 1;
    const int gcol = (tid & 1) * 16;
    const __half* Ahp = Ah + (size_t)(m0 + grow) * lda + gcol;
    const __half* Alp = twoA ? (Al + (size_t)(m0 + grow) * lda + gcol) : nullptr;
    const __half* Whp = Wh + (size_t)(n0 + grow) * K + gcol;
    const uint32_t sts_off = (uint32_t)grow * PITCH_B + (uint32_t)gcol * 2;

    const int a_lrow = (lane & 7) + ((lane >> 3) & 1) * 8;
    const int a_koff = (lane >> 4) * 8;
    const int b_lrow = (lane & 7) + ((lane >> 4) & 1) * 8;
    const int b_koff = ((lane >> 3) & 1) * 8;
    const uint32_t a_lbase = (uint32_t)(wr * 32 + a_lrow) * PITCH_B + (uint32_t)a_koff * 2;
    const uint32_t b_lbase = (uint32_t)(wc * 64 + b_lrow) * PITCH_B + (uint32_t)b_koff * 2;

    float acc[2][8][4];
    #pragma unroll
    for (int mt = 0; mt < 2; mt++)
        #pragma unroll
        for (int nt = 0; nt < 8; nt++)
            #pragma unroll
            for (int r = 0; r < 4; r++) acc[mt][nt][r] = 0.f;

    const int NC = K >> 5;

    auto issue = [&](int c) {
        const uint32_t d = sb + (uint32_t)(c & 1) * STAGE_B + sts_off;
        cp_async16(d + OFF_AH,      Ahp + c * 32);
        cp_async16(d + OFF_AH + 16, Ahp + c * 32 + 8);
        if (twoA) {
            cp_async16(d + OFF_AL,      Alp + c * 32);
            cp_async16(d + OFF_AL + 16, Alp + c * 32 + 8);
        }
        cp_async16(d + OFF_BH,      Whp + c * 32);
        cp_async16(d + OFF_BH + 16, Whp + c * 32 + 8);
        CP_COMMIT();
    };

    issue(0);
    if (NC > 1) issue(1);

    for (int c = 0; c < NC; c++) {
        if (c + 1 < NC) CP_WAIT(1); else CP_WAIT(0);
        __syncthreads();

        const uint32_t so = (uint32_t)(c & 1) * STAGE_B;

        #pragma unroll
        for (int step = 0; step < 2; step++) {
            const uint32_t kb = (uint32_t)step * 32;

            uint32_t ahr[2][4], alr[2][4];
            #pragma unroll
            for (int mt = 0; mt < 2; mt++) {
                const uint32_t aa = sb + so + a_lbase + (uint32_t)mt * (16 * PITCH_B) + kb;
                LDSM4(ahr[mt], aa + OFF_AH);
                if (twoA) LDSM4(alr[mt], aa + OFF_AL);
            }

            #pragma unroll
            for (int g = 0; g < 4; g++) {
                const uint32_t ba = sb + so + b_lbase + (uint32_t)g * (16 * PITCH_B) + kb;
                uint32_t bh[4];
                LDSM4(bh, ba + OFF_BH);
                #pragma unroll
                for (int mt = 0; mt < 2; mt++) {
                    MMA16816(acc[mt][2 * g],     ahr[mt], bh[0], bh[1]);
                    MMA16816(acc[mt][2 * g + 1], ahr[mt], bh[2], bh[3]);
                    if (twoA) {
                        MMA16816(acc[mt][2 * g],     alr[mt], bh[0], bh[1]);
                        MMA16816(acc[mt][2 * g + 1], alr[mt], bh[2], bh[3]);
                    }
                }
            }
        }
        __syncthreads();
        if (c + 2 < NC) issue(c + 2);
    }

    const int g = lane >> 2;
    const int t = lane & 3;
    #pragma unroll
    for (int mt = 0; mt < 2; mt++) {
        #pragma unroll
        for (int nt = 0; nt < 8; nt++) {
            const int col = n0 + wc * 64 + nt * 8 + t * 2;
            const float b0 = bias[col], b1 = bias[col + 1];
            const int r0 = m0 + wr * 32 + mt * 16 + g;
            float v00 = act_apply(acc[mt][nt][0] + b0, act);
            float v01 = act_apply(acc[mt][nt][1] + b1, act);
            float v10 = act_apply(acc[mt][nt][2] + b0, act);
            float v11 = act_apply(acc[mt][nt][3] + b1, act);
            if (Cf) {
                *(float2*)(Cf + (size_t)r0 * ldc + col) = make_float2(v00, v01);
                *(float2*)(Cf + (size_t)(r0 + 8) * ldc + col) = make_float2(v10, v11);
            }
            if (Ch) {
                if (Cl) {
                    uint32_t lo, hi;
                    hi = pack_h2(v00, v01, lo);
                    *(uint32_t*)(Ch + (size_t)r0 * ldc + col) = hi;
                    *(uint32_t*)(Cl + (size_t)r0 * ldc + col) = lo;
                    hi = pack_h2(v10, v11, lo);
                    *(uint32_t*)(Ch + (size_t)(r0 + 8) * ldc + col) = hi;
                    *(uint32_t*)(Cl + (size_t)(r0 + 8) * ldc + col) = lo;
                } else {
                    *(uint32_t*)(Ch + (size_t)r0 * ldc + col) = pack_h2_hi(v00, v01);
                    *(uint32_t*)(Ch + (size_t)(r0 + 8) * ldc + col) = pack_h2_hi(v10, v11);
                }
            }
        }
    }
}

// ---------------------------------------------------------------------------
// Warp-per-row LayerNorm. 8 warps/block, 1 row/warp. NV4 = D/128.
// ---------------------------------------------------------------------------
__device__ __forceinline__ void warp_reduce2(float& s, float& q) {
    #pragma unroll
    for (int o = 16; o > 0; o >>= 1) {
        s += __shfl_xor_sync(0xffffffffu, s, o);
        q += __shfl_xor_sync(0xffffffffu, q, o);
    }
}

__device__ __forceinline__ void ln_store(float4 o, float* Y, __half* H,
                                         __half* L, size_t off) {
    if (Y) *(float4*)(Y + off) = o;
    if (H) {
        if (L) {
            __half h[4], l[4];
            split1(o.x, h[0], l[0]); split1(o.y, h[1], l[1]);
            split1(o.z, h[2], l[2]); split1(o.w, h[3], l[3]);
            *(uint2*)(H + off) = *(uint2*)h;
            *(uint2*)(L + off) = *(uint2*)l;
        } else {
            __half h[4];
            h[0] = __float2half_rn(o.x); h[1] = __float2half_rn(o.y);
            h[2] = __float2half_rn(o.z); h[3] = __float2half_rn(o.w);
            *(uint2*)(H + off) = *(uint2*)h;
        }
    }
}

template <int NV4>
__global__ void ln_kernel(const float* __restrict__ X, int ldx,
                          const float* __restrict__ R, int ldr,
                          const float* __restrict__ g, const float* __restrict__ b,
                          float* __restrict__ Y,
                          __half* __restrict__ H,
                          __half* __restrict__ L, int ldy)
{
    const int row = blockIdx.x * 8 + (threadIdx.x >> 5);
    const int lane = threadIdx.x & 31;
    const float D = (float)(NV4 * 128);

    float4 v[NV4];
    float s = 0.f, q = 0.f;
    #pragma unroll
    for (int j = 0; j < NV4; j++) {
        const int c4 = (lane + j * 32) << 2;
        v[j] = *(const float4*)(X + (size_t)row * ldx + c4);
        if (R) {
            const float4 r = *(const float4*)(R + (size_t)row * ldr + c4);
            v[j].x += r.x; v[j].y += r.y; v[j].z += r.z; v[j].w += r.w;
        }
        s += v[j].x + v[j].y + v[j].z + v[j].w;
        q += v[j].x * v[j].x + v[j].y * v[j].y + v[j].z * v[j].z + v[j].w * v[j].w;
    }
    warp_reduce2(s, q);
    const float mean = s / D;
    const float rstd = rsqrtf(fmaxf(q / D - mean * mean, 0.f) + 1e-5f);
    #pragma unroll
    for (int j = 0; j < NV4; j++) {
        const int c4 = (lane + j * 32) << 2;
        const float4 g4 = *(const float4*)(g + c4);
        const float4 b4 = *(const float4*)(b + c4);
        float4 o;
        o.x = (v[j].x - mean) * rstd * g4.x + b4.x;
        o.y = (v[j].y - mean) * rstd * g4.y + b4.y;
        o.z = (v[j].z - mean) * rstd * g4.z + b4.z;
        o.w = (v[j].w - mean) * rstd * g4.w + b4.w;
        ln_store(o, Y, H, L, (size_t)row * ldy + c4);
    }
}

// time branch: LN((diag+1) * x_time), D = 256
__global__ void ln_diag_kernel(const float* __restrict__ X,
                               const float* __restrict__ diag,
                               const float* __restrict__ g, const float* __restrict__ b,
                               float* __restrict__ Y,
                               __half* __restrict__ H, int ldy)
{
    const int row = blockIdx.x * 8 + (threadIdx.x >> 5);
    const int lane = threadIdx.x & 31;
    const int bb = row >> 9, l = row & 511;

    float4 v[2];
    float s = 0.f, q = 0.f;
    #pragma unroll
    for (int j = 0; j < 2; j++) {
        const int c4 = (lane + j * 32) << 2;
        const int h = c4 >> 5;
        const float dscale = diag[((size_t)bb * NH + h) * LL + l] + 1.f;
        v[j] = *(const float4*)(X + (size_t)row * DT + c4);
        v[j].x *= dscale; v[j].y *= dscale; v[j].z *= dscale; v[j].w *= dscale;
        s += v[j].x + v[j].y + v[j].z + v[j].w;
        q += v[j].x * v[j].x + v[j].y * v[j].y + v[j].z * v[j].z + v[j].w * v[j].w;
    }
    warp_reduce2(s, q);
    const float mean = s / (float)DT;
    const float rstd = rsqrtf(fmaxf(q / (float)DT - mean * mean, 0.f) + 1e-5f);
    #pragma unroll
    for (int j = 0; j < 2; j++) {
        const int c4 = (lane + j * 32) << 2;
        const float4 g4 = *(const float4*)(g + c4);
        const float4 b4 = *(const float4*)(b + c4);
        float4 o;
        o.x = (v[j].x - mean) * rstd * g4.x + b4.x;
        o.y = (v[j].y - mean) * rstd * g4.y + b4.y;
        o.z = (v[j].z - mean) * rstd * g4.z + b4.z;
        o.w = (v[j].w - mean) * rstd * g4.w + b4.w;
        ln_store(o, Y, H, nullptr, (size_t)row * ldy + c4);
    }
}

// ---------------------------------------------------------------------------
// Tensor-core flash attention. Output att hi-only.
// ---------------------------------------------------------------------------
#define AP 72
#define ATT_SMEM (4 * 64 * AP * 2)

__global__ __launch_bounds__(128)
void attn_kernel(const __half* __restrict__ qkvh,
                 const __half* __restrict__ qkvl,
                 __half* __restrict__ attH,
                 float* __restrict__ diag)
{
    extern __shared__ __half sh[];
    __half* Qh = sh;
    __half* Ql = sh + 64 * AP;
    __half* Ks = sh + 2 * 64 * AP;
    __half* Vs = sh + 3 * 64 * AP;

    const int tid = threadIdx.x;
    const int w = tid >> 5, lane = tid & 31;
    const int qt = blockIdx.x, bhid = blockIdx.y;
    const int b = bhid >> 3, h = bhid & 7;

    const size_t base = (size_t)(b * LL) * (3 * DM) + h * HD;
    const __half* qh_g = qkvh + base;
    const __half* ql_g = qkvl + base;
    const __half* kh_g = qkvh + base + DM;
    const __half* vh_g = qkvh + base + 2 * DM;

    #pragma unroll
    for (int i = 0; i < 4; i++) {
        const int idx = tid + i * 128;
        const int r = idx >> 3, c = (idx & 7) * 8;
        const size_t go = (size_t)(qt * 64 + r) * (3 * DM) + c;
        *(uint4*)(Qh + r * AP + c) = *(const uint4*)(qh_g + go);
        *(uint4*)(Ql + r * AP + c) = *(const uint4*)(ql_g + go);
    }
    __syncthreads();

    const int a_row = (lane & 7) + ((lane >> 3) & 1) * 8;
    const int a_k   = (lane >> 4) * 8;
    uint32_t qhf[4][4], qlf[4][4];
    #pragma unroll
    for (int ks = 0; ks < 4; ks++) {
        LDSM4(qhf[ks], smem_u32(Qh + (w * 16 + a_row) * AP + ks * 16 + a_k));
        LDSM4(qlf[ks], smem_u32(Ql + (w * 16 + a_row) * AP + ks * 16 + a_k));
    }

    const int g  = lane >> 2;
    const int t2 = (lane & 3) * 2;
    const int b_row = (lane & 7) + ((lane >> 4) & 1) * 8;
    const int b_k   = ((lane >> 3) & 1) * 8;
    const int v_row = (lane & 7) + ((lane >> 3) & 1) * 8;
    const int v_col = ((lane >> 4) & 1) * 8;

    float m_[2] = {-1e30f, -1e30f}, l_[2] = {0.f, 0.f}, sd_[2] = {0.f, 0.f};
    float o[8][4];
    #pragma unroll
    for (int i = 0; i < 8; i++)
        #pragma unroll
        for (int j = 0; j < 4; j++) o[i][j] = 0.f;

    for (int kt = 0; kt < 8; kt++) {
        __syncthreads();
        #pragma unroll
        for (int i = 0; i < 4; i++) {
            const int idx = tid + i * 128;
            const int r = idx >> 3, c = (idx & 7) * 8;
            const size_t go = (size_t)(kt * 64 + r) * (3 * DM) + c;
            *(uint4*)(Ks + r * AP + c) = *(const uint4*)(kh_g + go);
            *(uint4*)(Vs + r * AP + c) = *(const uint4*)(vh_g + go);
        }
        __syncthreads();

        float s[8][4];
        #pragma unroll
        for (int i = 0; i < 8; i++)
            #pragma unroll
            for (int j = 0; j < 4; j++) s[i][j] = 0.f;

        #pragma unroll
        for (int ks = 0; ks < 4; ks++)
            #pragma unroll
            for (int np = 0; np < 4; np++) {
                uint32_t bf[4];
                LDSM4(bf, smem_u32(Ks + (np * 16 + b_row) * AP + ks * 16 + b_k));
                MMA16816(s[2 * np],     qhf[ks], bf[0], bf[1]);
                MMA16816(s[2 * np],     qlf[ks], bf[0], bf[1]);
                MMA16816(s[2 * np + 1], qhf[ks], bf[2], bf[3]);
                MMA16816(s[2 * np + 1], qlf[ks], bf[2], bf[3]);
            }

        #pragma unroll
        for (int i = 0; i < 8; i++)
            #pragma unroll
            for (int j = 0; j < 4; j++) s[i][j] *= 0.125f;

        if (kt == qt) {
            #pragma unroll
            for (int nt = 0; nt < 8; nt++)
                #pragma unroll
                for (int ci = 0; ci < 4; ci++) {
                    const int ri = w * 16 + g + (ci >> 1) * 8;
                    const int co = nt * 8 + t2 + (ci & 1);
                    if (ri == co) sd_[ci >> 1] = s[nt][ci];
                }
        }

        #pragma unroll
        for (int r = 0; r < 2; r++) {
            float mt = -1e30f;
            #pragma unroll
            for (int nt = 0; nt < 8; nt++)
                mt = fmaxf(mt, fmaxf(s[nt][2 * r], s[nt][2 * r + 1]));
            mt = fmaxf(mt, __shfl_xor_sync(0xffffffffu, mt, 1));
            mt = fmaxf(mt, __shfl_xor_sync(0xffffffffu, mt, 2));
            const float mn = fmaxf(m_[r], mt);
            const float corr = __expf(m_[r] - mn);
            float ps = 0.f;
            #pragma unroll
            for (int nt = 0; nt < 8; nt++) {
                const float p0 = __expf(s[nt][2 * r] - mn);
                const float p1 = __expf(s[nt][2 * r + 1] - mn);
                s[nt][2 * r] = p0; s[nt][2 * r + 1] = p1;
                ps += p0 + p1;
            }
            ps += __shfl_xor_sync(0xffffffffu, ps, 1);
            ps += __shfl_xor_sync(0xffffffffu, ps, 2);
            l_[r] = l_[r] * corr + ps;
            m_[r] = mn;
            #pragma unroll
            for (int nt = 0; nt < 8; nt++) {
                o[nt][2 * r] *= corr; o[nt][2 * r + 1] *= corr;
            }
        }

        #pragma unroll
        for (int j = 0; j < 4; j++) {
            uint32_t phf[4], plf[4];
            phf[0] = pack_h2(s[2 * j][0],     s[2 * j][1],     plf[0]);
            phf[1] = pack_h2(s[2 * j][2],     s[2 * j][3],     plf[1]);
            phf[2] = pack_h2(s[2 * j + 1][0], s[2 * j + 1][1], plf[2]);
            phf[3] = pack_h2(s[2 * j + 1][2], s[2 * j + 1][3], plf[3]);
            #pragma unroll
            for (int dp = 0; dp < 4; dp++) {
                uint32_t vf[4];
                LDSM4T(vf, smem_u32(Vs + (j * 16 + v_row) * AP + dp * 16 + v_col));
                MMA16816(o[2 * dp],     phf, vf[0], vf[1]);
                MMA16816(o[2 * dp],     plf, vf[0], vf[1]);
                MMA16816(o[2 * dp + 1], phf, vf[2], vf[3]);
                MMA16816(o[2 * dp + 1], plf, vf[2], vf[3]);
            }
        }
    }

    #pragma unroll
    for (int r = 0; r < 2; r++) {
        const float inv = 1.f / l_[r];
        const int row = qt * 64 + w * 16 + g + r * 8;
        const size_t ob = ((size_t)b * LL + row) * DM + h * HD;
        #pragma unroll
        for (int dt = 0; dt < 8; dt++)
            *(uint32_t*)(attH + ob + dt * 8 + t2) =
                pack_h2_hi(o[dt][2 * r] * inv, o[dt][2 * r + 1] * inv);
        if ((lane & 3) == (g >> 1))
            diag[(size_t)bhid * LL + row] = __expf(sd_[r] - m_[r]) * inv;
    }
}

// ---------------------------------------------------------------------------
// MaxPool 16 over seq, concat tok|time -> fp16 hi/lo [1024, 768]
// ---------------------------------------------------------------------------
__global__ void pool_kernel(const float* __restrict__ tok,
                            const float* __restrict__ tim,
                            __half* __restrict__ pcH,
                            __half* __restrict__ pcL)
{
    const int orow = blockIdx.x;
    const int b = orow >> 5, gq = orow & 31;
    for (int d = threadIdx.x; d < DCAT; d += blockDim.x) {
        float mx = -1e30f;
        if (d < DM) {
            const float* p = tok + ((size_t)b * LL + gq * 16) * DM + d;
            #pragma unroll
            for (int j = 0; j < 16; j++) mx = fmaxf(mx, p[j * DM]);
        } else {
            const float* p = tim + ((size_t)b * LL + gq * 16) * DT + (d - DM);
            #pragma unroll
            for (int j = 0; j < 16; j++) mx = fmaxf(mx, p[j * DT]);
        }
        __half h, l;
        split1(mx, h, l);
        pcH[(size_t)orow * DCAT + d] = h;
        pcL[(size_t)orow * DCAT + d] = l;
    }
}

// ---------------------------------------------------------------------------
// Host orchestration
// ---------------------------------------------------------------------------
static void wsplit_launch(const float* X, __half* H, long n)
{
    const int n4 = (int)(n / 4);
    wsplit_kernel<<<(n4 + 255) / 256, 256>>>(X, H, n4);
}

extern "C" void kernel_launch(void* const* d_in, const int* in_sizes, int n_in,
                              void* d_out, int out_size)
{
    const float* in[26];
    for (int i = 0; i < 26; i++) in[i] = (const float*)d_in[i];

    float *x, *ao, *xc, *ff, *tok, *timeb, *diag, *o1;
    cudaGetSymbolAddress((void**)&x,     g_x);
    cudaGetSymbolAddress((void**)&ao,    g_ao);
    cudaGetSymbolAddress((void**)&xc,    g_xc);
    cudaGetSymbolAddress((void**)&ff,    g_ff);
    cudaGetSymbolAddress((void**)&tok,   g_tok);
    cudaGetSymbolAddress((void**)&timeb, g_time);
    cudaGetSymbolAddress((void**)&diag,  g_diag);
    cudaGetSymbolAddress((void**)&o1,    g_o1);

    __half *ln0h, *xh, *qkvh, *qkvl, *atth, *xch, *h1h, *pch, *pcl, *wh;
    cudaGetSymbolAddress((void**)&ln0h, g_ln0h);
    cudaGetSymbolAddress((void**)&xh,   g_xh);
    cudaGetSymbolAddress((void**)&qkvh, g_qkvh); cudaGetSymbolAddress((void**)&qkvl, g_qkvl);
    cudaGetSymbolAddress((void**)&atth, g_atth);
    cudaGetSymbolAddress((void**)&xch,  g_xch);
    cudaGetSymbolAddress((void**)&h1h,  g_h1h);
    cudaGetSymbolAddress((void**)&pch,  g_pch);  cudaGetSymbolAddress((void**)&pcl,  g_pcl);
    cudaGetSymbolAddress((void**)&wh,   g_wh);

    cudaFuncSetAttribute(attn_kernel,
                         cudaFuncAttributeMaxDynamicSharedMemorySize, ATT_SMEM);
    cudaFuncSetAttribute(gemm_hf,
                         cudaFuncAttributeMaxDynamicSharedMemorySize, GEMM_SMEM);

    // pre-convert all weights to fp16
    wsplit_launch(in[4],  wh + OFF_W_IN,  (long)NLAYER * DM * DM);
    wsplit_launch(in[6],  wh + OFF_W_QKV, (long)NLAYER * 3 * DM * DM);
    wsplit_launch(in[8],  wh + OFF_W_AO,  (long)NLAYER * DM * DM);
    wsplit_launch(in[10], wh + OFF_W_L1,  (long)NLAYER * DFF * DCAT);
    wsplit_launch(in[12], wh + OFF_W_L2,  (long)NLAYER * DCAT * DFF);
    wsplit_launch(in[22], wh + OFF_W_OUT, (long)DT * DCAT);

    const int M = MROWS;
    for (int i = 0; i < NLAYER; i++) {
        const float* xin = i ? tok : in[0];
        const float* tin = i ? timeb : in[1];

        // norm0 -> fp16 hi only
        ln_kernel<4><<<M / 8, 256>>>(xin, DM, nullptr, 0,
                                     in[2] + i * DM, in[3] + i * DM,
                                     nullptr, ln0h, nullptr, DM);
        // in_proj (1-term) -> fp32 x + fp16 hi
        gemm_hf<<<dim3(M / 128, DM / 128), 256, GEMM_SMEM>>>(
            ln0h, nullptr, DM, wh + OFF_W_IN + (long)i * DM * DM, DM,
            in[5] + i * DM, x, xh, nullptr, DM, 0);
        // qkv (1-term) -> fp16 hi/lo (2-term output for attention Q)
        gemm_hf<<<dim3(M / 128, 3 * DM / 128), 256, GEMM_SMEM>>>(
            xh, nullptr, DM, wh + OFF_W_QKV + (long)i * 3 * DM * DM, DM,
            in[7] + i * 3 * DM, nullptr, qkvh, qkvl, 3 * DM, 0);

        attn_kernel<<<dim3(LL / 64, BB * NH), 128, ATT_SMEM>>>(
            qkvh, qkvl, atth, diag);

        // attn out proj (1-term) -> fp32
        gemm_hf<<<dim3(M / 128, DM / 128), 256, GEMM_SMEM>>>(
            atth, nullptr, DM, wh + OFF_W_AO + (long)i * DM * DM, DM,
            in[9] + i * DM, ao, nullptr, nullptr, DM, 0);

        // n1 -> xc fp32 + xch hi-only ; n2 -> xc+DM fp32 + xch+DM hi-only
        ln_kernel<4><<<M / 8, 256>>>(ao, DM, x, DM,
                                     in[14] + i * DM, in[15] + i * DM,
                                     xc, xch, nullptr, DCAT);
        ln_diag_kernel<<<M / 8, 256>>>(tin, diag,
                                       in[16] + i * DT, in[17] + i * DT,
                                       xc + DM, xch + DM, DCAT);

        // FF1 (1-term) -> h1 hi-only ; FF2 (1-term) -> fp32
        gemm_hf<<<dim3(M / 128, DFF / 128), 256, GEMM_SMEM>>>(
            xch, nullptr, DCAT, wh + OFF_W_L1 + (long)i * DFF * DCAT, DCAT,
            in[11] + i * DFF, nullptr, h1h, nullptr, DFF, 1);
        gemm_hf<<<dim3(M / 128, DCAT / 128), 256, GEMM_SMEM>>>(
            h1h, nullptr, DFF, wh + OFF_W_L2 + (long)i * DCAT * DFF, DFF,
            in[13] + i * DCAT, ff, nullptr, nullptr, DCAT, 0);

        // n3 / n4 -> fp32 streams
        ln_kernel<4><<<M / 8, 256>>>(ff, DCAT, xc, DCAT,
                                     in[18] + i * DM, in[19] + i * DM,
                                     tok, nullptr, nullptr, DM);
        ln_kernel<2><<<M / 8, 256>>>(ff + DM, DCAT, xc + DM, DCAT,
                                     in[20] + i * DT, in[21] + i * DT,
                                     timeb, nullptr, nullptr, DT);
    }

    pool_kernel<<<BB * 32, 256>>>(tok, timeb, pch, pcl);
    gemm_hf<<<dim3(BB * 32 / 128, DT / 128), 256, GEMM_SMEM>>>(
        pch, pcl, DCAT, wh + OFF_W_OUT, DCAT, in[23],
        o1, nullptr, nullptr, DT, 2);
    ln_kernel<2><<<BB * 32 / 8, 256>>>(o1, DT, nullptr, 0, in[24], in[25],
                                       (float*)d_out, nullptr, nullptr, DT);
}

// round 14
// speedup vs baseline: 3.9655x; 1.0778x over previous
#include <cuda_runtime.h>
#include <cuda_fp16.h>
#include <math.h>
#include <stdint.h>

// ---------------------------------------------------------------------------
// Problem constants
// ---------------------------------------------------------------------------
#define BB 32
#define LL 512
#define DM 512
#define DT 256
#define NH 8
#define HD 64
#define DFF 2048
#define NLAYER 2
#define MROWS (BB * LL)          // 16384
#define DCAT (DM + DT)           // 768

// ---------------------------------------------------------------------------
// Scratch (device globals)
// ---------------------------------------------------------------------------
__device__ float g_x   [MROWS * DM];
__device__ float g_ao  [MROWS * DM];
__device__ float g_xc  [MROWS * DCAT];
__device__ float g_ff  [MROWS * DCAT];
__device__ float g_tok [MROWS * DM];
__device__ float g_time[MROWS * DT];
__device__ float g_diag[BB * NH * LL];
__device__ float g_o1  [BB * 32 * DT];

// fp16 activation buffers
__device__ __half g_ln0h[MROWS * DM];                   // hi only
__device__ __half g_xh  [MROWS * DM];                   // hi only
__device__ __half g_qkvh[MROWS * 3 * DM], g_qkvl[MROWS * 3 * DM];
__device__ __half g_atth[MROWS * DM];                   // hi only
__device__ __half g_xch [MROWS * DCAT];                 // hi only
__device__ __half g_h1h [MROWS * DFF];                  // hi only
__device__ __half g_pch [BB * 32 * DCAT], g_pcl[BB * 32 * DCAT];

// fp16 weights
#define OFF_W_IN  0
#define OFF_W_QKV (OFF_W_IN  + NLAYER * DM * DM)
#define OFF_W_AO  (OFF_W_QKV + NLAYER * 3 * DM * DM)
#define OFF_W_L1  (OFF_W_AO  + NLAYER * DM * DM)
#define OFF_W_L2  (OFF_W_L1  + NLAYER * DFF * DCAT)
#define OFF_W_OUT (OFF_W_L2  + NLAYER * DCAT * DFF)
#define W_TOTAL   (OFF_W_OUT + DT * DCAT)
__device__ __half g_wh[W_TOTAL];

// ---------------------------------------------------------------------------
// Helpers
// ---------------------------------------------------------------------------
__device__ __forceinline__ uint32_t smem_u32(const void* p) {
    uint32_t a;
    asm("{ .reg .u64 t; cvta.to.shared.u64 t, %1; cvt.u32.u64 %0, t; }"
        : "=r"(a) : "l"(p));
    return a;
}

__device__ __forceinline__ void split1(float v, __half& h, __half& l) {
    h = __float2half_rn(v);
    l = __float2half_rn(v - __half2float(h));
}

__device__ __forceinline__ uint32_t pack_h2(float a, float b, uint32_t& lo) {
    __half ha, la, hb, lb;
    split1(a, ha, la); split1(b, hb, lb);
    lo = (uint32_t)__half_as_ushort(la) | ((uint32_t)__half_as_ushort(lb) << 16);
    return (uint32_t)__half_as_ushort(ha) | ((uint32_t)__half_as_ushort(hb) << 16);
}

__device__ __forceinline__ uint32_t pack_h2_hi(float a, float b) {
    __half ha = __float2half_rn(a), hb = __float2half_rn(b);
    return (uint32_t)__half_as_ushort(ha) | ((uint32_t)__half_as_ushort(hb) << 16);
}

// weights: float -> fp16 (hi only)
__global__ void wsplit_kernel(const float* __restrict__ X,
                              __half* __restrict__ H, int n4)
{
    const int i = blockIdx.x * blockDim.x + threadIdx.x;
    if (i >= n4) return;
    const float4 v = *(const float4*)(X + (size_t)i * 4);
    __half h[4];
    h[0] = __float2half_rn(v.x); h[1] = __float2half_rn(v.y);
    h[2] = __float2half_rn(v.z); h[3] = __float2half_rn(v.w);
    *(uint2*)(H + (size_t)i * 4) = *(uint2*)h;
}

// ---------------------------------------------------------------------------
// MMA / ldmatrix / cp.async primitives
// ---------------------------------------------------------------------------
#define LDSM4(R, addr) \
    asm volatile("ldmatrix.sync.aligned.m8n8.x4.shared.b16 {%0,%1,%2,%3}, [%4];" \
        : "=r"((R)[0]), "=r"((R)[1]), "=r"((R)[2]), "=r"((R)[3]) : "r"(addr))

#define LDSM4T(R, addr) \
    asm volatile("ldmatrix.sync.aligned.m8n8.x4.trans.shared.b16 {%0,%1,%2,%3}, [%4];" \
        : "=r"((R)[0]), "=r"((R)[1]), "=r"((R)[2]), "=r"((R)[3]) : "r"(addr))

#define MMA16816(D, A, B0, B1) \
    asm volatile("mma.sync.aligned.m16n8k16.row.col.f32.f16.f16.f32 " \
        "{%0,%1,%2,%3}, {%4,%5,%6,%7}, {%8,%9}, {%0,%1,%2,%3};" \
        : "+f"((D)[0]), "+f"((D)[1]), "+f"((D)[2]), "+f"((D)[3]) \
        : "r"((A)[0]), "r"((A)[1]), "r"((A)[2]), "r"((A)[3]), "r"(B0), "r"(B1))

__device__ __forceinline__ void cp_async16(uint32_t d, const void* s) {
    asm volatile("cp.async.cg.shared.global [%0], [%1], 16;" :: "r"(d), "l"(s));
}
#define CP_COMMIT() asm volatile("cp.async.commit_group;" ::: "memory")
#define CP_WAIT(n)  asm volatile("cp.async.wait_group %0;" :: "n"(n) : "memory")

__device__ __forceinline__ float act_apply(float v, int act) {
    if (act == 1) return fmaxf(v, 0.f);
    if (act == 2) return 0.5f * v * (1.f + erff(v * 0.70710678118654752f));
    return v;
}

// ---------------------------------------------------------------------------
// fp16 mma.sync GEMM. A = Ah (+ optional Al) fp16, W = Wh fp16, fp32 accum.
// 128x128 CTA tile, K-chunk 32, 8 warps of 32x64, 3-stage cp.async pipeline
// (one __syncthreads per chunk; issue(c+2) writes the third buffer).
// ---------------------------------------------------------------------------
#define PITCH_B 80
#define OFF_AH 0
#define OFF_AL (128 * PITCH_B)
#define OFF_BH (2 * 128 * PITCH_B)
#define STAGE_B (3 * 128 * PITCH_B)   // 30720
#define GEMM_SMEM (3 * STAGE_B)       // 92160

__global__ __launch_bounds__(256)
void gemm_hf(const __half* __restrict__ Ah, const __half* __restrict__ Al,
             int lda,
             const __half* __restrict__ Wh, int K,
             const float* __restrict__ bias,
             float* __restrict__ Cf,
             __half* __restrict__ Ch, __half* __restrict__ Cl,
             int ldc, int act)
{
    extern __shared__ char sm[];
    const uint32_t sb = smem_u32(sm);
    const bool twoA = (Al != nullptr);

    const int tid = threadIdx.x;
    const int wid = tid >> 5;
    const int lane = tid & 31;
    const int m0 = blockIdx.x * 128;
    const int n0 = blockIdx.y * 128;
    const int wr = wid & 3;
    const int wc = wid >> 2;

    const int grow = tid >> 1;
    const int gcol = (tid & 1) * 16;
    const __half* Ahp = Ah + (size_t)(m0 + grow) * lda + gcol;
    const __half* Alp = twoA ? (Al + (size_t)(m0 + grow) * lda + gcol) : nullptr;
    const __half* Whp = Wh + (size_t)(n0 + grow) * K + gcol;
    const uint32_t sts_off = (uint32_t)grow * PITCH_B + (uint32_t)gcol * 2;

    const int a_lrow = (lane & 7) + ((lane >> 3) & 1) * 8;
    const int a_koff = (lane >> 4) * 8;
    const int b_lrow = (lane & 7) + ((lane >> 4) & 1) * 8;
    const int b_koff = ((lane >> 3) & 1) * 8;
    const uint32_t a_lbase = (uint32_t)(wr * 32 + a_lrow) * PITCH_B + (uint32_t)a_koff * 2;
    const uint32_t b_lbase = (uint32_t)(wc * 64 + b_lrow) * PITCH_B + (uint32_t)b_koff * 2;

    float acc[2][8][4];
    #pragma unroll
    for (int mt = 0; mt < 2; mt++)
        #pragma unroll
        for (int nt = 0; nt < 8; nt++)
            #pragma unroll
            for (int r = 0; r < 4; r++) acc[mt][nt][r] = 0.f;

    const int NC = K >> 5;

    auto issue = [&](int c) {
        const uint32_t d = sb + (uint32_t)(c % 3) * STAGE_B + sts_off;
        cp_async16(d + OFF_AH,      Ahp + c * 32);
        cp_async16(d + OFF_AH + 16, Ahp + c * 32 + 8);
        if (twoA) {
            cp_async16(d + OFF_AL,      Alp + c * 32);
            cp_async16(d + OFF_AL + 16, Alp + c * 32 + 8);
        }
        cp_async16(d + OFF_BH,      Whp + c * 32);
        cp_async16(d + OFF_BH + 16, Whp + c * 32 + 8);
        CP_COMMIT();
    };

    issue(0);
    if (NC > 1) issue(1);

    for (int c = 0; c < NC; c++) {
        if (c + 1 < NC) CP_WAIT(1); else CP_WAIT(0);
        __syncthreads();    // chunk c visible to all warps; compute(c-1) done

        const uint32_t so = (uint32_t)(c % 3) * STAGE_B;

        // issue chunk c+2 into the third buffer (neither c nor c+1): no
        // trailing barrier needed.
        if (c + 2 < NC) issue(c + 2);

        #pragma unroll
        for (int step = 0; step < 2; step++) {
            const uint32_t kb = (uint32_t)step * 32;

            uint32_t ahr[2][4], alr[2][4];
            #pragma unroll
            for (int mt = 0; mt < 2; mt++) {
                const uint32_t aa = sb + so + a_lbase + (uint32_t)mt * (16 * PITCH_B) + kb;
                LDSM4(ahr[mt], aa + OFF_AH);
                if (twoA) LDSM4(alr[mt], aa + OFF_AL);
            }

            #pragma unroll
            for (int g = 0; g < 4; g++) {
                const uint32_t ba = sb + so + b_lbase + (uint32_t)g * (16 * PITCH_B) + kb;
                uint32_t bh[4];
                LDSM4(bh, ba + OFF_BH);
                #pragma unroll
                for (int mt = 0; mt < 2; mt++) {
                    MMA16816(acc[mt][2 * g],     ahr[mt], bh[0], bh[1]);
                    MMA16816(acc[mt][2 * g + 1], ahr[mt], bh[2], bh[3]);
                    if (twoA) {
                        MMA16816(acc[mt][2 * g],     alr[mt], bh[0], bh[1]);
                        MMA16816(acc[mt][2 * g + 1], alr[mt], bh[2], bh[3]);
                    }
                }
            }
        }
    }

    const int g = lane >> 2;
    const int t = lane & 3;
    #pragma unroll
    for (int mt = 0; mt < 2; mt++) {
        #pragma unroll
        for (int nt = 0; nt < 8; nt++) {
            const int col = n0 + wc * 64 + nt * 8 + t * 2;
            const float b0 = bias[col], b1 = bias[col + 1];
            const int r0 = m0 + wr * 32 + mt * 16 + g;
            float v00 = act_apply(acc[mt][nt][0] + b0, act);
            float v01 = act_apply(acc[mt][nt][1] + b1, act);
            float v10 = act_apply(acc[mt][nt][2] + b0, act);
            float v11 = act_apply(acc[mt][nt][3] + b1, act);
            if (Cf) {
                *(float2*)(Cf + (size_t)r0 * ldc + col) = make_float2(v00, v01);
                *(float2*)(Cf + (size_t)(r0 + 8) * ldc + col) = make_float2(v10, v11);
            }
            if (Ch) {
                if (Cl) {
                    uint32_t lo, hi;
                    hi = pack_h2(v00, v01, lo);
                    *(uint32_t*)(Ch + (size_t)r0 * ldc + col) = hi;
                    *(uint32_t*)(Cl + (size_t)r0 * ldc + col) = lo;
                    hi = pack_h2(v10, v11, lo);
                    *(uint32_t*)(Ch + (size_t)(r0 + 8) * ldc + col) = hi;
                    *(uint32_t*)(Cl + (size_t)(r0 + 8) * ldc + col) = lo;
                } else {
                    *(uint32_t*)(Ch + (size_t)r0 * ldc + col) = pack_h2_hi(v00, v01);
                    *(uint32_t*)(Ch + (size_t)(r0 + 8) * ldc + col) = pack_h2_hi(v10, v11);
                }
            }
        }
    }
}

// ---------------------------------------------------------------------------
// Warp-per-row LayerNorm. 8 warps/block, 1 row/warp. NV4 = D/128.
// ---------------------------------------------------------------------------
__device__ __forceinline__ void warp_reduce2(float& s, float& q) {
    #pragma unroll
    for (int o = 16; o > 0; o >>= 1) {
        s += __shfl_xor_sync(0xffffffffu, s, o);
        q += __shfl_xor_sync(0xffffffffu, q, o);
    }
}

__device__ __forceinline__ void ln_store(float4 o, float* Y, __half* H,
                                         __half* L, size_t off) {
    if (Y) *(float4*)(Y + off) = o;
    if (H) {
        if (L) {
            __half h[4], l[4];
            split1(o.x, h[0], l[0]); split1(o.y, h[1], l[1]);
            split1(o.z, h[2], l[2]); split1(o.w, h[3], l[3]);
            *(uint2*)(H + off) = *(uint2*)h;
            *(uint2*)(L + off) = *(uint2*)l;
        } else {
            __half h[4];
            h[0] = __float2half_rn(o.x); h[1] = __float2half_rn(o.y);
            h[2] = __float2half_rn(o.z); h[3] = __float2half_rn(o.w);
            *(uint2*)(H + off) = *(uint2*)h;
        }
    }
}

template <int NV4>
__global__ void ln_kernel(const float* __restrict__ X, int ldx,
                          const float* __restrict__ R, int ldr,
                          const float* __restrict__ g, const float* __restrict__ b,
                          float* __restrict__ Y,
                          __half* __restrict__ H,
                          __half* __restrict__ L, int ldy)
{
    const int row = blockIdx.x * 8 + (threadIdx.x >> 5);
    const int lane = threadIdx.x & 31;
    const float D = (float)(NV4 * 128);

    float4 v[NV4];
    float s = 0.f, q = 0.f;
    #pragma unroll
    for (int j = 0; j < NV4; j++) {
        const int c4 = (lane + j * 32) << 2;
        v[j] = *(const float4*)(X + (size_t)row * ldx + c4);
        if (R) {
            const float4 r = *(const float4*)(R + (size_t)row * ldr + c4);
            v[j].x += r.x; v[j].y += r.y; v[j].z += r.z; v[j].w += r.w;
        }
        s += v[j].x + v[j].y + v[j].z + v[j].w;
        q += v[j].x * v[j].x + v[j].y * v[j].y + v[j].z * v[j].z + v[j].w * v[j].w;
    }
    warp_reduce2(s, q);
    const float mean = s / D;
    const float rstd = rsqrtf(fmaxf(q / D - mean * mean, 0.f) + 1e-5f);
    #pragma unroll
    for (int j = 0; j < NV4; j++) {
        const int c4 = (lane + j * 32) << 2;
        const float4 g4 = *(const float4*)(g + c4);
        const float4 b4 = *(const float4*)(b + c4);
        float4 o;
        o.x = (v[j].x - mean) * rstd * g4.x + b4.x;
        o.y = (v[j].y - mean) * rstd * g4.y + b4.y;
        o.z = (v[j].z - mean) * rstd * g4.z + b4.z;
        o.w = (v[j].w - mean) * rstd * g4.w + b4.w;
        ln_store(o, Y, H, L, (size_t)row * ldy + c4);
    }
}

// time branch: LN((diag+1) * x_time), D = 256
__global__ void ln_diag_kernel(const float* __restrict__ X,
                               const float* __restrict__ diag,
                               const float* __restrict__ g, const float* __restrict__ b,
                               float* __restrict__ Y,
                               __half* __restrict__ H, int ldy)
{
    const int row = blockIdx.x * 8 + (threadIdx.x >> 5);
    const int lane = threadIdx.x & 31;
    const int bb = row >> 9, l = row & 511;

    float4 v[2];
    float s = 0.f, q = 0.f;
    #pragma unroll
    for (int j = 0; j < 2; j++) {
        const int c4 = (lane + j * 32) << 2;
        const int h = c4 >> 5;
        const float dscale = diag[((size_t)bb * NH + h) * LL + l] + 1.f;
        v[j] = *(const float4*)(X + (size_t)row * DT + c4);
        v[j].x *= dscale; v[j].y *= dscale; v[j].z *= dscale; v[j].w *= dscale;
        s += v[j].x + v[j].y + v[j].z + v[j].w;
        q += v[j].x * v[j].x + v[j].y * v[j].y + v[j].z * v[j].z + v[j].w * v[j].w;
    }
    warp_reduce2(s, q);
    const float mean = s / (float)DT;
    const float rstd = rsqrtf(fmaxf(q / (float)DT - mean * mean, 0.f) + 1e-5f);
    #pragma unroll
    for (int j = 0; j < 2; j++) {
        const int c4 = (lane + j * 32) << 2;
        const float4 g4 = *(const float4*)(g + c4);
        const float4 b4 = *(const float4*)(b + c4);
        float4 o;
        o.x = (v[j].x - mean) * rstd * g4.x + b4.x;
        o.y = (v[j].y - mean) * rstd * g4.y + b4.y;
        o.z = (v[j].z - mean) * rstd * g4.z + b4.z;
        o.w = (v[j].w - mean) * rstd * g4.w + b4.w;
        ln_store(o, Y, H, nullptr, (size_t)row * ldy + c4);
    }
}

// ---------------------------------------------------------------------------
// Tensor-core flash attention. QK 2-term, PV 1-term. Output att hi-only.
// ---------------------------------------------------------------------------
#define AP 72
#define ATT_SMEM (4 * 64 * AP * 2)

__global__ __launch_bounds__(128)
void attn_kernel(const __half* __restrict__ qkvh,
                 const __half* __restrict__ qkvl,
                 __half* __restrict__ attH,
                 float* __restrict__ diag)
{
    extern __shared__ __half sh[];
    __half* Qh = sh;
    __half* Ql = sh + 64 * AP;
    __half* Ks = sh + 2 * 64 * AP;
    __half* Vs = sh + 3 * 64 * AP;

    const int tid = threadIdx.x;
    const int w = tid >> 5, lane = tid & 31;
    const int qt = blockIdx.x, bhid = blockIdx.y;
    const int b = bhid >> 3, h = bhid & 7;

    const size_t base = (size_t)(b * LL) * (3 * DM) + h * HD;
    const __half* qh_g = qkvh + base;
    const __half* ql_g = qkvl + base;
    const __half* kh_g = qkvh + base + DM;
    const __half* vh_g = qkvh + base + 2 * DM;

    #pragma unroll
    for (int i = 0; i < 4; i++) {
        const int idx = tid + i * 128;
        const int r = idx >> 3, c = (idx & 7) * 8;
        const size_t go = (size_t)(qt * 64 + r) * (3 * DM) + c;
        *(uint4*)(Qh + r * AP + c) = *(const uint4*)(qh_g + go);
        *(uint4*)(Ql + r * AP + c) = *(const uint4*)(ql_g + go);
    }
    __syncthreads();

    const int a_row = (lane & 7) + ((lane >> 3) & 1) * 8;
    const int a_k   = (lane >> 4) * 8;
    uint32_t qhf[4][4], qlf[4][4];
    #pragma unroll
    for (int ks = 0; ks < 4; ks++) {
        LDSM4(qhf[ks], smem_u32(Qh + (w * 16 + a_row) * AP + ks * 16 + a_k));
        LDSM4(qlf[ks], smem_u32(Ql + (w * 16 + a_row) * AP + ks * 16 + a_k));
    }

    const int g  = lane >> 2;
    const int t2 = (lane & 3) * 2;
    const int b_row = (lane & 7) + ((lane >> 4) & 1) * 8;
    const int b_k   = ((lane >> 3) & 1) * 8;
    const int v_row = (lane & 7) + ((lane >> 3) & 1) * 8;
    const int v_col = ((lane >> 4) & 1) * 8;

    float m_[2] = {-1e30f, -1e30f}, l_[2] = {0.f, 0.f}, sd_[2] = {0.f, 0.f};
    float o[8][4];
    #pragma unroll
    for (int i = 0; i < 8; i++)
        #pragma unroll
        for (int j = 0; j < 4; j++) o[i][j] = 0.f;

    for (int kt = 0; kt < 8; kt++) {
        __syncthreads();
        #pragma unroll
        for (int i = 0; i < 4; i++) {
            const int idx = tid + i * 128;
            const int r = idx >> 3, c = (idx & 7) * 8;
            const size_t go = (size_t)(kt * 64 + r) * (3 * DM) + c;
            *(uint4*)(Ks + r * AP + c) = *(const uint4*)(kh_g + go);
            *(uint4*)(Vs + r * AP + c) = *(const uint4*)(vh_g + go);
        }
        __syncthreads();

        float s[8][4];
        #pragma unroll
        for (int i = 0; i < 8; i++)
            #pragma unroll
            for (int j = 0; j < 4; j++) s[i][j] = 0.f;

        #pragma unroll
        for (int ks = 0; ks < 4; ks++)
            #pragma unroll
            for (int np = 0; np < 4; np++) {
                uint32_t bf[4];
                LDSM4(bf, smem_u32(Ks + (np * 16 + b_row) * AP + ks * 16 + b_k));
                MMA16816(s[2 * np],     qhf[ks], bf[0], bf[1]);
                MMA16816(s[2 * np],     qlf[ks], bf[0], bf[1]);
                MMA16816(s[2 * np + 1], qhf[ks], bf[2], bf[3]);
                MMA16816(s[2 * np + 1], qlf[ks], bf[2], bf[3]);
            }

        #pragma unroll
        for (int i = 0; i < 8; i++)
            #pragma unroll
            for (int j = 0; j < 4; j++) s[i][j] *= 0.125f;

        if (kt == qt) {
            #pragma unroll
            for (int nt = 0; nt < 8; nt++)
                #pragma unroll
                for (int ci = 0; ci < 4; ci++) {
                    const int ri = w * 16 + g + (ci >> 1) * 8;
                    const int co = nt * 8 + t2 + (ci & 1);
                    if (ri == co) sd_[ci >> 1] = s[nt][ci];
                }
        }

        #pragma unroll
        for (int r = 0; r < 2; r++) {
            float mt = -1e30f;
            #pragma unroll
            for (int nt = 0; nt < 8; nt++)
                mt = fmaxf(mt, fmaxf(s[nt][2 * r], s[nt][2 * r + 1]));
            mt = fmaxf(mt, __shfl_xor_sync(0xffffffffu, mt, 1));
            mt = fmaxf(mt, __shfl_xor_sync(0xffffffffu, mt, 2));
            const float mn = fmaxf(m_[r], mt);
            const float corr = __expf(m_[r] - mn);
            float ps = 0.f;
            #pragma unroll
            for (int nt = 0; nt < 8; nt++) {
                const float p0 = __expf(s[nt][2 * r] - mn);
                const float p1 = __expf(s[nt][2 * r + 1] - mn);
                s[nt][2 * r] = p0; s[nt][2 * r + 1] = p1;
                ps += p0 + p1;
            }
            ps += __shfl_xor_sync(0xffffffffu, ps, 1);
            ps += __shfl_xor_sync(0xffffffffu, ps, 2);
            l_[r] = l_[r] * corr + ps;
            m_[r] = mn;
            #pragma unroll
            for (int nt = 0; nt < 8; nt++) {
                o[nt][2 * r] *= corr; o[nt][2 * r + 1] *= corr;
            }
        }

        // O += P V  (P single fp16 term)
        #pragma unroll
        for (int j = 0; j < 4; j++) {
            uint32_t phf[4];
            phf[0] = pack_h2_hi(s[2 * j][0],     s[2 * j][1]);
            phf[1] = pack_h2_hi(s[2 * j][2],     s[2 * j][3]);
            phf[2] = pack_h2_hi(s[2 * j + 1][0], s[2 * j + 1][1]);
            phf[3] = pack_h2_hi(s[2 * j + 1][2], s[2 * j + 1][3]);
            #pragma unroll
            for (int dp = 0; dp < 4; dp++) {
                uint32_t vf[4];
                LDSM4T(vf, smem_u32(Vs + (j * 16 + v_row) * AP + dp * 16 + v_col));
                MMA16816(o[2 * dp],     phf, vf[0], vf[1]);
                MMA16816(o[2 * dp + 1], phf, vf[2], vf[3]);
            }
        }
    }

    #pragma unroll
    for (int r = 0; r < 2; r++) {
        const float inv = 1.f / l_[r];
        const int row = qt * 64 + w * 16 + g + r * 8;
        const size_t ob = ((size_t)b * LL + row) * DM + h * HD;
        #pragma unroll
        for (int dt = 0; dt < 8; dt++)
            *(uint32_t*)(attH + ob + dt * 8 + t2) =
                pack_h2_hi(o[dt][2 * r] * inv, o[dt][2 * r + 1] * inv);
        if ((lane & 3) == (g >> 1))
            diag[(size_t)bhid * LL + row] = __expf(sd_[r] - m_[r]) * inv;
    }
}

// ---------------------------------------------------------------------------
// MaxPool 16 over seq, concat tok|time -> fp16 hi/lo [1024, 768]
// ---------------------------------------------------------------------------
__global__ void pool_kernel(const float* __restrict__ tok,
                            const float* __restrict__ tim,
                            __half* __restrict__ pcH,
                            __half* __restrict__ pcL)
{
    const int orow = blockIdx.x;
    const int b = orow >> 5, gq = orow & 31;
    for (int d = threadIdx.x; d < DCAT; d += blockDim.x) {
        float mx = -1e30f;
        if (d < DM) {
            const float* p = tok + ((size_t)b * LL + gq * 16) * DM + d;
            #pragma unroll
            for (int j = 0; j < 16; j++) mx = fmaxf(mx, p[j * DM]);
        } else {
            const float* p = tim + ((size_t)b * LL + gq * 16) * DT + (d - DM);
            #pragma unroll
            for (int j = 0; j < 16; j++) mx = fmaxf(mx, p[j * DT]);
        }
        __half h, l;
        split1(mx, h, l);
        pcH[(size_t)orow * DCAT + d] = h;
        pcL[(size_t)orow * DCAT + d] = l;
    }
}

// ---------------------------------------------------------------------------
// Host orchestration
// ---------------------------------------------------------------------------
static void wsplit_launch(const float* X, __half* H, long n)
{
    const int n4 = (int)(n / 4);
    wsplit_kernel<<<(n4 + 255) / 256, 256>>>(X, H, n4);
}

extern "C" void kernel_launch(void* const* d_in, const int* in_sizes, int n_in,
                              void* d_out, int out_size)
{
    const float* in[26];
    for (int i = 0; i < 26; i++) in[i] = (const float*)d_in[i];

    float *x, *ao, *xc, *ff, *tok, *timeb, *diag, *o1;
    cudaGetSymbolAddress((void**)&x,     g_x);
    cudaGetSymbolAddress((void**)&ao,    g_ao);
    cudaGetSymbolAddress((void**)&xc,    g_xc);
    cudaGetSymbolAddress((void**)&ff,    g_ff);
    cudaGetSymbolAddress((void**)&tok,   g_tok);
    cudaGetSymbolAddress((void**)&timeb, g_time);
    cudaGetSymbolAddress((void**)&diag,  g_diag);
    cudaGetSymbolAddress((void**)&o1,    g_o1);

    __half *ln0h, *xh, *qkvh, *qkvl, *atth, *xch, *h1h, *pch, *pcl, *wh;
    cudaGetSymbolAddress((void**)&ln0h, g_ln0h);
    cudaGetSymbolAddress((void**)&xh,   g_xh);
    cudaGetSymbolAddress((void**)&qkvh, g_qkvh); cudaGetSymbolAddress((void**)&qkvl, g_qkvl);
    cudaGetSymbolAddress((void**)&atth, g_atth);
    cudaGetSymbolAddress((void**)&xch,  g_xch);
    cudaGetSymbolAddress((void**)&h1h,  g_h1h);
    cudaGetSymbolAddress((void**)&pch,  g_pch);  cudaGetSymbolAddress((void**)&pcl,  g_pcl);
    cudaGetSymbolAddress((void**)&wh,   g_wh);

    cudaFuncSetAttribute(attn_kernel,
                         cudaFuncAttributeMaxDynamicSharedMemorySize, ATT_SMEM);
    cudaFuncSetAttribute(gemm_hf,
                         cudaFuncAttributeMaxDynamicSharedMemorySize, GEMM_SMEM);

    // pre-convert all weights to fp16
    wsplit_launch(in[4],  wh + OFF_W_IN,  (long)NLAYER * DM * DM);
    wsplit_launch(in[6],  wh + OFF_W_QKV, (long)NLAYER * 3 * DM * DM);
    wsplit_launch(in[8],  wh + OFF_W_AO,  (long)NLAYER * DM * DM);
    wsplit_launch(in[10], wh + OFF_W_L1,  (long)NLAYER * DFF * DCAT);
    wsplit_launch(in[12], wh + OFF_W_L2,  (long)NLAYER * DCAT * DFF);
    wsplit_launch(in[22], wh + OFF_W_OUT, (long)DT * DCAT);

    const int M = MROWS;
    for (int i = 0; i < NLAYER; i++) {
        const float* xin = i ? tok : in[0];
        const float* tin = i ? timeb : in[1];

        // norm0 -> fp16 hi only
        ln_kernel<4><<<M / 8, 256>>>(xin, DM, nullptr, 0,
                                     in[2] + i * DM, in[3] + i * DM,
                                     nullptr, ln0h, nullptr, DM);
        // in_proj (1-term) -> fp32 x + fp16 hi
        gemm_hf<<<dim3(M / 128, DM / 128), 256, GEMM_SMEM>>>(
            ln0h, nullptr, DM, wh + OFF_W_IN + (long)i * DM * DM, DM,
            in[5] + i * DM, x, xh, nullptr, DM, 0);
        // qkv (1-term) -> fp16 hi/lo (2-term output for attention Q)
        gemm_hf<<<dim3(M / 128, 3 * DM / 128), 256, GEMM_SMEM>>>(
            xh, nullptr, DM, wh + OFF_W_QKV + (long)i * 3 * DM * DM, DM,
            in[7] + i * 3 * DM, nullptr, qkvh, qkvl, 3 * DM, 0);

        attn_kernel<<<dim3(LL / 64, BB * NH), 128, ATT_SMEM>>>(
            qkvh, qkvl, atth, diag);

        // attn out proj (1-term) -> fp32
        gemm_hf<<<dim3(M / 128, DM / 128), 256, GEMM_SMEM>>>(
            atth, nullptr, DM, wh + OFF_W_AO + (long)i * DM * DM, DM,
            in[9] + i * DM, ao, nullptr, nullptr, DM, 0);

        // n1 -> xc fp32 + xch hi-only ; n2 -> xc+DM fp32 + xch+DM hi-only
        ln_kernel<4><<<M / 8, 256>>>(ao, DM, x, DM,
                                     in[14] + i * DM, in[15] + i * DM,
                                     xc, xch, nullptr, DCAT);
        ln_diag_kernel<<<M / 8, 256>>>(tin, diag,
                                       in[16] + i * DT, in[17] + i * DT,
                                       xc + DM, xch + DM, DCAT);

        // FF1 (1-term) -> h1 hi-only ; FF2 (1-term) -> fp32
        gemm_hf<<<dim3(M / 128, DFF / 128), 256, GEMM_SMEM>>>(
            xch, nullptr, DCAT, wh + OFF_W_L1 + (long)i * DFF * DCAT, DCAT,
            in[11] + i * DFF, nullptr, h1h, nullptr, DFF, 1);
        gemm_hf<<<dim3(M / 128, DCAT / 128), 256, GEMM_SMEM>>>(
            h1h, nullptr, DFF, wh + OFF_W_L2 + (long)i * DCAT * DFF, DFF,
            in[13] + i * DCAT, ff, nullptr, nullptr, DCAT, 0);

        // n3 / n4 -> fp32 streams
        ln_kernel<4><<<M / 8, 256>>>(ff, DCAT, xc, DCAT,
                                     in[18] + i * DM, in[19] + i * DM,
                                     tok, nullptr, nullptr, DM);
        ln_kernel<2><<<M / 8, 256>>>(ff + DM, DCAT, xc + DM, DCAT,
                                     in[20] + i * DT, in[21] + i * DT,
                                     timeb, nullptr, nullptr, DT);
    }

    pool_kernel<<<BB * 32, 256>>>(tok, timeb, pch, pcl);
    gemm_hf<<<dim3(BB * 32 / 128, DT / 128), 256, GEMM_SMEM>>>(
        pch, pcl, DCAT, wh + OFF_W_OUT, DCAT, in[23],
        o1, nullptr, nullptr, DT, 2);
    ln_kernel<2><<<BB * 32 / 8, 256>>>(o1, DT, nullptr, 0, in[24], in[25],
                                       (float*)d_out, nullptr, nullptr, DT);
}

// round 16
// speedup vs baseline: 4.7640x; 1.2014x over previous
#include <cuda_runtime.h>
#include <cuda_fp16.h>
#include <math.h>
#include <stdint.h>

// ---------------------------------------------------------------------------
// Problem constants
// ---------------------------------------------------------------------------
#define BB 32
#define LL 512
#define DM 512
#define DT 256
#define NH 8
#define HD 64
#define DFF 2048
#define NLAYER 2
#define MROWS (BB * LL)          // 16384
#define DCAT (DM + DT)           // 768

// ---------------------------------------------------------------------------
// Scratch (device globals)
// ---------------------------------------------------------------------------
__device__ float g_x   [MROWS * DM];
__device__ float g_ao  [MROWS * DM];
__device__ float g_xc  [MROWS * DCAT];
__device__ float g_ff  [MROWS * DCAT];
__device__ float g_tok [MROWS * DM];
__device__ float g_time[MROWS * DT];
__device__ float g_diag[BB * NH * LL];
__device__ float g_o1  [BB * 32 * DT];

// fp16 activation buffers
__device__ __half g_ln0h[MROWS * DM];                   // hi only
__device__ __half g_xh  [MROWS * DM];                   // hi only
__device__ __half g_qkvh[MROWS * 3 * DM], g_qkvl[MROWS * 3 * DM];
__device__ __half g_atth[MROWS * DM];                   // hi only
__device__ __half g_xch [MROWS * DCAT];                 // hi only
__device__ __half g_h1h [MROWS * DFF];                  // hi only
__device__ __half g_pch [BB * 32 * DCAT], g_pcl[BB * 32 * DCAT];

// fp16 weights
#define OFF_W_IN  0
#define OFF_W_QKV (OFF_W_IN  + NLAYER * DM * DM)
#define OFF_W_AO  (OFF_W_QKV + NLAYER * 3 * DM * DM)
#define OFF_W_L1  (OFF_W_AO  + NLAYER * DM * DM)
#define OFF_W_L2  (OFF_W_L1  + NLAYER * DFF * DCAT)
#define OFF_W_OUT (OFF_W_L2  + NLAYER * DCAT * DFF)
#define W_TOTAL   (OFF_W_OUT + DT * DCAT)
__device__ __half g_wh[W_TOTAL];

// ---------------------------------------------------------------------------
// Helpers
// ---------------------------------------------------------------------------
__device__ __forceinline__ uint32_t smem_u32(const void* p) {
    uint32_t a;
    asm("{ .reg .u64 t; cvta.to.shared.u64 t, %1; cvt.u32.u64 %0, t; }"
        : "=r"(a) : "l"(p));
    return a;
}

__device__ __forceinline__ void split1(float v, __half& h, __half& l) {
    h = __float2half_rn(v);
    l = __float2half_rn(v - __half2float(h));
}

__device__ __forceinline__ uint32_t pack_h2(float a, float b, uint32_t& lo) {
    __half ha, la, hb, lb;
    split1(a, ha, la); split1(b, hb, lb);
    lo = (uint32_t)__half_as_ushort(la) | ((uint32_t)__half_as_ushort(lb) << 16);
    return (uint32_t)__half_as_ushort(ha) | ((uint32_t)__half_as_ushort(hb) << 16);
}

__device__ __forceinline__ uint32_t pack_h2_hi(float a, float b) {
    __half ha = __float2half_rn(a), hb = __float2half_rn(b);
    return (uint32_t)__half_as_ushort(ha) | ((uint32_t)__half_as_ushort(hb) << 16);
}

// weights: float -> fp16 (hi only)
__global__ void wsplit_kernel(const float* __restrict__ X,
                              __half* __restrict__ H, int n4)
{
    const int i = blockIdx.x * blockDim.x + threadIdx.x;
    if (i >= n4) return;
    const float4 v = *(const float4*)(X + (size_t)i * 4);
    __half h[4];
    h[0] = __float2half_rn(v.x); h[1] = __float2half_rn(v.y);
    h[2] = __float2half_rn(v.z); h[3] = __float2half_rn(v.w);
    *(uint2*)(H + (size_t)i * 4) = *(uint2*)h;
}

// ---------------------------------------------------------------------------
// MMA / ldmatrix / cp.async primitives
// ---------------------------------------------------------------------------
#define LDSM4(R, addr) \
    asm volatile("ldmatrix.sync.aligned.m8n8.x4.shared.b16 {%0,%1,%2,%3}, [%4];" \
        : "=r"((R)[0]), "=r"((R)[1]), "=r"((R)[2]), "=r"((R)[3]) : "r"(addr))

#define LDSM4T(R, addr) \
    asm volatile("ldmatrix.sync.aligned.m8n8.x4.trans.shared.b16 {%0,%1,%2,%3}, [%4];" \
        : "=r"((R)[0]), "=r"((R)[1]), "=r"((R)[2]), "=r"((R)[3]) : "r"(addr))

#define MMA16816(D, A, B0, B1) \
    asm volatile("mma.sync.aligned.m16n8k16.row.col.f32.f16.f16.f32 " \
        "{%0,%1,%2,%3}, {%4,%5,%6,%7}, {%8,%9}, {%0,%1,%2,%3};" \
        : "+f"((D)[0]), "+f"((D)[1]), "+f"((D)[2]), "+f"((D)[3]) \
        : "r"((A)[0]), "r"((A)[1]), "r"((A)[2]), "r"((A)[3]), "r"(B0), "r"(B1))

__device__ __forceinline__ void cp_async16(uint32_t d, const void* s) {
    asm volatile("cp.async.cg.shared.global [%0], [%1], 16;" :: "r"(d), "l"(s));
}
#define CP_COMMIT() asm volatile("cp.async.commit_group;" ::: "memory")
#define CP_WAIT(n)  asm volatile("cp.async.wait_group %0;" :: "n"(n) : "memory")

__device__ __forceinline__ float act_apply(float v, int act) {
    if (act == 1) return fmaxf(v, 0.f);
    if (act == 2) return 0.5f * v * (1.f + erff(v * 0.70710678118654752f));
    return v;
}

// ---------------------------------------------------------------------------
// fp16 mma.sync GEMM, templated on TWOA (A = hi or hi+lo).
// 128x128 CTA tile, K-chunk 32, 8 warps of 32x64, 3-stage cp.async pipeline.
// 1-term stage = 20.5KB (3 stages = 61.4KB -> 3 CTAs/SM).
// ---------------------------------------------------------------------------
#define PITCH_B 80

template <int TWOA>
__global__ __launch_bounds__(256)
void gemm_hf(const __half* __restrict__ Ah, const __half* __restrict__ Al,
             int lda,
             const __half* __restrict__ Wh, int K,
             const float* __restrict__ bias,
             float* __restrict__ Cf,
             __half* __restrict__ Ch, __half* __restrict__ Cl,
             int ldc, int act)
{
    constexpr uint32_t OFF_AH = 0;
    constexpr uint32_t OFF_AL = 128 * PITCH_B;                       // 2-term only
    constexpr uint32_t OFF_BH = (TWOA ? 2 : 1) * 128 * PITCH_B;
    constexpr uint32_t STAGE  = (TWOA ? 3 : 2) * 128 * PITCH_B;

    extern __shared__ char sm[];
    const uint32_t sb = smem_u32(sm);

    const int tid = threadIdx.x;
    const int wid = tid >> 5;
    const int lane = tid & 31;
    const int m0 = blockIdx.x * 128;
    const int n0 = blockIdx.y * 128;
    const int wr = wid & 3;
    const int wc = wid >> 2;

    const int grow = tid >> 1;
    const int gcol = (tid & 1) * 16;
    const __half* Ahp = Ah + (size_t)(m0 + grow) * lda + gcol;
    const __half* Alp = TWOA ? (Al + (size_t)(m0 + grow) * lda + gcol) : nullptr;
    const __half* Whp = Wh + (size_t)(n0 + grow) * K + gcol;
    const uint32_t sts_off = (uint32_t)grow * PITCH_B + (uint32_t)gcol * 2;

    const int a_lrow = (lane & 7) + ((lane >> 3) & 1) * 8;
    const int a_koff = (lane >> 4) * 8;
    const int b_lrow = (lane & 7) + ((lane >> 4) & 1) * 8;
    const int b_koff = ((lane >> 3) & 1) * 8;
    const uint32_t a_lbase = (uint32_t)(wr * 32 + a_lrow) * PITCH_B + (uint32_t)a_koff * 2;
    const uint32_t b_lbase = (uint32_t)(wc * 64 + b_lrow) * PITCH_B + (uint32_t)b_koff * 2;

    float acc[2][8][4];
    #pragma unroll
    for (int mt = 0; mt < 2; mt++)
        #pragma unroll
        for (int nt = 0; nt < 8; nt++)
            #pragma unroll
            for (int r = 0; r < 4; r++) acc[mt][nt][r] = 0.f;

    const int NC = K >> 5;

    auto issue = [&](int c) {
        const uint32_t d = sb + (uint32_t)(c % 3) * STAGE + sts_off;
        cp_async16(d + OFF_AH,      Ahp + c * 32);
        cp_async16(d + OFF_AH + 16, Ahp + c * 32 + 8);
        if (TWOA) {
            cp_async16(d + OFF_AL,      Alp + c * 32);
            cp_async16(d + OFF_AL + 16, Alp + c * 32 + 8);
        }
        cp_async16(d + OFF_BH,      Whp + c * 32);
        cp_async16(d + OFF_BH + 16, Whp + c * 32 + 8);
        CP_COMMIT();
    };

    issue(0);
    if (NC > 1) issue(1);

    for (int c = 0; c < NC; c++) {
        if (c + 1 < NC) CP_WAIT(1); else CP_WAIT(0);
        __syncthreads();    // chunk c visible; compute(c-1) complete

        const uint32_t so = (uint32_t)(c % 3) * STAGE;
        if (c + 2 < NC) issue(c + 2);   // third buffer: no trailing barrier

        #pragma unroll
        for (int step = 0; step < 2; step++) {
            const uint32_t kb = (uint32_t)step * 32;

            uint32_t ahr[2][4], alr[2][4];
            #pragma unroll
            for (int mt = 0; mt < 2; mt++) {
                const uint32_t aa = sb + so + a_lbase + (uint32_t)mt * (16 * PITCH_B) + kb;
                LDSM4(ahr[mt], aa + OFF_AH);
                if (TWOA) LDSM4(alr[mt], aa + OFF_AL);
            }

            #pragma unroll
            for (int g = 0; g < 4; g++) {
                const uint32_t ba = sb + so + b_lbase + (uint32_t)g * (16 * PITCH_B) + kb;
                uint32_t bh[4];
                LDSM4(bh, ba + OFF_BH);
                #pragma unroll
                for (int mt = 0; mt < 2; mt++) {
                    MMA16816(acc[mt][2 * g],     ahr[mt], bh[0], bh[1]);
                    MMA16816(acc[mt][2 * g + 1], ahr[mt], bh[2], bh[3]);
                    if (TWOA) {
                        MMA16816(acc[mt][2 * g],     alr[mt], bh[0], bh[1]);
                        MMA16816(acc[mt][2 * g + 1], alr[mt], bh[2], bh[3]);
                    }
                }
            }
        }
    }

    const int g = lane >> 2;
    const int t = lane & 3;
    #pragma unroll
    for (int mt = 0; mt < 2; mt++) {
        #pragma unroll
        for (int nt = 0; nt < 8; nt++) {
            const int col = n0 + wc * 64 + nt * 8 + t * 2;
            const float b0 = bias[col], b1 = bias[col + 1];
            const int r0 = m0 + wr * 32 + mt * 16 + g;
            float v00 = act_apply(acc[mt][nt][0] + b0, act);
            float v01 = act_apply(acc[mt][nt][1] + b1, act);
            float v10 = act_apply(acc[mt][nt][2] + b0, act);
            float v11 = act_apply(acc[mt][nt][3] + b1, act);
            if (Cf) {
                *(float2*)(Cf + (size_t)r0 * ldc + col) = make_float2(v00, v01);
                *(float2*)(Cf + (size_t)(r0 + 8) * ldc + col) = make_float2(v10, v11);
            }
            if (Ch) {
                if (Cl) {
                    uint32_t lo, hi;
                    hi = pack_h2(v00, v01, lo);
                    *(uint32_t*)(Ch + (size_t)r0 * ldc + col) = hi;
                    *(uint32_t*)(Cl + (size_t)r0 * ldc + col) = lo;
                    hi = pack_h2(v10, v11, lo);
                    *(uint32_t*)(Ch + (size_t)(r0 + 8) * ldc + col) = hi;
                    *(uint32_t*)(Cl + (size_t)(r0 + 8) * ldc + col) = lo;
                } else {
                    *(uint32_t*)(Ch + (size_t)r0 * ldc + col) = pack_h2_hi(v00, v01);
                    *(uint32_t*)(Ch + (size_t)(r0 + 8) * ldc + col) = pack_h2_hi(v10, v11);
                }
            }
        }
    }
}

#define GEMM_SMEM1 (3 * 2 * 128 * PITCH_B)   // 61440 (1-term)
#define GEMM_SMEM2 (3 * 3 * 128 * PITCH_B)   // 92160 (2-term)

// ---------------------------------------------------------------------------
// Warp-per-row LayerNorm. 8 warps/block, 1 row/warp. NV4 = D/128.
// ---------------------------------------------------------------------------
__device__ __forceinline__ void warp_reduce2(float& s, float& q) {
    #pragma unroll
    for (int o = 16; o > 0; o >>= 1) {
        s += __shfl_xor_sync(0xffffffffu, s, o);
        q += __shfl_xor_sync(0xffffffffu, q, o);
    }
}

__device__ __forceinline__ void ln_store(float4 o, float* Y, __half* H,
                                         __half* L, size_t off) {
    if (Y) *(float4*)(Y + off) = o;
    if (H) {
        if (L) {
            __half h[4], l[4];
            split1(o.x, h[0], l[0]); split1(o.y, h[1], l[1]);
            split1(o.z, h[2], l[2]); split1(o.w, h[3], l[3]);
            *(uint2*)(H + off) = *(uint2*)h;
            *(uint2*)(L + off) = *(uint2*)l;
        } else {
            __half h[4];
            h[0] = __float2half_rn(o.x); h[1] = __float2half_rn(o.y);
            h[2] = __float2half_rn(o.z); h[3] = __float2half_rn(o.w);
            *(uint2*)(H + off) = *(uint2*)h;
        }
    }
}

template <int NV4>
__global__ void ln_kernel(const float* __restrict__ X, int ldx,
                          const float* __restrict__ R, int ldr,
                          const float* __restrict__ g, const float* __restrict__ b,
                          float* __restrict__ Y,
                          __half* __restrict__ H,
                          __half* __restrict__ L, int ldy)
{
    const int row = blockIdx.x * 8 + (threadIdx.x >> 5);
    const int lane = threadIdx.x & 31;
    const float D = (float)(NV4 * 128);

    float4 v[NV4];
    float s = 0.f, q = 0.f;
    #pragma unroll
    for (int j = 0; j < NV4; j++) {
        const int c4 = (lane + j * 32) << 2;
        v[j] = *(const float4*)(X + (size_t)row * ldx + c4);
        if (R) {
            const float4 r = *(const float4*)(R + (size_t)row * ldr + c4);
            v[j].x += r.x; v[j].y += r.y; v[j].z += r.z; v[j].w += r.w;
        }
        s += v[j].x + v[j].y + v[j].z + v[j].w;
        q += v[j].x * v[j].x + v[j].y * v[j].y + v[j].z * v[j].z + v[j].w * v[j].w;
    }
    warp_reduce2(s, q);
    const float mean = s / D;
    const float rstd = rsqrtf(fmaxf(q / D - mean * mean, 0.f) + 1e-5f);
    #pragma unroll
    for (int j = 0; j < NV4; j++) {
        const int c4 = (lane + j * 32) << 2;
        const float4 g4 = *(const float4*)(g + c4);
        const float4 b4 = *(const float4*)(b + c4);
        float4 o;
        o.x = (v[j].x - mean) * rstd * g4.x + b4.x;
        o.y = (v[j].y - mean) * rstd * g4.y + b4.y;
        o.z = (v[j].z - mean) * rstd * g4.z + b4.z;
        o.w = (v[j].w - mean) * rstd * g4.w + b4.w;
        ln_store(o, Y, H, L, (size_t)row * ldy + c4);
    }
}

// time branch: LN((diag+1) * x_time), D = 256
__global__ void ln_diag_kernel(const float* __restrict__ X,
                               const float* __restrict__ diag,
                               const float* __restrict__ g, const float* __restrict__ b,
                               float* __restrict__ Y,
                               __half* __restrict__ H, int ldy)
{
    const int row = blockIdx.x * 8 + (threadIdx.x >> 5);
    const int lane = threadIdx.x & 31;
    const int bb = row >> 9, l = row & 511;

    float4 v[2];
    float s = 0.f, q = 0.f;
    #pragma unroll
    for (int j = 0; j < 2; j++) {
        const int c4 = (lane + j * 32) << 2;
        const int h = c4 >> 5;
        const float dscale = diag[((size_t)bb * NH + h) * LL + l] + 1.f;
        v[j] = *(const float4*)(X + (size_t)row * DT + c4);
        v[j].x *= dscale; v[j].y *= dscale; v[j].z *= dscale; v[j].w *= dscale;
        s += v[j].x + v[j].y + v[j].z + v[j].w;
        q += v[j].x * v[j].x + v[j].y * v[j].y + v[j].z * v[j].z + v[j].w * v[j].w;
    }
    warp_reduce2(s, q);
    const float mean = s / (float)DT;
    const float rstd = rsqrtf(fmaxf(q / (float)DT - mean * mean, 0.f) + 1e-5f);
    #pragma unroll
    for (int j = 0; j < 2; j++) {
        const int c4 = (lane + j * 32) << 2;
        const float4 g4 = *(const float4*)(g + c4);
        const float4 b4 = *(const float4*)(b + c4);
        float4 o;
        o.x = (v[j].x - mean) * rstd * g4.x + b4.x;
        o.y = (v[j].y - mean) * rstd * g4.y + b4.y;
        o.z = (v[j].z - mean) * rstd * g4.z + b4.z;
        o.w = (v[j].w - mean) * rstd * g4.w + b4.w;
        ln_store(o, Y, H, nullptr, (size_t)row * ldy + c4);
    }
}

// ---------------------------------------------------------------------------
// Tensor-core flash attention. QK 2-term, PV 1-term. Output att hi-only.
// ---------------------------------------------------------------------------
#define AP 72
#define ATT_SMEM (4 * 64 * AP * 2)

__global__ __launch_bounds__(128)
void attn_kernel(const __half* __restrict__ qkvh,
                 const __half* __restrict__ qkvl,
                 __half* __restrict__ attH,
                 float* __restrict__ diag)
{
    extern __shared__ __half sh[];
    __half* Qh = sh;
    __half* Ql = sh + 64 * AP;
    __half* Ks = sh + 2 * 64 * AP;
    __half* Vs = sh + 3 * 64 * AP;

    const int tid = threadIdx.x;
    const int w = tid >> 5, lane = tid & 31;
    const int qt = blockIdx.x, bhid = blockIdx.y;
    const int b = bhid >> 3, h = bhid & 7;

    const size_t base = (size_t)(b * LL) * (3 * DM) + h * HD;
    const __half* qh_g = qkvh + base;
    const __half* ql_g = qkvl + base;
    const __half* kh_g = qkvh + base + DM;
    const __half* vh_g = qkvh + base + 2 * DM;

    #pragma unroll
    for (int i = 0; i < 4; i++) {
        const int idx = tid + i * 128;
        const int r = idx >> 3, c = (idx & 7) * 8;
        const size_t go = (size_t)(qt * 64 + r) * (3 * DM) + c;
        *(uint4*)(Qh + r * AP + c) = *(const uint4*)(qh_g + go);
        *(uint4*)(Ql + r * AP + c) = *(const uint4*)(ql_g + go);
    }
    __syncthreads();

    const int a_row = (lane & 7) + ((lane >> 3) & 1) * 8;
    const int a_k   = (lane >> 4) * 8;
    uint32_t qhf[4][4], qlf[4][4];
    #pragma unroll
    for (int ks = 0; ks < 4; ks++) {
        LDSM4(qhf[ks], smem_u32(Qh + (w * 16 + a_row) * AP + ks * 16 + a_k));
        LDSM4(qlf[ks], smem_u32(Ql + (w * 16 + a_row) * AP + ks * 16 + a_k));
    }

    const int g  = lane >> 2;
    const int t2 = (lane & 3) * 2;
    const int b_row = (lane & 7) + ((lane >> 4) & 1) * 8;
    const int b_k   = ((lane >> 3) & 1) * 8;
    const int v_row = (lane & 7) + ((lane >> 3) & 1) * 8;
    const int v_col = ((lane >> 4) & 1) * 8;

    float m_[2] = {-1e30f, -1e30f}, l_[2] = {0.f, 0.f}, sd_[2] = {0.f, 0.f};
    float o[8][4];
    #pragma unroll
    for (int i = 0; i < 8; i++)
        #pragma unroll
        for (int j = 0; j < 4; j++) o[i][j] = 0.f;

    for (int kt = 0; kt < 8; kt++) {
        __syncthreads();
        #pragma unroll
        for (int i = 0; i < 4; i++) {
            const int idx = tid + i * 128;
            const int r = idx >> 3, c = (idx & 7) * 8;
            const size_t go = (size_t)(kt * 64 + r) * (3 * DM) + c;
            *(uint4*)(Ks + r * AP + c) = *(const uint4*)(kh_g + go);
            *(uint4*)(Vs + r * AP + c) = *(const uint4*)(vh_g + go);
        }
        __syncthreads();

        float s[8][4];
        #pragma unroll
        for (int i = 0; i < 8; i++)
            #pragma unroll
            for (int j = 0; j < 4; j++) s[i][j] = 0.f;

        #pragma unroll
        for (int ks = 0; ks < 4; ks++)
            #pragma unroll
            for (int np = 0; np < 4; np++) {
                uint32_t bf[4];
                LDSM4(bf, smem_u32(Ks + (np * 16 + b_row) * AP + ks * 16 + b_k));
                MMA16816(s[2 * np],     qhf[ks], bf[0], bf[1]);
                MMA16816(s[2 * np],     qlf[ks], bf[0], bf[1]);
                MMA16816(s[2 * np + 1], qhf[ks], bf[2], bf[3]);
                MMA16816(s[2 * np + 1], qlf[ks], bf[2], bf[3]);
            }

        #pragma unroll
        for (int i = 0; i < 8; i++)
            #pragma unroll
            for (int j = 0; j < 4; j++) s[i][j] *= 0.125f;

        if (kt == qt) {
            #pragma unroll
            for (int nt = 0; nt < 8; nt++)
                #pragma unroll
                for (int ci = 0; ci < 4; ci++) {
                    const int ri = w * 16 + g + (ci >> 1) * 8;
                    const int co = nt * 8 + t2 + (ci & 1);
                    if (ri == co) sd_[ci >> 1] = s[nt][ci];
                }
        }

        #pragma unroll
        for (int r = 0; r < 2; r++) {
            float mt = -1e30f;
            #pragma unroll
            for (int nt = 0; nt < 8; nt++)
                mt = fmaxf(mt, fmaxf(s[nt][2 * r], s[nt][2 * r + 1]));
            mt = fmaxf(mt, __shfl_xor_sync(0xffffffffu, mt, 1));
            mt = fmaxf(mt, __shfl_xor_sync(0xffffffffu, mt, 2));
            const float mn = fmaxf(m_[r], mt);
            const float corr = __expf(m_[r] - mn);
            float ps = 0.f;
            #pragma unroll
            for (int nt = 0; nt < 8; nt++) {
                const float p0 = __expf(s[nt][2 * r] - mn);
                const float p1 = __expf(s[nt][2 * r + 1] - mn);
                s[nt][2 * r] = p0; s[nt][2 * r + 1] = p1;
                ps += p0 + p1;
            }
            ps += __shfl_xor_sync(0xffffffffu, ps, 1);
            ps += __shfl_xor_sync(0xffffffffu, ps, 2);
            l_[r] = l_[r] * corr + ps;
            m_[r] = mn;
            #pragma unroll
            for (int nt = 0; nt < 8; nt++) {
                o[nt][2 * r] *= corr; o[nt][2 * r + 1] *= corr;
            }
        }

        // O += P V  (P single fp16 term)
        #pragma unroll
        for (int j = 0; j < 4; j++) {
            uint32_t phf[4];
            phf[0] = pack_h2_hi(s[2 * j][0],     s[2 * j][1]);
            phf[1] = pack_h2_hi(s[2 * j][2],     s[2 * j][3]);
            phf[2] = pack_h2_hi(s[2 * j + 1][0], s[2 * j + 1][1]);
            phf[3] = pack_h2_hi(s[2 * j + 1][2], s[2 * j + 1][3]);
            #pragma unroll
            for (int dp = 0; dp < 4; dp++) {
                uint32_t vf[4];
                LDSM4T(vf, smem_u32(Vs + (j * 16 + v_row) * AP + dp * 16 + v_col));
                MMA16816(o[2 * dp],     phf, vf[0], vf[1]);
                MMA16816(o[2 * dp + 1], phf, vf[2], vf[3]);
            }
        }
    }

    #pragma unroll
    for (int r = 0; r < 2; r++) {
        const float inv = 1.f / l_[r];
        const int row = qt * 64 + w * 16 + g + r * 8;
        const size_t ob = ((size_t)b * LL + row) * DM + h * HD;
        #pragma unroll
        for (int dt = 0; dt < 8; dt++)
            *(uint32_t*)(attH + ob + dt * 8 + t2) =
                pack_h2_hi(o[dt][2 * r] * inv, o[dt][2 * r + 1] * inv);
        if ((lane & 3) == (g >> 1))
            diag[(size_t)bhid * LL + row] = __expf(sd_[r] - m_[r]) * inv;
    }
}

// ---------------------------------------------------------------------------
// MaxPool 16 over seq, concat tok|time -> fp16 hi/lo [1024, 768]
// ---------------------------------------------------------------------------
__global__ void pool_kernel(const float* __restrict__ tok,
                            const float* __restrict__ tim,
                            __half* __restrict__ pcH,
                            __half* __restrict__ pcL)
{
    const int orow = blockIdx.x;
    const int b = orow >> 5, gq = orow & 31;
    for (int d = threadIdx.x; d < DCAT; d += blockDim.x) {
        float mx = -1e30f;
        if (d < DM) {
            const float* p = tok + ((size_t)b * LL + gq * 16) * DM + d;
            #pragma unroll
            for (int j = 0; j < 16; j++) mx = fmaxf(mx, p[j * DM]);
        } else {
            const float* p = tim + ((size_t)b * LL + gq * 16) * DT + (d - DM);
            #pragma unroll
            for (int j = 0; j < 16; j++) mx = fmaxf(mx, p[j * DT]);
        }
        __half h, l;
        split1(mx, h, l);
        pcH[(size_t)orow * DCAT + d] = h;
        pcL[(size_t)orow * DCAT + d] = l;
    }
}

// ---------------------------------------------------------------------------
// Host orchestration
// ---------------------------------------------------------------------------
static void wsplit_launch(const float* X, __half* H, long n)
{
    const int n4 = (int)(n / 4);
    wsplit_kernel<<<(n4 + 255) / 256, 256>>>(X, H, n4);
}

extern "C" void kernel_launch(void* const* d_in, const int* in_sizes, int n_in,
                              void* d_out, int out_size)
{
    const float* in[26];
    for (int i = 0; i < 26; i++) in[i] = (const float*)d_in[i];

    float *x, *ao, *xc, *ff, *tok, *timeb, *diag, *o1;
    cudaGetSymbolAddress((void**)&x,     g_x);
    cudaGetSymbolAddress((void**)&ao,    g_ao);
    cudaGetSymbolAddress((void**)&xc,    g_xc);
    cudaGetSymbolAddress((void**)&ff,    g_ff);
    cudaGetSymbolAddress((void**)&tok,   g_tok);
    cudaGetSymbolAddress((void**)&timeb, g_time);
    cudaGetSymbolAddress((void**)&diag,  g_diag);
    cudaGetSymbolAddress((void**)&o1,    g_o1);

    __half *ln0h, *xh, *qkvh, *qkvl, *atth, *xch, *h1h, *pch, *pcl, *wh;
    cudaGetSymbolAddress((void**)&ln0h, g_ln0h);
    cudaGetSymbolAddress((void**)&xh,   g_xh);
    cudaGetSymbolAddress((void**)&qkvh, g_qkvh); cudaGetSymbolAddress((void**)&qkvl, g_qkvl);
    cudaGetSymbolAddress((void**)&atth, g_atth);
    cudaGetSymbolAddress((void**)&xch,  g_xch);
    cudaGetSymbolAddress((void**)&h1h,  g_h1h);
    cudaGetSymbolAddress((void**)&pch,  g_pch);  cudaGetSymbolAddress((void**)&pcl,  g_pcl);
    cudaGetSymbolAddress((void**)&wh,   g_wh);

    cudaFuncSetAttribute(attn_kernel,
                         cudaFuncAttributeMaxDynamicSharedMemorySize, ATT_SMEM);
    cudaFuncSetAttribute(gemm_hf<0>,
                         cudaFuncAttributeMaxDynamicSharedMemorySize, GEMM_SMEM1);
    cudaFuncSetAttribute(gemm_hf<1>,
                         cudaFuncAttributeMaxDynamicSharedMemorySize, GEMM_SMEM2);

    // pre-convert all weights to fp16
    wsplit_launch(in[4],  wh + OFF_W_IN,  (long)NLAYER * DM * DM);
    wsplit_launch(in[6],  wh + OFF_W_QKV, (long)NLAYER * 3 * DM * DM);
    wsplit_launch(in[8],  wh + OFF_W_AO,  (long)NLAYER * DM * DM);
    wsplit_launch(in[10], wh + OFF_W_L1,  (long)NLAYER * DFF * DCAT);
    wsplit_launch(in[12], wh + OFF_W_L2,  (long)NLAYER * DCAT * DFF);
    wsplit_launch(in[22], wh + OFF_W_OUT, (long)DT * DCAT);

    const int M = MROWS;
    for (int i = 0; i < NLAYER; i++) {
        const float* xin = i ? tok : in[0];
        const float* tin = i ? timeb : in[1];

        // norm0 -> fp16 hi only
        ln_kernel<4><<<M / 8, 256>>>(xin, DM, nullptr, 0,
                                     in[2] + i * DM, in[3] + i * DM,
                                     nullptr, ln0h, nullptr, DM);
        // in_proj (1-term) -> fp32 x + fp16 hi
        gemm_hf<0><<<dim3(M / 128, DM / 128), 256, GEMM_SMEM1>>>(
            ln0h, nullptr, DM, wh + OFF_W_IN + (long)i * DM * DM, DM,
            in[5] + i * DM, x, xh, nullptr, DM, 0);
        // qkv (1-term) -> fp16 hi/lo (2-term output for attention Q)
        gemm_hf<0><<<dim3(M / 128, 3 * DM / 128), 256, GEMM_SMEM1>>>(
            xh, nullptr, DM, wh + OFF_W_QKV + (long)i * 3 * DM * DM, DM,
            in[7] + i * 3 * DM, nullptr, qkvh, qkvl, 3 * DM, 0);

        attn_kernel<<<dim3(LL / 64, BB * NH), 128, ATT_SMEM>>>(
            qkvh, qkvl, atth, diag);

        // attn out proj (1-term) -> fp32
        gemm_hf<0><<<dim3(M / 128, DM / 128), 256, GEMM_SMEM1>>>(
            atth, nullptr, DM, wh + OFF_W_AO + (long)i * DM * DM, DM,
            in[9] + i * DM, ao, nullptr, nullptr, DM, 0);

        // n1 -> xc fp32 + xch hi-only ; n2 -> xc+DM fp32 + xch+DM hi-only
        ln_kernel<4><<<M / 8, 256>>>(ao, DM, x, DM,
                                     in[14] + i * DM, in[15] + i * DM,
                                     xc, xch, nullptr, DCAT);
        ln_diag_kernel<<<M / 8, 256>>>(tin, diag,
                                       in[16] + i * DT, in[17] + i * DT,
                                       xc + DM, xch + DM, DCAT);

        // FF1 (1-term) -> h1 hi-only ; FF2 (1-term) -> fp32
        gemm_hf<0><<<dim3(M / 128, DFF / 128), 256, GEMM_SMEM1>>>(
            xch, nullptr, DCAT, wh + OFF_W_L1 + (long)i * DFF * DCAT, DCAT,
            in[11] + i * DFF, nullptr, h1h, nullptr, DFF, 1);
        gemm_hf<0><<<dim3(M / 128, DCAT / 128), 256, GEMM_SMEM1>>>(
            h1h, nullptr, DFF, wh + OFF_W_L2 + (long)i * DCAT * DFF, DFF,
            in[13] + i * DCAT, ff, nullptr, nullptr, DCAT, 0);

        // n3 / n4 -> fp32 streams
        ln_kernel<4><<<M / 8, 256>>>(ff, DCAT, xc, DCAT,
                                     in[18] + i * DM, in[19] + i * DM,
                                     tok, nullptr, nullptr, DM);
        ln_kernel<2><<<M / 8, 256>>>(ff + DM, DCAT, xc + DM, DCAT,
                                     in[20] + i * DT, in[21] + i * DT,
                                     timeb, nullptr, nullptr, DT);
    }

    pool_kernel<<<BB * 32, 256>>>(tok, timeb, pch, pcl);
    gemm_hf<1><<<dim3(BB * 32 / 128, DT / 128), 256, GEMM_SMEM2>>>(
        pch, pcl, DCAT, wh + OFF_W_OUT, DCAT, in[23],
        o1, nullptr, nullptr, DT, 2);
    ln_kernel<2><<<BB * 32 / 8, 256>>>(o1, DT, nullptr, 0, in[24], in[25],
                                       (float*)d_out, nullptr, nullptr, DT);
}

// round 17
// speedup vs baseline: 4.9768x; 1.0447x over previous
#include <cuda_runtime.h>
#include <cuda_fp16.h>
#include <math.h>
#include <stdint.h>

// ---------------------------------------------------------------------------
// Problem constants
// ---------------------------------------------------------------------------
#define BB 32
#define LL 512
#define DM 512
#define DT 256
#define NH 8
#define HD 64
#define DFF 2048
#define NLAYER 2
#define MROWS (BB * LL)          // 16384
#define DCAT (DM + DT)           // 768

// ---------------------------------------------------------------------------
// Scratch (device globals)
// ---------------------------------------------------------------------------
__device__ float g_x   [MROWS * DM];
__device__ float g_ao  [MROWS * DM];
__device__ float g_xc  [MROWS * DCAT];
__device__ float g_ff  [MROWS * DCAT];
__device__ float g_tok [MROWS * DM];
__device__ float g_time[MROWS * DT];
__device__ float g_diag[BB * NH * LL];
__device__ float g_o1  [BB * 32 * DT];

// fp16 activation buffers (all hi-only except pooled concat)
__device__ __half g_ln0h[MROWS * DM];
__device__ __half g_xh  [MROWS * DM];
__device__ __half g_qkvh[MROWS * 3 * DM];
__device__ __half g_atth[MROWS * DM];
__device__ __half g_xch [MROWS * DCAT];
__device__ __half g_h1h [MROWS * DFF];
__device__ __half g_pch [BB * 32 * DCAT], g_pcl[BB * 32 * DCAT];

// fp16 weights
#define OFF_W_IN  0
#define OFF_W_QKV (OFF_W_IN  + NLAYER * DM * DM)
#define OFF_W_AO  (OFF_W_QKV + NLAYER * 3 * DM * DM)
#define OFF_W_L1  (OFF_W_AO  + NLAYER * DM * DM)
#define OFF_W_L2  (OFF_W_L1  + NLAYER * DFF * DCAT)
#define OFF_W_OUT (OFF_W_L2  + NLAYER * DCAT * DFF)
#define W_TOTAL   (OFF_W_OUT + DT * DCAT)
__device__ __half g_wh[W_TOTAL];

// ---------------------------------------------------------------------------
// Helpers
// ---------------------------------------------------------------------------
__device__ __forceinline__ uint32_t smem_u32(const void* p) {
    uint32_t a;
    asm("{ .reg .u64 t; cvta.to.shared.u64 t, %1; cvt.u32.u64 %0, t; }"
        : "=r"(a) : "l"(p));
    return a;
}

__device__ __forceinline__ void split1(float v, __half& h, __half& l) {
    h = __float2half_rn(v);
    l = __float2half_rn(v - __half2float(h));
}

__device__ __forceinline__ uint32_t pack_h2(float a, float b, uint32_t& lo) {
    __half ha, la, hb, lb;
    split1(a, ha, la); split1(b, hb, lb);
    lo = (uint32_t)__half_as_ushort(la) | ((uint32_t)__half_as_ushort(lb) << 16);
    return (uint32_t)__half_as_ushort(ha) | ((uint32_t)__half_as_ushort(hb) << 16);
}

__device__ __forceinline__ uint32_t pack_h2_hi(float a, float b) {
    __half ha = __float2half_rn(a), hb = __float2half_rn(b);
    return (uint32_t)__half_as_ushort(ha) | ((uint32_t)__half_as_ushort(hb) << 16);
}

// weights: float -> fp16 (hi only)
__global__ void wsplit_kernel(const float* __restrict__ X,
                              __half* __restrict__ H, int n4)
{
    const int i = blockIdx.x * blockDim.x + threadIdx.x;
    if (i >= n4) return;
    const float4 v = *(const float4*)(X + (size_t)i * 4);
    __half h[4];
    h[0] = __float2half_rn(v.x); h[1] = __float2half_rn(v.y);
    h[2] = __float2half_rn(v.z); h[3] = __float2half_rn(v.w);
    *(uint2*)(H + (size_t)i * 4) = *(uint2*)h;
}

// ---------------------------------------------------------------------------
// MMA / ldmatrix / cp.async primitives
// ---------------------------------------------------------------------------
#define LDSM4(R, addr) \
    asm volatile("ldmatrix.sync.aligned.m8n8.x4.shared.b16 {%0,%1,%2,%3}, [%4];" \
        : "=r"((R)[0]), "=r"((R)[1]), "=r"((R)[2]), "=r"((R)[3]) : "r"(addr))

#define LDSM4T(R, addr) \
    asm volatile("ldmatrix.sync.aligned.m8n8.x4.trans.shared.b16 {%0,%1,%2,%3}, [%4];" \
        : "=r"((R)[0]), "=r"((R)[1]), "=r"((R)[2]), "=r"((R)[3]) : "r"(addr))

#define MMA16816(D, A, B0, B1) \
    asm volatile("mma.sync.aligned.m16n8k16.row.col.f32.f16.f16.f32 " \
        "{%0,%1,%2,%3}, {%4,%5,%6,%7}, {%8,%9}, {%0,%1,%2,%3};" \
        : "+f"((D)[0]), "+f"((D)[1]), "+f"((D)[2]), "+f"((D)[3]) \
        : "r"((A)[0]), "r"((A)[1]), "r"((A)[2]), "r"((A)[3]), "r"(B0), "r"(B1))

__device__ __forceinline__ void cp_async16(uint32_t d, const void* s) {
    asm volatile("cp.async.cg.shared.global [%0], [%1], 16;" :: "r"(d), "l"(s));
}
#define CP_COMMIT() asm volatile("cp.async.commit_group;" ::: "memory")
#define CP_WAIT(n)  asm volatile("cp.async.wait_group %0;" :: "n"(n) : "memory")

__device__ __forceinline__ float act_apply(float v, int act) {
    if (act == 1) return fmaxf(v, 0.f);
    if (act == 2) return 0.5f * v * (1.f + erff(v * 0.70710678118654752f));
    return v;
}

// ---------------------------------------------------------------------------
// fp16 mma.sync GEMM, templated on TWOA (A = hi or hi+lo).
// 128x128 CTA tile, K-chunk 32, 8 warps of 32x64, 3-stage cp.async pipeline.
// ---------------------------------------------------------------------------
#define PITCH_B 80

template <int TWOA>
__global__ __launch_bounds__(256)
void gemm_hf(const __half* __restrict__ Ah, const __half* __restrict__ Al,
             int lda,
             const __half* __restrict__ Wh, int K,
             const float* __restrict__ bias,
             float* __restrict__ Cf,
             __half* __restrict__ Ch, __half* __restrict__ Cl,
             int ldc, int act)
{
    constexpr uint32_t OFF_AH = 0;
    constexpr uint32_t OFF_AL = 128 * PITCH_B;
    constexpr uint32_t OFF_BH = (TWOA ? 2 : 1) * 128 * PITCH_B;
    constexpr uint32_t STAGE  = (TWOA ? 3 : 2) * 128 * PITCH_B;

    extern __shared__ char sm[];
    const uint32_t sb = smem_u32(sm);

    const int tid = threadIdx.x;
    const int wid = tid >> 5;
    const int lane = tid & 31;
    const int m0 = blockIdx.x * 128;
    const int n0 = blockIdx.y * 128;
    const int wr = wid & 3;
    const int wc = wid >> 2;

    const int grow = tid >> 1;
    const int gcol = (tid & 1) * 16;
    const __half* Ahp = Ah + (size_t)(m0 + grow) * lda + gcol;
    const __half* Alp = TWOA ? (Al + (size_t)(m0 + grow) * lda + gcol) : nullptr;
    const __half* Whp = Wh + (size_t)(n0 + grow) * K + gcol;
    const uint32_t sts_off = (uint32_t)grow * PITCH_B + (uint32_t)gcol * 2;

    const int a_lrow = (lane & 7) + ((lane >> 3) & 1) * 8;
    const int a_koff = (lane >> 4) * 8;
    const int b_lrow = (lane & 7) + ((lane >> 4) & 1) * 8;
    const int b_koff = ((lane >> 3) & 1) * 8;
    const uint32_t a_lbase = (uint32_t)(wr * 32 + a_lrow) * PITCH_B + (uint32_t)a_koff * 2;
    const uint32_t b_lbase = (uint32_t)(wc * 64 + b_lrow) * PITCH_B + (uint32_t)b_koff * 2;

    float acc[2][8][4];
    #pragma unroll
    for (int mt = 0; mt < 2; mt++)
        #pragma unroll
        for (int nt = 0; nt < 8; nt++)
            #pragma unroll
            for (int r = 0; r < 4; r++) acc[mt][nt][r] = 0.f;

    const int NC = K >> 5;

    auto issue = [&](int c) {
        const uint32_t d = sb + (uint32_t)(c % 3) * STAGE + sts_off;
        cp_async16(d + OFF_AH,      Ahp + c * 32);
        cp_async16(d + OFF_AH + 16, Ahp + c * 32 + 8);
        if (TWOA) {
            cp_async16(d + OFF_AL,      Alp + c * 32);
            cp_async16(d + OFF_AL + 16, Alp + c * 32 + 8);
        }
        cp_async16(d + OFF_BH,      Whp + c * 32);
        cp_async16(d + OFF_BH + 16, Whp + c * 32 + 8);
        CP_COMMIT();
    };

    issue(0);
    if (NC > 1) issue(1);

    for (int c = 0; c < NC; c++) {
        if (c + 1 < NC) CP_WAIT(1); else CP_WAIT(0);
        __syncthreads();

        const uint32_t so = (uint32_t)(c % 3) * STAGE;
        if (c + 2 < NC) issue(c + 2);

        #pragma unroll
        for (int step = 0; step < 2; step++) {
            const uint32_t kb = (uint32_t)step * 32;

            uint32_t ahr[2][4], alr[2][4];
            #pragma unroll
            for (int mt = 0; mt < 2; mt++) {
                const uint32_t aa = sb + so + a_lbase + (uint32_t)mt * (16 * PITCH_B) + kb;
                LDSM4(ahr[mt], aa + OFF_AH);
                if (TWOA) LDSM4(alr[mt], aa + OFF_AL);
            }

            #pragma unroll
            for (int g = 0; g < 4; g++) {
                const uint32_t ba = sb + so + b_lbase + (uint32_t)g * (16 * PITCH_B) + kb;
                uint32_t bh[4];
                LDSM4(bh, ba + OFF_BH);
                #pragma unroll
                for (int mt = 0; mt < 2; mt++) {
                    MMA16816(acc[mt][2 * g],     ahr[mt], bh[0], bh[1]);
                    MMA16816(acc[mt][2 * g + 1], ahr[mt], bh[2], bh[3]);
                    if (TWOA) {
                        MMA16816(acc[mt][2 * g],     alr[mt], bh[0], bh[1]);
                        MMA16816(acc[mt][2 * g + 1], alr[mt], bh[2], bh[3]);
                    }
                }
            }
        }
    }

    const int g = lane >> 2;
    const int t = lane & 3;
    #pragma unroll
    for (int mt = 0; mt < 2; mt++) {
        #pragma unroll
        for (int nt = 0; nt < 8; nt++) {
            const int col = n0 + wc * 64 + nt * 8 + t * 2;
            const float b0 = bias[col], b1 = bias[col + 1];
            const int r0 = m0 + wr * 32 + mt * 16 + g;
            float v00 = act_apply(acc[mt][nt][0] + b0, act);
            float v01 = act_apply(acc[mt][nt][1] + b1, act);
            float v10 = act_apply(acc[mt][nt][2] + b0, act);
            float v11 = act_apply(acc[mt][nt][3] + b1, act);
            if (Cf) {
                *(float2*)(Cf + (size_t)r0 * ldc + col) = make_float2(v00, v01);
                *(float2*)(Cf + (size_t)(r0 + 8) * ldc + col) = make_float2(v10, v11);
            }
            if (Ch) {
                if (Cl) {
                    uint32_t lo, hi;
                    hi = pack_h2(v00, v01, lo);
                    *(uint32_t*)(Ch + (size_t)r0 * ldc + col) = hi;
                    *(uint32_t*)(Cl + (size_t)r0 * ldc + col) = lo;
                    hi = pack_h2(v10, v11, lo);
                    *(uint32_t*)(Ch + (size_t)(r0 + 8) * ldc + col) = hi;
                    *(uint32_t*)(Cl + (size_t)(r0 + 8) * ldc + col) = lo;
                } else {
                    *(uint32_t*)(Ch + (size_t)r0 * ldc + col) = pack_h2_hi(v00, v01);
                    *(uint32_t*)(Ch + (size_t)(r0 + 8) * ldc + col) = pack_h2_hi(v10, v11);
                }
            }
        }
    }
}

#define GEMM_SMEM1 (3 * 2 * 128 * PITCH_B)   // 61440 (1-term)
#define GEMM_SMEM2 (3 * 3 * 128 * PITCH_B)   // 92160 (2-term)

// ---------------------------------------------------------------------------
// Warp-per-row LayerNorm. 8 warps/block, 1 row/warp. NV4 = D/128.
// ---------------------------------------------------------------------------
__device__ __forceinline__ void warp_reduce2(float& s, float& q) {
    #pragma unroll
    for (int o = 16; o > 0; o >>= 1) {
        s += __shfl_xor_sync(0xffffffffu, s, o);
        q += __shfl_xor_sync(0xffffffffu, q, o);
    }
}

__device__ __forceinline__ void ln_store(float4 o, float* Y, __half* H,
                                         __half* L, size_t off) {
    if (Y) *(float4*)(Y + off) = o;
    if (H) {
        if (L) {
            __half h[4], l[4];
            split1(o.x, h[0], l[0]); split1(o.y, h[1], l[1]);
            split1(o.z, h[2], l[2]); split1(o.w, h[3], l[3]);
            *(uint2*)(H + off) = *(uint2*)h;
            *(uint2*)(L + off) = *(uint2*)l;
        } else {
            __half h[4];
            h[0] = __float2half_rn(o.x); h[1] = __float2half_rn(o.y);
            h[2] = __float2half_rn(o.z); h[3] = __float2half_rn(o.w);
            *(uint2*)(H + off) = *(uint2*)h;
        }
    }
}

template <int NV4>
__global__ void ln_kernel(const float* __restrict__ X, int ldx,
                          const float* __restrict__ R, int ldr,
                          const float* __restrict__ g, const float* __restrict__ b,
                          float* __restrict__ Y,
                          __half* __restrict__ H,
                          __half* __restrict__ L, int ldy)
{
    const int row = blockIdx.x * 8 + (threadIdx.x >> 5);
    const int lane = threadIdx.x & 31;
    const float D = (float)(NV4 * 128);

    float4 v[NV4];
    float s = 0.f, q = 0.f;
    #pragma unroll
    for (int j = 0; j < NV4; j++) {
        const int c4 = (lane + j * 32) << 2;
        v[j] = *(const float4*)(X + (size_t)row * ldx + c4);
        if (R) {
            const float4 r = *(const float4*)(R + (size_t)row * ldr + c4);
            v[j].x += r.x; v[j].y += r.y; v[j].z += r.z; v[j].w += r.w;
        }
        s += v[j].x + v[j].y + v[j].z + v[j].w;
        q += v[j].x * v[j].x + v[j].y * v[j].y + v[j].z * v[j].z + v[j].w * v[j].w;
    }
    warp_reduce2(s, q);
    const float mean = s / D;
    const float rstd = rsqrtf(fmaxf(q / D - mean * mean, 0.f) + 1e-5f);
    #pragma unroll
    for (int j = 0; j < NV4; j++) {
        const int c4 = (lane + j * 32) << 2;
        const float4 g4 = *(const float4*)(g + c4);
        const float4 b4 = *(const float4*)(b + c4);
        float4 o;
        o.x = (v[j].x - mean) * rstd * g4.x + b4.x;
        o.y = (v[j].y - mean) * rstd * g4.y + b4.y;
        o.z = (v[j].z - mean) * rstd * g4.z + b4.z;
        o.w = (v[j].w - mean) * rstd * g4.w + b4.w;
        ln_store(o, Y, H, L, (size_t)row * ldy + c4);
    }
}

// time branch: LN((diag+1) * x_time), D = 256
__global__ void ln_diag_kernel(const float* __restrict__ X,
                               const float* __restrict__ diag,
                               const float* __restrict__ g, const float* __restrict__ b,
                               float* __restrict__ Y,
                               __half* __restrict__ H, int ldy)
{
    const int row = blockIdx.x * 8 + (threadIdx.x >> 5);
    const int lane = threadIdx.x & 31;
    const int bb = row >> 9, l = row & 511;

    float4 v[2];
    float s = 0.f, q = 0.f;
    #pragma unroll
    for (int j = 0; j < 2; j++) {
        const int c4 = (lane + j * 32) << 2;
        const int h = c4 >> 5;
        const float dscale = diag[((size_t)bb * NH + h) * LL + l] + 1.f;
        v[j] = *(const float4*)(X + (size_t)row * DT + c4);
        v[j].x *= dscale; v[j].y *= dscale; v[j].z *= dscale; v[j].w *= dscale;
        s += v[j].x + v[j].y + v[j].z + v[j].w;
        q += v[j].x * v[j].x + v[j].y * v[j].y + v[j].z * v[j].z + v[j].w * v[j].w;
    }
    warp_reduce2(s, q);
    const float mean = s / (float)DT;
    const float rstd = rsqrtf(fmaxf(q / (float)DT - mean * mean, 0.f) + 1e-5f);
    #pragma unroll
    for (int j = 0; j < 2; j++) {
        const int c4 = (lane + j * 32) << 2;
        const float4 g4 = *(const float4*)(g + c4);
        const float4 b4 = *(const float4*)(b + c4);
        float4 o;
        o.x = (v[j].x - mean) * rstd * g4.x + b4.x;
        o.y = (v[j].y - mean) * rstd * g4.y + b4.y;
        o.z = (v[j].z - mean) * rstd * g4.z + b4.z;
        o.w = (v[j].w - mean) * rstd * g4.w + b4.w;
        ln_store(o, Y, H, nullptr, (size_t)row * ldy + c4);
    }
}

// ---------------------------------------------------------------------------
// Tensor-core flash attention. QK 1-term, PV 1-term, cp.async double-buffered
// K/V. smem: Q + 2xK + 2xV = 5 tiles of 64 x AP halves.
// ---------------------------------------------------------------------------
#define AP 72
#define ATT_SMEM (5 * 64 * AP * 2)     // 46080

__global__ __launch_bounds__(128)
void attn_kernel(const __half* __restrict__ qkvh,
                 __half* __restrict__ attH,
                 float* __restrict__ diag)
{
    extern __shared__ __half sh[];
    __half* Qh = sh;
    __half* Kb[2] = { sh + 1 * 64 * AP, sh + 2 * 64 * AP };
    __half* Vb[2] = { sh + 3 * 64 * AP, sh + 4 * 64 * AP };

    const int tid = threadIdx.x;
    const int w = tid >> 5, lane = tid & 31;
    const int qt = blockIdx.x, bhid = blockIdx.y;
    const int b = bhid >> 3, h = bhid & 7;

    const size_t base = (size_t)(b * LL) * (3 * DM) + h * HD;
    const __half* qh_g = qkvh + base;
    const __half* kh_g = qkvh + base + DM;
    const __half* vh_g = qkvh + base + 2 * DM;

    // per-thread K/V load mapping: 4 x (row, 16B chunk)
    const int kv_r[1] = {0};
    auto issue_tile = [&](int kt) {
        __half* Kd = Kb[kt & 1];
        __half* Vd = Vb[kt & 1];
        #pragma unroll
        for (int i = 0; i < 4; i++) {
            const int idx = tid + i * 128;
            const int r = idx >> 3, c = (idx & 7) * 8;
            const size_t go = (size_t)(kt * 64 + r) * (3 * DM) + c;
            cp_async16(smem_u32(Kd + r * AP + c), kh_g + go);
            cp_async16(smem_u32(Vd + r * AP + c), vh_g + go);
        }
        CP_COMMIT();
    };
    (void)kv_r;

    // load Q (direct) + issue tile 0
    issue_tile(0);
    #pragma unroll
    for (int i = 0; i < 4; i++) {
        const int idx = tid + i * 128;
        const int r = idx >> 3, c = (idx & 7) * 8;
        *(uint4*)(Qh + r * AP + c) =
            *(const uint4*)(qh_g + (size_t)(qt * 64 + r) * (3 * DM) + c);
    }
    __syncthreads();

    const int a_row = (lane & 7) + ((lane >> 3) & 1) * 8;
    const int a_k   = (lane >> 4) * 8;
    uint32_t qhf[4][4];
    #pragma unroll
    for (int ks = 0; ks < 4; ks++)
        LDSM4(qhf[ks], smem_u32(Qh + (w * 16 + a_row) * AP + ks * 16 + a_k));

    const int g  = lane >> 2;
    const int t2 = (lane & 3) * 2;
    const int b_row = (lane & 7) + ((lane >> 4) & 1) * 8;
    const int b_k   = ((lane >> 3) & 1) * 8;
    const int v_row = (lane & 7) + ((lane >> 3) & 1) * 8;
    const int v_col = ((lane >> 4) & 1) * 8;

    float m_[2] = {-1e30f, -1e30f}, l_[2] = {0.f, 0.f}, sd_[2] = {0.f, 0.f};
    float o[8][4];
    #pragma unroll
    for (int i = 0; i < 8; i++)
        #pragma unroll
        for (int j = 0; j < 4; j++) o[i][j] = 0.f;

    for (int kt = 0; kt < 8; kt++) {
        CP_WAIT(0);
        __syncthreads();            // tile kt visible; prev compute done
        if (kt + 1 < 8) issue_tile(kt + 1);

        const __half* Ks = Kb[kt & 1];
        const __half* Vs = Vb[kt & 1];

        float s[8][4];
        #pragma unroll
        for (int i = 0; i < 8; i++)
            #pragma unroll
            for (int j = 0; j < 4; j++) s[i][j] = 0.f;

        #pragma unroll
        for (int ks = 0; ks < 4; ks++)
            #pragma unroll
            for (int np = 0; np < 4; np++) {
                uint32_t bf[4];
                LDSM4(bf, smem_u32(Ks + (np * 16 + b_row) * AP + ks * 16 + b_k));
                MMA16816(s[2 * np],     qhf[ks], bf[0], bf[1]);
                MMA16816(s[2 * np + 1], qhf[ks], bf[2], bf[3]);
            }

        #pragma unroll
        for (int i = 0; i < 8; i++)
            #pragma unroll
            for (int j = 0; j < 4; j++) s[i][j] *= 0.125f;

        if (kt == qt) {
            #pragma unroll
            for (int nt = 0; nt < 8; nt++)
                #pragma unroll
                for (int ci = 0; ci < 4; ci++) {
                    const int ri = w * 16 + g + (ci >> 1) * 8;
                    const int co = nt * 8 + t2 + (ci & 1);
                    if (ri == co) sd_[ci >> 1] = s[nt][ci];
                }
        }

        #pragma unroll
        for (int r = 0; r < 2; r++) {
            float mt = -1e30f;
            #pragma unroll
            for (int nt = 0; nt < 8; nt++)
                mt = fmaxf(mt, fmaxf(s[nt][2 * r], s[nt][2 * r + 1]));
            mt = fmaxf(mt, __shfl_xor_sync(0xffffffffu, mt, 1));
            mt = fmaxf(mt, __shfl_xor_sync(0xffffffffu, mt, 2));
            const float mn = fmaxf(m_[r], mt);
            const float corr = __expf(m_[r] - mn);
            float ps = 0.f;
            #pragma unroll
            for (int nt = 0; nt < 8; nt++) {
                const float p0 = __expf(s[nt][2 * r] - mn);
                const float p1 = __expf(s[nt][2 * r + 1] - mn);
                s[nt][2 * r] = p0; s[nt][2 * r + 1] = p1;
                ps += p0 + p1;
            }
            ps += __shfl_xor_sync(0xffffffffu, ps, 1);
            ps += __shfl_xor_sync(0xffffffffu, ps, 2);
            l_[r] = l_[r] * corr + ps;
            m_[r] = mn;
            #pragma unroll
            for (int nt = 0; nt < 8; nt++) {
                o[nt][2 * r] *= corr; o[nt][2 * r + 1] *= corr;
            }
        }

        // O += P V  (P single fp16 term)
        #pragma unroll
        for (int j = 0; j < 4; j++) {
            uint32_t phf[4];
            phf[0] = pack_h2_hi(s[2 * j][0],     s[2 * j][1]);
            phf[1] = pack_h2_hi(s[2 * j][2],     s[2 * j][3]);
            phf[2] = pack_h2_hi(s[2 * j + 1][0], s[2 * j + 1][1]);
            phf[3] = pack_h2_hi(s[2 * j + 1][2], s[2 * j + 1][3]);
            #pragma unroll
            for (int dp = 0; dp < 4; dp++) {
                uint32_t vf[4];
                LDSM4T(vf, smem_u32(Vs + (j * 16 + v_row) * AP + dp * 16 + v_col));
                MMA16816(o[2 * dp],     phf, vf[0], vf[1]);
                MMA16816(o[2 * dp + 1], phf, vf[2], vf[3]);
            }
        }
    }

    #pragma unroll
    for (int r = 0; r < 2; r++) {
        const float inv = 1.f / l_[r];
        const int row = qt * 64 + w * 16 + g + r * 8;
        const size_t ob = ((size_t)b * LL + row) * DM + h * HD;
        #pragma unroll
        for (int dt = 0; dt < 8; dt++)
            *(uint32_t*)(attH + ob + dt * 8 + t2) =
                pack_h2_hi(o[dt][2 * r] * inv, o[dt][2 * r + 1] * inv);
        if ((lane & 3) == (g >> 1))
            diag[(size_t)bhid * LL + row] = __expf(sd_[r] - m_[r]) * inv;
    }
}

// ---------------------------------------------------------------------------
// MaxPool 16 over seq, concat tok|time -> fp16 hi/lo [1024, 768]
// ---------------------------------------------------------------------------
__global__ void pool_kernel(const float* __restrict__ tok,
                            const float* __restrict__ tim,
                            __half* __restrict__ pcH,
                            __half* __restrict__ pcL)
{
    const int orow = blockIdx.x;
    const int b = orow >> 5, gq = orow & 31;
    for (int d = threadIdx.x; d < DCAT; d += blockDim.x) {
        float mx = -1e30f;
        if (d < DM) {
            const float* p = tok + ((size_t)b * LL + gq * 16) * DM + d;
            #pragma unroll
            for (int j = 0; j < 16; j++) mx = fmaxf(mx, p[j * DM]);
        } else {
            const float* p = tim + ((size_t)b * LL + gq * 16) * DT + (d - DM);
            #pragma unroll
            for (int j = 0; j < 16; j++) mx = fmaxf(mx, p[j * DT]);
        }
        __half h, l;
        split1(mx, h, l);
        pcH[(size_t)orow * DCAT + d] = h;
        pcL[(size_t)orow * DCAT + d] = l;
    }
}

// ---------------------------------------------------------------------------
// Host orchestration
// ---------------------------------------------------------------------------
static void wsplit_launch(const float* X, __half* H, long n)
{
    const int n4 = (int)(n / 4);
    wsplit_kernel<<<(n4 + 255) / 256, 256>>>(X, H, n4);
}

extern "C" void kernel_launch(void* const* d_in, const int* in_sizes, int n_in,
                              void* d_out, int out_size)
{
    const float* in[26];
    for (int i = 0; i < 26; i++) in[i] = (const float*)d_in[i];

    float *x, *ao, *xc, *ff, *tok, *timeb, *diag, *o1;
    cudaGetSymbolAddress((void**)&x,     g_x);
    cudaGetSymbolAddress((void**)&ao,    g_ao);
    cudaGetSymbolAddress((void**)&xc,    g_xc);
    cudaGetSymbolAddress((void**)&ff,    g_ff);
    cudaGetSymbolAddress((void**)&tok,   g_tok);
    cudaGetSymbolAddress((void**)&timeb, g_time);
    cudaGetSymbolAddress((void**)&diag,  g_diag);
    cudaGetSymbolAddress((void**)&o1,    g_o1);

    __half *ln0h, *xh, *qkvh, *atth, *xch, *h1h, *pch, *pcl, *wh;
    cudaGetSymbolAddress((void**)&ln0h, g_ln0h);
    cudaGetSymbolAddress((void**)&xh,   g_xh);
    cudaGetSymbolAddress((void**)&qkvh, g_qkvh);
    cudaGetSymbolAddress((void**)&atth, g_atth);
    cudaGetSymbolAddress((void**)&xch,  g_xch);
    cudaGetSymbolAddress((void**)&h1h,  g_h1h);
    cudaGetSymbolAddress((void**)&pch,  g_pch);  cudaGetSymbolAddress((void**)&pcl,  g_pcl);
    cudaGetSymbolAddress((void**)&wh,   g_wh);

    cudaFuncSetAttribute(attn_kernel,
                         cudaFuncAttributeMaxDynamicSharedMemorySize, ATT_SMEM);
    cudaFuncSetAttribute(gemm_hf<0>,
                         cudaFuncAttributeMaxDynamicSharedMemorySize, GEMM_SMEM1);
    cudaFuncSetAttribute(gemm_hf<1>,
                         cudaFuncAttributeMaxDynamicSharedMemorySize, GEMM_SMEM2);

    // pre-convert all weights to fp16
    wsplit_launch(in[4],  wh + OFF_W_IN,  (long)NLAYER * DM * DM);
    wsplit_launch(in[6],  wh + OFF_W_QKV, (long)NLAYER * 3 * DM * DM);
    wsplit_launch(in[8],  wh + OFF_W_AO,  (long)NLAYER * DM * DM);
    wsplit_launch(in[10], wh + OFF_W_L1,  (long)NLAYER * DFF * DCAT);
    wsplit_launch(in[12], wh + OFF_W_L2,  (long)NLAYER * DCAT * DFF);
    wsplit_launch(in[22], wh + OFF_W_OUT, (long)DT * DCAT);

    const int M = MROWS;
    for (int i = 0; i < NLAYER; i++) {
        const float* xin = i ? tok : in[0];
        const float* tin = i ? timeb : in[1];

        // norm0 -> fp16 hi only
        ln_kernel<4><<<M / 8, 256>>>(xin, DM, nullptr, 0,
                                     in[2] + i * DM, in[3] + i * DM,
                                     nullptr, ln0h, nullptr, DM);
        // in_proj (1-term) -> fp32 x + fp16 hi
        gemm_hf<0><<<dim3(M / 128, DM / 128), 256, GEMM_SMEM1>>>(
            ln0h, nullptr, DM, wh + OFF_W_IN + (long)i * DM * DM, DM,
            in[5] + i * DM, x, xh, nullptr, DM, 0);
        // qkv (1-term) -> fp16 hi only
        gemm_hf<0><<<dim3(M / 128, 3 * DM / 128), 256, GEMM_SMEM1>>>(
            xh, nullptr, DM, wh + OFF_W_QKV + (long)i * 3 * DM * DM, DM,
            in[7] + i * 3 * DM, nullptr, qkvh, nullptr, 3 * DM, 0);

        attn_kernel<<<dim3(LL / 64, BB * NH), 128, ATT_SMEM>>>(
            qkvh, atth, diag);

        // attn out proj (1-term) -> fp32
        gemm_hf<0><<<dim3(M / 128, DM / 128), 256, GEMM_SMEM1>>>(
            atth, nullptr, DM, wh + OFF_W_AO + (long)i * DM * DM, DM,
            in[9] + i * DM, ao, nullptr, nullptr, DM, 0);

        // n1 -> xc fp32 + xch hi-only ; n2 -> xc+DM fp32 + xch+DM hi-only
        ln_kernel<4><<<M / 8, 256>>>(ao, DM, x, DM,
                                     in[14] + i * DM, in[15] + i * DM,
                                     xc, xch, nullptr, DCAT);
        ln_diag_kernel<<<M / 8, 256>>>(tin, diag,
                                       in[16] + i * DT, in[17] + i * DT,
                                       xc + DM, xch + DM, DCAT);

        // FF1 (1-term) -> h1 hi-only ; FF2 (1-term) -> fp32
        gemm_hf<0><<<dim3(M / 128, DFF / 128), 256, GEMM_SMEM1>>>(
            xch, nullptr, DCAT, wh + OFF_W_L1 + (long)i * DFF * DCAT, DCAT,
            in[11] + i * DFF, nullptr, h1h, nullptr, DFF, 1);
        gemm_hf<0><<<dim3(M / 128, DCAT / 128), 256, GEMM_SMEM1>>>(
            h1h, nullptr, DFF, wh + OFF_W_L2 + (long)i * DCAT * DFF, DFF,
            in[13] + i * DCAT, ff, nullptr, nullptr, DCAT, 0);

        // n3 / n4 -> fp32 streams
        ln_kernel<4><<<M / 8, 256>>>(ff, DCAT, xc, DCAT,
                                     in[18] + i * DM, in[19] + i * DM,
                                     tok, nullptr, nullptr, DM);
        ln_kernel<2><<<M / 8, 256>>>(ff + DM, DCAT, xc + DM, DCAT,
                                     in[20] + i * DT, in[21] + i * DT,
                                     timeb, nullptr, nullptr, DT);
    }

    pool_kernel<<<BB * 32, 256>>>(tok, timeb, pch, pcl);
    gemm_hf<1><<<dim3(BB * 32 / 128, DT / 128), 256, GEMM_SMEM2>>>(
        pch, pcl, DCAT, wh + OFF_W_OUT, DCAT, in[23],
        o1, nullptr, nullptr, DT, 2);
    ln_kernel<2><<<BB * 32 / 8, 256>>>(o1, DT, nullptr, 0, in[24], in[25],
                                       (float*)d_out, nullptr, nullptr, DT);
}